// round 6
// baseline (speedup 1.0000x reference)
#include <cuda_runtime.h>
#include <cstddef>
#include <cstdint>

// ---------------- problem constants ----------------
#define BB 8
#define NN 256
#define DD_ 768
#define ROWS (BB*NN)     // 2048
#define SCALE_Q 0.20412414523193154f   // 24^-0.5
#define FULLMASK 0xffffffffu

// ---------------- scratch (device globals; no allocation) ----------------
__device__ float g_hln [ROWS*DD_];
__device__ float g_qt  [8*32*256*24];
__device__ float g_kt  [8*32*256*24];
__device__ float g_vt  [8*32*256*24];
__device__ float g_qk  [8*32*256*256];
__device__ float g_a   [8*32*256*256];
__device__ float g_vatt[ROWS*DD_];
__device__ float g_hmid[ROWS*DD_];
__device__ float g_hln2[ROWS*DD_];
__device__ float g_t   [ROWS*DD_];

// ---------------- helpers ----------------
__device__ __forceinline__ float warpSum(float v){
#pragma unroll
    for (int o = 16; o; o >>= 1) v += __shfl_xor_sync(FULLMASK, v, o);
    return v;
}
__device__ __forceinline__ float warpMax(float v){
#pragma unroll
    for (int o = 16; o; o >>= 1) v = fmaxf(v, __shfl_xor_sync(FULLMASK, v, o));
    return v;
}
__device__ __forceinline__ float sum16(float v){
#pragma unroll
    for (int o = 8; o; o >>= 1) v += __shfl_xor_sync(FULLMASK, v, o);
    return v;
}
__device__ __forceinline__ float gelu_tanh(float x){
    float y = 0.7978845608028654f * (x + 0.044715f * x * x * x);
    y = fminf(fmaxf(y, -30.f), 30.f);
    float t = __expf(2.f * y);
    float th = (t - 1.f) / (t + 1.f);
    return 0.5f * x * (1.f + th);
}
__device__ __forceinline__ float sigmoidf_(float x){
    return 1.f / (1.f + __expf(-x));
}
__device__ __forceinline__ uint32_t f2tf32(float x){
    uint32_t r;
    asm("cvt.rna.tf32.f32 %0, %1;" : "=r"(r) : "f"(x));
    return r;
}
__device__ __forceinline__ void mma_tf32(float* c, const uint32_t* a, const uint32_t* b){
    asm volatile("mma.sync.aligned.m16n8k8.row.col.f32.tf32.tf32.f32 "
        "{%0,%1,%2,%3}, {%4,%5,%6,%7}, {%8,%9}, {%0,%1,%2,%3};"
        : "+f"(c[0]), "+f"(c[1]), "+f"(c[2]), "+f"(c[3])
        : "r"(a[0]), "r"(a[1]), "r"(a[2]), "r"(a[3]), "r"(b[0]), "r"(b[1]));
}

// ---------------- LayerNorm over 768 ----------------
__global__ __launch_bounds__(256) void ln768_kernel(
    const float* __restrict__ x, const float* __restrict__ g,
    const float* __restrict__ b, float* __restrict__ y)
{
    int row = blockIdx.x;
    int tid = threadIdx.x;
    const float* xr = x + (size_t)row * DD_;
    float*       yr = y + (size_t)row * DD_;
    float v0 = xr[tid], v1 = xr[tid+256], v2 = xr[tid+512];
    __shared__ float red[8];
    float s = warpSum(v0 + v1 + v2);
    if ((tid & 31) == 0) red[tid >> 5] = s;
    __syncthreads();
    float tot = 0.f;
#pragma unroll
    for (int i = 0; i < 8; i++) tot += red[i];
    __syncthreads();
    float mean = tot * (1.f/768.f);
    float d0 = v0-mean, d1 = v1-mean, d2 = v2-mean;
    float q = warpSum(d0*d0 + d1*d1 + d2*d2);
    if ((tid & 31) == 0) red[tid >> 5] = q;
    __syncthreads();
    float vt = 0.f;
#pragma unroll
    for (int i = 0; i < 8; i++) vt += red[i];
    float rstd = rsqrtf(vt * (1.f/768.f) + 1e-5f);
    yr[tid]     = d0*rstd*g[tid]     + b[tid];
    yr[tid+256] = d1*rstd*g[tid+256] + b[tid+256];
    yr[tid+512] = d2*rstd*g[tid+512] + b[tid+512];
}

// ---------------- tf32 tensor-core GEMM, CTA 128x128, warp 64x32 ----------------
template<int EPI>   // 0 none, 1 gelu
__global__ __launch_bounds__(256) void gemm_tf32(
    const float* __restrict__ A, const float* __restrict__ Bm,
    const float* __restrict__ bias, const float* __restrict__ R,
    float* __restrict__ C, int M, int N, int K)
{
    __shared__ uint32_t sA[16][136];   // k-major: sA[k][m]
    __shared__ uint32_t sB[16][136];   // sB[k][n]
    int tid = threadIdx.x;
    int m0 = blockIdx.y * 128, n0 = blockIdx.x * 128;
    int lane = tid & 31, warp = tid >> 5;
    int wr = warp >> 2, wc = warp & 3;         // 2x4 warp grid
    int g  = lane >> 2, tg = lane & 3;
    int ar = tid >> 1, ak = (tid & 1) * 8;
    int bk = tid >> 4, bn = (tid & 15) * 8;

    float acc[4][4][4];
#pragma unroll
    for (int mb = 0; mb < 4; mb++)
#pragma unroll
        for (int nb = 0; nb < 4; nb++)
#pragma unroll
            for (int r = 0; r < 4; r++) acc[mb][nb][r] = 0.f;

    for (int k0 = 0; k0 < K; k0 += 16){
        const float* ap = &A[(size_t)(m0+ar)*K + k0 + ak];
        float4 a0 = *(const float4*)ap;
        float4 a1 = *(const float4*)(ap+4);
        sA[ak+0][ar]=f2tf32(a0.x); sA[ak+1][ar]=f2tf32(a0.y);
        sA[ak+2][ar]=f2tf32(a0.z); sA[ak+3][ar]=f2tf32(a0.w);
        sA[ak+4][ar]=f2tf32(a1.x); sA[ak+5][ar]=f2tf32(a1.y);
        sA[ak+6][ar]=f2tf32(a1.z); sA[ak+7][ar]=f2tf32(a1.w);
        const float* bp = &Bm[(size_t)(k0+bk)*N + n0 + bn];
        float4 b0 = *(const float4*)bp;
        float4 b1 = *(const float4*)(bp+4);
        sB[bk][bn+0]=f2tf32(b0.x); sB[bk][bn+1]=f2tf32(b0.y);
        sB[bk][bn+2]=f2tf32(b0.z); sB[bk][bn+3]=f2tf32(b0.w);
        sB[bk][bn+4]=f2tf32(b1.x); sB[bk][bn+5]=f2tf32(b1.y);
        sB[bk][bn+6]=f2tf32(b1.z); sB[bk][bn+7]=f2tf32(b1.w);
        __syncthreads();
#pragma unroll
        for (int ks = 0; ks < 16; ks += 8){
            uint32_t af[4][4], bf[4][2];
#pragma unroll
            for (int mb = 0; mb < 4; mb++){
                int mrow = wr*64 + mb*16 + g;
                af[mb][0] = sA[ks+tg  ][mrow];
                af[mb][1] = sA[ks+tg  ][mrow+8];
                af[mb][2] = sA[ks+tg+4][mrow];
                af[mb][3] = sA[ks+tg+4][mrow+8];
            }
#pragma unroll
            for (int nb = 0; nb < 4; nb++){
                int ncol = wc*32 + nb*8 + g;
                bf[nb][0] = sB[ks+tg  ][ncol];
                bf[nb][1] = sB[ks+tg+4][ncol];
            }
#pragma unroll
            for (int mb = 0; mb < 4; mb++)
#pragma unroll
                for (int nb = 0; nb < 4; nb++)
                    mma_tf32(acc[mb][nb], af[mb], bf[nb]);
        }
        __syncthreads();
    }
#pragma unroll
    for (int mb = 0; mb < 4; mb++){
#pragma unroll
        for (int nb = 0; nb < 4; nb++){
            int col = n0 + wc*32 + nb*8 + tg*2;
            float bv0 = bias[col], bv1 = bias[col+1];
#pragma unroll
            for (int hf = 0; hf < 2; hf++){
                int row = m0 + wr*64 + mb*16 + g + hf*8;
                float v0 = acc[mb][nb][hf*2+0] + bv0;
                float v1 = acc[mb][nb][hf*2+1] + bv1;
                if (EPI == 1){ v0 = gelu_tanh(v0); v1 = gelu_tanh(v1); }
                if (R){
                    v0 += R[(size_t)row*N + col];
                    v1 += R[(size_t)row*N + col + 1];
                }
                *(float2*)&C[(size_t)row*N + col] = make_float2(v0, v1);
            }
        }
    }
}

// ---------------- tf32 QKV GEMM with head-transposed scatter ----------------
__global__ __launch_bounds__(256) void gemm_qkv_tf32(
    const float* __restrict__ A, const float* __restrict__ Bm,
    const float* __restrict__ bias,
    float* __restrict__ qt, float* __restrict__ kt, float* __restrict__ vt)
{
    const int N = 2304, K = 768;
    __shared__ uint32_t sA[16][136];
    __shared__ uint32_t sB[16][136];
    int tid = threadIdx.x;
    int m0 = blockIdx.y * 128, n0 = blockIdx.x * 128;
    int lane = tid & 31, warp = tid >> 5;
    int wr = warp >> 2, wc = warp & 3;
    int g  = lane >> 2, tg = lane & 3;
    int ar = tid >> 1, ak = (tid & 1) * 8;
    int bk = tid >> 4, bn = (tid & 15) * 8;

    float acc[4][4][4];
#pragma unroll
    for (int mb = 0; mb < 4; mb++)
#pragma unroll
        for (int nb = 0; nb < 4; nb++)
#pragma unroll
            for (int r = 0; r < 4; r++) acc[mb][nb][r] = 0.f;

    for (int k0 = 0; k0 < K; k0 += 16){
        const float* ap = &A[(size_t)(m0+ar)*K + k0 + ak];
        float4 a0 = *(const float4*)ap;
        float4 a1 = *(const float4*)(ap+4);
        sA[ak+0][ar]=f2tf32(a0.x); sA[ak+1][ar]=f2tf32(a0.y);
        sA[ak+2][ar]=f2tf32(a0.z); sA[ak+3][ar]=f2tf32(a0.w);
        sA[ak+4][ar]=f2tf32(a1.x); sA[ak+5][ar]=f2tf32(a1.y);
        sA[ak+6][ar]=f2tf32(a1.z); sA[ak+7][ar]=f2tf32(a1.w);
        const float* bp = &Bm[(size_t)(k0+bk)*N + n0 + bn];
        float4 b0 = *(const float4*)bp;
        float4 b1 = *(const float4*)(bp+4);
        sB[bk][bn+0]=f2tf32(b0.x); sB[bk][bn+1]=f2tf32(b0.y);
        sB[bk][bn+2]=f2tf32(b0.z); sB[bk][bn+3]=f2tf32(b0.w);
        sB[bk][bn+4]=f2tf32(b1.x); sB[bk][bn+5]=f2tf32(b1.y);
        sB[bk][bn+6]=f2tf32(b1.z); sB[bk][bn+7]=f2tf32(b1.w);
        __syncthreads();
#pragma unroll
        for (int ks = 0; ks < 16; ks += 8){
            uint32_t af[4][4], bf[4][2];
#pragma unroll
            for (int mb = 0; mb < 4; mb++){
                int mrow = wr*64 + mb*16 + g;
                af[mb][0] = sA[ks+tg  ][mrow];
                af[mb][1] = sA[ks+tg  ][mrow+8];
                af[mb][2] = sA[ks+tg+4][mrow];
                af[mb][3] = sA[ks+tg+4][mrow+8];
            }
#pragma unroll
            for (int nb = 0; nb < 4; nb++){
                int ncol = wc*32 + nb*8 + g;
                bf[nb][0] = sB[ks+tg  ][ncol];
                bf[nb][1] = sB[ks+tg+4][ncol];
            }
#pragma unroll
            for (int mb = 0; mb < 4; mb++)
#pragma unroll
                for (int nb = 0; nb < 4; nb++)
                    mma_tf32(acc[mb][nb], af[mb], bf[nb]);
        }
        __syncthreads();
    }
#pragma unroll
    for (int mb = 0; mb < 4; mb++){
#pragma unroll
        for (int hf = 0; hf < 2; hf++){
            int m = m0 + wr*64 + mb*16 + g + hf*8;
            int b = m >> 8, l = m & 255;
#pragma unroll
            for (int nb = 0; nb < 4; nb++){
#pragma unroll
                for (int e = 0; e < 2; e++){
                    int n = n0 + wc*32 + nb*8 + tg*2 + e;
                    float v = acc[mb][nb][hf*2+e] + bias[n];
                    int seg = n / 768;
                    int nn = n - seg*768;
                    int dd = nn >> 5, h = nn & 31;
                    size_t idx = (((size_t)(b*32 + h))*256 + l)*24 + dd;
                    if (seg == 0)      qt[idx] = v * SCALE_Q;
                    else if (seg == 1) kt[idx] = v;
                    else               vt[idx] = v;
                }
            }
        }
    }
}

// ---------------- QK kernel ----------------
__global__ __launch_bounds__(256) void qk_kernel(
    const float* __restrict__ qt, const float* __restrict__ kt,
    float* __restrict__ qk)
{
    int bh = blockIdx.y;
    int l0 = (blockIdx.x >> 1) * 128;
    int m0 = (blockIdx.x & 1) * 128;
    __shared__ float sQ[24*132];
    __shared__ float sK[24*132];
    int tid = threadIdx.x;
    const float* qb = qt + (size_t)bh*6144 + (size_t)l0*24;
    const float* kb = kt + (size_t)bh*6144 + (size_t)m0*24;
    for (int i = tid; i < 3072; i += 256){
        int r = i / 24, d = i - r*24;
        sQ[d*132 + r] = qb[i];
        sK[d*132 + r] = kb[i];
    }
    __syncthreads();
    int tx = tid & 15, ty = tid >> 4;
    float acc[8][8];
#pragma unroll
    for (int i = 0; i < 8; i++)
#pragma unroll
        for (int j = 0; j < 8; j++) acc[i][j] = 0.f;
#pragma unroll 6
    for (int k = 0; k < 24; k++){
        float4 a0 = *(const float4*)&sQ[k*132 + ty*8];
        float4 a1 = *(const float4*)&sQ[k*132 + ty*8 + 4];
        float4 b0 = *(const float4*)&sK[k*132 + tx*8];
        float4 b1 = *(const float4*)&sK[k*132 + tx*8 + 4];
        float a[8] = {a0.x,a0.y,a0.z,a0.w,a1.x,a1.y,a1.z,a1.w};
        float b[8] = {b0.x,b0.y,b0.z,b0.w,b1.x,b1.y,b1.z,b1.w};
#pragma unroll
        for (int i = 0; i < 8; i++)
#pragma unroll
            for (int j = 0; j < 8; j++) acc[i][j] += a[i]*b[j];
    }
    float* out = qk + (size_t)bh*65536 + (size_t)l0*256 + m0;
#pragma unroll
    for (int i = 0; i < 8; i++){
        float* orow = out + (size_t)(ty*8 + i)*256 + tx*8;
        *(float4*)orow     = make_float4(acc[i][0],acc[i][1],acc[i][2],acc[i][3]);
        *(float4*)(orow+4) = make_float4(acc[i][4],acc[i][5],acc[i][6],acc[i][7]);
    }
}

// ---------------- fused edge kernel (unchanged from R5) ----------------
#define OFF_WEG  0
#define OFF_WOE  4096
#define OFF_EW1  6144
#define OFF_EW2  10240
#define OFF_PAR  14336
#define OFF_HHAT 14848          // [32][260]
#define OFF_GATE 23168          // [32][260]
#define OFF_MASK 31488          // [256]
#define OFF_GRP  31744
#define GRP_SZ   12672
#define EK_FLOATS (OFF_GRP + 2*GRP_SZ)
__global__ __launch_bounds__(512, 1) void edge_attn_kernel(
    const float* __restrict__ e_in, const float* __restrict__ mask,
    const float* __restrict__ qk,
    const float* __restrict__ W_eg, const float* __restrict__ b_eg,
    const float* __restrict__ W_oe, const float* __restrict__ b_oe,
    const float* __restrict__ eln_g, const float* __restrict__ eln_b,
    const float* __restrict__ ffn_g, const float* __restrict__ ffn_b,
    const float* __restrict__ eW1, const float* __restrict__ eb1,
    const float* __restrict__ eW2, const float* __restrict__ eb2,
    float* __restrict__ e_out, float* __restrict__ a_all)
{
    extern __shared__ float sm[];
    float* sWeg  = sm + OFF_WEG;
    float* sWoe  = sm + OFF_WOE;
    float* sEW1  = sm + OFF_EW1;
    float* sEW2  = sm + OFF_EW2;
    float* sPar  = sm + OFF_PAR;
    float* sHhat = sm + OFF_HHAT;
    float* sGate = sm + OFF_GATE;
    float* sMask = sm + OFF_MASK;

    int tid  = threadIdx.x;
    int grp  = tid >> 8;
    int t    = tid & 255;
    int ty   = t >> 4;
    int tx   = t & 15;
    int lane = tid & 31;
    int w    = tid >> 5;
    int row  = blockIdx.x;
    int b    = row >> 8;
    int l    = row & 255;
    int m0g  = grp * 128;
    float* sX   = sm + OFF_GRP + grp*GRP_SZ;
    float* sQKc = sX + 8448;
    size_t qkbase = ((size_t)b*32)*65536 + (size_t)l*256;

    for (int i = tid; i < 4096; i += 512){
        sWeg[i] = W_eg[i]; sEW1[i] = eW1[i]; sEW2[i] = eW2[i];
    }
    for (int i = tid; i < 2048; i += 512) sWoe[i] = W_oe[i];
    if (tid < 64){
        sPar[tid]     = b_eg[tid];
        sPar[64+tid]  = b_oe[tid];
        sPar[128+tid] = eb1[tid];
        sPar[192+tid] = eb2[tid];
        sPar[256+tid] = eln_g[tid];
        sPar[320+tid] = eln_b[tid];
        sPar[384+tid] = ffn_g[tid];
        sPar[448+tid] = ffn_b[tid];
    }
    for (int i = t; i < 1024; i += 256){
        int h = i >> 5, mq = (i & 31) * 4;
        *(float4*)&sQKc[h*132 + mq] =
            *(const float4*)&qk[qkbase + (size_t)h*65536 + m0g + mq];
    }
    if (t < 128) sMask[m0g + t] = mask[(size_t)row*256 + m0g + t];
    __syncthreads();

    float lgv[4], lbv[4], fgv[4], fbv[4];
#pragma unroll
    for (int j = 0; j < 4; j++){
        lgv[j] = sPar[256 + tx*4 + j];
        lbv[j] = sPar[320 + tx*4 + j];
        fgv[j] = sPar[384 + tx*4 + j];
        fbv[j] = sPar[448 + tx*4 + j];
    }

    float r_[8][4];

#pragma unroll
    for (int i = 0; i < 8; i++){
        float4 e4 = *(const float4*)&e_in[((size_t)row*256 + m0g + ty*8 + i)*64 + tx*4];
        r_[i][0]=e4.x; r_[i][1]=e4.y; r_[i][2]=e4.z; r_[i][3]=e4.w;
        float s = sum16(e4.x + e4.y + e4.z + e4.w);
        float mean = s * (1.f/64.f);
        float d0=e4.x-mean, d1=e4.y-mean, d2=e4.z-mean, d3=e4.w-mean;
        float q = sum16(d0*d0 + d1*d1 + d2*d2 + d3*d3);
        float rs = rsqrtf(q * (1.f/64.f) + 1e-5f);
        int col = (ty*8 + i + tx*4) & 127;
        sX[(tx*4+0)*132 + col] = d0*rs*lgv[0] + lbv[0];
        sX[(tx*4+1)*132 + col] = d1*rs*lgv[1] + lbv[1];
        sX[(tx*4+2)*132 + col] = d2*rs*lgv[2] + lbv[2];
        sX[(tx*4+3)*132 + col] = d3*rs*lgv[3] + lbv[3];
    }
    __syncthreads();

    float acc[8][4];
#pragma unroll
    for (int i=0;i<8;i++)
#pragma unroll
        for (int j=0;j<4;j++) acc[i][j]=0.f;
#pragma unroll 8
    for (int k = 0; k < 64; k++){
        int ofs = k & ~3;
        float4 a0 = *(const float4*)&sX[k*132 + ((ty*8     + ofs) & 127)];
        float4 a1 = *(const float4*)&sX[k*132 + ((ty*8 + 4 + ofs) & 127)];
        float4 b4 = *(const float4*)&sWeg[k*64 + tx*4];
        float a[8]={a0.x,a0.y,a0.z,a0.w,a1.x,a1.y,a1.z,a1.w};
        float bv[4]={b4.x,b4.y,b4.z,b4.w};
#pragma unroll
        for (int i=0;i<8;i++)
#pragma unroll
            for (int j=0;j<4;j++) acc[i][j] += a[i]*bv[j];
    }
    if (tx < 8){
#pragma unroll
        for (int j=0;j<4;j++){
            int h = tx*4 + j;
            float bb = sPar[h];
#pragma unroll
            for (int i=0;i<8;i++){
                int m = ty*8 + i;
                sHhat[h*260 + m0g + m] = acc[i][j] + bb + sQKc[h*132 + m];
            }
        }
    } else {
#pragma unroll
        for (int j=0;j<4;j++){
            int n = tx*4 + j;
            int h = n - 32;
            float bb = sPar[n];
#pragma unroll
            for (int i=0;i<8;i++){
                int m = ty*8 + i;
                sGate[h*260 + m0g + m] = sigmoidf_(acc[i][j] + bb + sMask[m0g + m]);
            }
        }
    }
    __syncthreads();

#pragma unroll
    for (int i=0;i<8;i++)
#pragma unroll
        for (int j=0;j<4;j++) acc[i][j]=0.f;
#pragma unroll 8
    for (int k = 0; k < 32; k++){
        float4 a0 = *(const float4*)&sHhat[k*260 + m0g + ty*8];
        float4 a1 = *(const float4*)&sHhat[k*260 + m0g + ty*8 + 4];
        float4 b4 = *(const float4*)&sWoe[k*64 + tx*4];
        float a[8]={a0.x,a0.y,a0.z,a0.w,a1.x,a1.y,a1.z,a1.w};
        float bv[4]={b4.x,b4.y,b4.z,b4.w};
#pragma unroll
        for (int i=0;i<8;i++)
#pragma unroll
            for (int j=0;j<4;j++) acc[i][j] += a[i]*bv[j];
    }
#pragma unroll
    for (int i=0;i<8;i++)
#pragma unroll
        for (int j=0;j<4;j++)
            r_[i][j] += acc[i][j] + sPar[64 + tx*4 + j];

#pragma unroll
    for (int i = 0; i < 8; i++){
        float s = sum16(r_[i][0] + r_[i][1] + r_[i][2] + r_[i][3]);
        float mean = s * (1.f/64.f);
        float d0=r_[i][0]-mean, d1=r_[i][1]-mean, d2=r_[i][2]-mean, d3=r_[i][3]-mean;
        float q = sum16(d0*d0 + d1*d1 + d2*d2 + d3*d3);
        float rs = rsqrtf(q * (1.f/64.f) + 1e-5f);
        int col = (ty*8 + i + tx*4) & 127;
        sX[(tx*4+0)*132 + col] = d0*rs*fgv[0] + fbv[0];
        sX[(tx*4+1)*132 + col] = d1*rs*fgv[1] + fbv[1];
        sX[(tx*4+2)*132 + col] = d2*rs*fgv[2] + fbv[2];
        sX[(tx*4+3)*132 + col] = d3*rs*fgv[3] + fbv[3];
    }
    __syncthreads();

#pragma unroll
    for (int i=0;i<8;i++)
#pragma unroll
        for (int j=0;j<4;j++) acc[i][j]=0.f;
#pragma unroll 8
    for (int k = 0; k < 64; k++){
        int ofs = k & ~3;
        float4 a0 = *(const float4*)&sX[k*132 + ((ty*8     + ofs) & 127)];
        float4 a1 = *(const float4*)&sX[k*132 + ((ty*8 + 4 + ofs) & 127)];
        float4 b4 = *(const float4*)&sEW1[k*64 + tx*4];
        float a[8]={a0.x,a0.y,a0.z,a0.w,a1.x,a1.y,a1.z,a1.w};
        float bv[4]={b4.x,b4.y,b4.z,b4.w};
#pragma unroll
        for (int i=0;i<8;i++)
#pragma unroll
            for (int j=0;j<4;j++) acc[i][j] += a[i]*bv[j];
    }
    __syncthreads();
#pragma unroll
    for (int i = 0; i < 8; i++){
        int col = (ty*8 + i + tx*4) & 127;
#pragma unroll
        for (int j = 0; j < 4; j++)
            sX[(tx*4+j)*132 + col] = gelu_tanh(acc[i][j] + sPar[128 + tx*4 + j]);
    }
    __syncthreads();

#pragma unroll
    for (int i=0;i<8;i++)
#pragma unroll
        for (int j=0;j<4;j++) acc[i][j]=0.f;
#pragma unroll 8
    for (int k = 0; k < 64; k++){
        int ofs = k & ~3;
        float4 a0 = *(const float4*)&sX[k*132 + ((ty*8     + ofs) & 127)];
        float4 a1 = *(const float4*)&sX[k*132 + ((ty*8 + 4 + ofs) & 127)];
        float4 b4 = *(const float4*)&sEW2[k*64 + tx*4];
        float a[8]={a0.x,a0.y,a0.z,a0.w,a1.x,a1.y,a1.z,a1.w};
        float bv[4]={b4.x,b4.y,b4.z,b4.w};
#pragma unroll
        for (int i=0;i<8;i++)
#pragma unroll
            for (int j=0;j<4;j++) acc[i][j] += a[i]*bv[j];
    }
#pragma unroll
    for (int i = 0; i < 8; i++){
        float4 o;
        o.x = r_[i][0] + acc[i][0] + sPar[192 + tx*4 + 0];
        o.y = r_[i][1] + acc[i][1] + sPar[192 + tx*4 + 1];
        o.z = r_[i][2] + acc[i][2] + sPar[192 + tx*4 + 2];
        o.w = r_[i][3] + acc[i][3] + sPar[192 + tx*4 + 3];
        *(float4*)&e_out[((size_t)row*256 + m0g + ty*8 + i)*64 + tx*4] = o;
    }
    __syncthreads();

#pragma unroll
    for (int hi = 0; hi < 2; hi++){
        int h = w + hi*16;
        float p[8], g[8];
        float mx = -3.4e38f;
#pragma unroll
        for (int j = 0; j < 8; j++){
            int m = j*32 + lane;
            p[j] = sHhat[h*260 + m] + sMask[m];
            mx = fmaxf(mx, p[j]);
        }
        mx = warpMax(mx);
        float s = 0.f, gs = 0.f;
#pragma unroll
        for (int j = 0; j < 8; j++){
            p[j] = __expf(p[j] - mx);
            s += p[j];
            g[j] = sGate[h*260 + j*32 + lane];
            gs += g[j];
        }
        s = warpSum(s); gs = warpSum(gs);
        float c = (1.f / s) * log1pf(gs);
        float* ao = a_all + (((size_t)(b*32 + h))*256 + l)*256;
#pragma unroll
        for (int j = 0; j < 8; j++)
            ao[j*32 + lane] = p[j] * g[j] * c;
    }
}

// ---------------- AV kernel ----------------
#define AV_FLOATS (64*260 + 24*260)
__global__ __launch_bounds__(256) void av_kernel(
    const float* __restrict__ a_all, const float* __restrict__ vt,
    float* __restrict__ vatt)
{
    extern __shared__ float sm[];
    float* sA = sm;
    float* sV = sm + 64*260;
    int bh = blockIdx.y;
    int l0 = blockIdx.x * 64;
    int b = bh >> 5, h = bh & 31;
    int tid = threadIdx.x;
    const float* ab = a_all + (size_t)bh*65536 + (size_t)l0*256;
    for (int i = tid; i < 4096; i += 256){
        int ll = i >> 6, m = (i & 63) * 4;
        *(float4*)&sA[ll*260 + m] = *(const float4*)&ab[(size_t)ll*256 + m];
    }
    const float* vb = vt + (size_t)bh*6144;
    for (int i = tid; i < 6144; i += 256){
        int m = i / 24, dd = i - m*24;
        sV[dd*260 + m] = vb[i];
    }
    __syncthreads();
    int w = tid >> 5, lane = tid & 31;
    if (lane < 24){
        const float* vr = &sV[lane*260];
#pragma unroll
        for (int j = 0; j < 8; j++){
            int ll = w*8 + j;
            const float* ar = &sA[ll*260];
            float acc = 0.f;
#pragma unroll 8
            for (int m = 0; m < 256; m += 4){
                float4 a = *(const float4*)&ar[m];
                float4 v = *(const float4*)&vr[m];
                acc += a.x*v.x + a.y*v.y + a.z*v.z + a.w*v.w;
            }
            vatt[(size_t)(b*256 + l0 + ll)*768 + lane*32 + h] = acc;
        }
    }
}

// ---------------- host ----------------
extern "C" void kernel_launch(void* const* d_in, const int* in_sizes, int n_in,
                              void* d_out, int out_size)
{
    const float* h_in   = (const float*)d_in[0];
    const float* e_in   = (const float*)d_in[1];
    const float* mask   = (const float*)d_in[2];
    const float* ln_h_g = (const float*)d_in[3];
    const float* ln_h_b = (const float*)d_in[4];
    const float* ln_e_g = (const float*)d_in[5];
    const float* ln_e_b = (const float*)d_in[6];
    const float* W_qkv  = (const float*)d_in[7];
    const float* b_qkv  = (const float*)d_in[8];
    const float* W_eg   = (const float*)d_in[9];
    const float* b_eg   = (const float*)d_in[10];
    const float* W_oh   = (const float*)d_in[11];
    const float* b_oh   = (const float*)d_in[12];
    const float* W_oe   = (const float*)d_in[13];
    const float* b_oe   = (const float*)d_in[14];
    const float* nffn_g = (const float*)d_in[15];
    const float* nffn_b = (const float*)d_in[16];
    const float* nW1    = (const float*)d_in[17];
    const float* nb1    = (const float*)d_in[18];
    const float* nW2    = (const float*)d_in[19];
    const float* nb2    = (const float*)d_in[20];
    const float* effn_g = (const float*)d_in[21];
    const float* effn_b = (const float*)d_in[22];
    const float* eW1    = (const float*)d_in[23];
    const float* eb1    = (const float*)d_in[24];
    const float* eW2    = (const float*)d_in[25];
    const float* eb2    = (const float*)d_in[26];

    float* out_h = (float*)d_out;
    float* out_e = out_h + (size_t)ROWS * DD_;

    float *hln, *qt, *kt, *vt, *qk, *aa, *vatt, *hmid, *hln2, *tbuf;
    cudaGetSymbolAddress((void**)&hln,  g_hln);
    cudaGetSymbolAddress((void**)&qt,   g_qt);
    cudaGetSymbolAddress((void**)&kt,   g_kt);
    cudaGetSymbolAddress((void**)&vt,   g_vt);
    cudaGetSymbolAddress((void**)&qk,   g_qk);
    cudaGetSymbolAddress((void**)&aa,   g_a);
    cudaGetSymbolAddress((void**)&vatt, g_vatt);
    cudaGetSymbolAddress((void**)&hmid, g_hmid);
    cudaGetSymbolAddress((void**)&hln2, g_hln2);
    cudaGetSymbolAddress((void**)&tbuf, g_t);

    cudaFuncSetAttribute(edge_attn_kernel,
                         cudaFuncAttributeMaxDynamicSharedMemorySize,
                         EK_FLOATS * 4);
    cudaFuncSetAttribute(av_kernel,
                         cudaFuncAttributeMaxDynamicSharedMemorySize,
                         AV_FLOATS * 4);

    // 1) h layernorm
    ln768_kernel<<<ROWS, 256>>>(h_in, ln_h_g, ln_h_b, hln);

    // 2) QKV GEMM (tf32 tensor cores) with transposed scatter
    gemm_qkv_tf32<<<dim3(18, 16), 256>>>(hln, W_qkv, b_qkv, qt, kt, vt);

    // 3) QK = Q K^T per head
    qk_kernel<<<dim3(4, 256), 256>>>(qt, kt, qk);

    // 4) fused edge attention + edge FFN -> e_out, A'
    edge_attn_kernel<<<ROWS, 512, EK_FLOATS * 4>>>(
        e_in, mask, qk,
        W_eg, b_eg, W_oe, b_oe,
        ln_e_g, ln_e_b, effn_g, effn_b,
        eW1, eb1, eW2, eb2,
        out_e, aa);

    // 5) V_att = A' @ V
    av_kernel<<<dim3(4, 256), 256, AV_FLOATS * 4>>>(aa, vt, vatt);

    // 6) h_mid = h + V_att @ W_oh + b_oh   (tf32)
    gemm_tf32<0><<<dim3(6, 16), 256>>>(vatt, W_oh, b_oh, h_in, hmid,
                                       ROWS, DD_, DD_);

    // 7) node FFN (tf32)
    ln768_kernel<<<ROWS, 256>>>(hmid, nffn_g, nffn_b, hln2);
    gemm_tf32<1><<<dim3(6, 16), 256>>>(hln2, nW1, nb1, nullptr, tbuf,
                                       ROWS, DD_, DD_);
    gemm_tf32<0><<<dim3(6, 16), 256>>>(tbuf, nW2, nb2, hmid, out_h,
                                       ROWS, DD_, DD_);
}

// round 7
// speedup vs baseline: 2.0392x; 2.0392x over previous
#include <cuda_runtime.h>
#include <cuda_fp16.h>
#include <cstddef>
#include <cstdint>

// ---------------- problem constants ----------------
#define BB 8
#define NN 256
#define DD_ 768
#define ROWS (BB*NN)     // 2048
#define SCALE_Q 0.20412414523193154f   // 24^-0.5
#define FULLMASK 0xffffffffu

// ---------------- scratch (device globals; no allocation) ----------------
__device__ float g_hln [ROWS*DD_];
__device__ float g_qt  [8*32*256*24];
__device__ float g_kt  [8*32*256*24];
__device__ float g_vt  [8*32*256*24];
__device__ float g_qk  [8*32*256*256];
__device__ float g_a   [8*32*256*256];
__device__ float g_vatt[ROWS*DD_];
__device__ float g_hmid[ROWS*DD_];
__device__ float g_hln2[ROWS*DD_];
__device__ float g_t   [ROWS*DD_];

// ---------------- helpers ----------------
__device__ __forceinline__ float warpSum(float v){
#pragma unroll
    for (int o = 16; o; o >>= 1) v += __shfl_xor_sync(FULLMASK, v, o);
    return v;
}
__device__ __forceinline__ float warpMax(float v){
#pragma unroll
    for (int o = 16; o; o >>= 1) v = fmaxf(v, __shfl_xor_sync(FULLMASK, v, o));
    return v;
}
__device__ __forceinline__ float sum16(float v){
#pragma unroll
    for (int o = 8; o; o >>= 1) v += __shfl_xor_sync(FULLMASK, v, o);
    return v;
}
__device__ __forceinline__ float gelu_tanh(float x){
    float y = 0.7978845608028654f * (x + 0.044715f * x * x * x);
    y = fminf(fmaxf(y, -30.f), 30.f);
    float t = __expf(2.f * y);
    float th = (t - 1.f) / (t + 1.f);
    return 0.5f * x * (1.f + th);
}
__device__ __forceinline__ float sigmoidf_(float x){
    return 1.f / (1.f + __expf(-x));
}
__device__ __forceinline__ uint32_t f2tf32(float x){
    uint32_t r;
    asm("cvt.rna.tf32.f32 %0, %1;" : "=r"(r) : "f"(x));
    return r;
}
__device__ __forceinline__ void mma_tf32(float* c, const uint32_t* a, const uint32_t* b){
    asm volatile("mma.sync.aligned.m16n8k8.row.col.f32.tf32.tf32.f32 "
        "{%0,%1,%2,%3}, {%4,%5,%6,%7}, {%8,%9}, {%0,%1,%2,%3};"
        : "+f"(c[0]), "+f"(c[1]), "+f"(c[2]), "+f"(c[3])
        : "r"(a[0]), "r"(a[1]), "r"(a[2]), "r"(a[3]), "r"(b[0]), "r"(b[1]));
}
__device__ __forceinline__ void mma_f16(float* c, const uint32_t* a, const uint32_t* b){
    asm volatile("mma.sync.aligned.m16n8k16.row.col.f32.f16.f16.f32 "
        "{%0,%1,%2,%3}, {%4,%5,%6,%7}, {%8,%9}, {%0,%1,%2,%3};"
        : "+f"(c[0]), "+f"(c[1]), "+f"(c[2]), "+f"(c[3])
        : "r"(a[0]), "r"(a[1]), "r"(a[2]), "r"(a[3]), "r"(b[0]), "r"(b[1]));
}

// fp16 mma helper over smem operands:
// A: fp16 [m][k], strideA2 in half2 units; B: fp16 [n][k], strideB2 in half2 units.
// Warp tile 64(m) x 16(n): 4 m-tiles x 2 n-tiles of m16n8k16.
template<int KS>
__device__ __forceinline__ void warp_gemm_f16(
    const uint32_t* __restrict__ Xu, int strideA2,
    const uint32_t* __restrict__ Wu, int strideB2,
    int wm, int wn, int g, int tq, float acc[4][2][4])
{
#pragma unroll
    for (int ks = 0; ks < KS; ks++){
        int kh = ks*8;
        uint32_t a[4][4], b[2][2];
#pragma unroll
        for (int mt = 0; mt < 4; mt++){
            int rm = wm + mt*16 + g;
            a[mt][0] = Xu[rm*strideA2 + kh + tq];
            a[mt][1] = Xu[(rm+8)*strideA2 + kh + tq];
            a[mt][2] = Xu[rm*strideA2 + kh + tq + 4];
            a[mt][3] = Xu[(rm+8)*strideA2 + kh + tq + 4];
        }
#pragma unroll
        for (int nt = 0; nt < 2; nt++){
            int n = wn + nt*8 + g;
            b[nt][0] = Wu[n*strideB2 + kh + tq];
            b[nt][1] = Wu[n*strideB2 + kh + tq + 4];
        }
#pragma unroll
        for (int mt = 0; mt < 4; mt++)
#pragma unroll
            for (int nt = 0; nt < 2; nt++)
                mma_f16(acc[mt][nt], a[mt], b[nt]);
    }
}

// ---------------- LayerNorm over 768 ----------------
__global__ __launch_bounds__(256) void ln768_kernel(
    const float* __restrict__ x, const float* __restrict__ g,
    const float* __restrict__ b, float* __restrict__ y)
{
    int row = blockIdx.x;
    int tid = threadIdx.x;
    const float* xr = x + (size_t)row * DD_;
    float*       yr = y + (size_t)row * DD_;
    float v0 = xr[tid], v1 = xr[tid+256], v2 = xr[tid+512];
    __shared__ float red[8];
    float s = warpSum(v0 + v1 + v2);
    if ((tid & 31) == 0) red[tid >> 5] = s;
    __syncthreads();
    float tot = 0.f;
#pragma unroll
    for (int i = 0; i < 8; i++) tot += red[i];
    __syncthreads();
    float mean = tot * (1.f/768.f);
    float d0 = v0-mean, d1 = v1-mean, d2 = v2-mean;
    float q = warpSum(d0*d0 + d1*d1 + d2*d2);
    if ((tid & 31) == 0) red[tid >> 5] = q;
    __syncthreads();
    float vt = 0.f;
#pragma unroll
    for (int i = 0; i < 8; i++) vt += red[i];
    float rstd = rsqrtf(vt * (1.f/768.f) + 1e-5f);
    yr[tid]     = d0*rstd*g[tid]     + b[tid];
    yr[tid+256] = d1*rstd*g[tid+256] + b[tid+256];
    yr[tid+512] = d2*rstd*g[tid+512] + b[tid+512];
}

// ---------------- tf32 tensor-core GEMM, CTA 128x128, warp 64x32 ----------------
template<int EPI>   // 0 none, 1 gelu
__global__ __launch_bounds__(256) void gemm_tf32(
    const float* __restrict__ A, const float* __restrict__ Bm,
    const float* __restrict__ bias, const float* __restrict__ R,
    float* __restrict__ C, int M, int N, int K)
{
    __shared__ uint32_t sA[16][136];
    __shared__ uint32_t sB[16][136];
    int tid = threadIdx.x;
    int m0 = blockIdx.y * 128, n0 = blockIdx.x * 128;
    int lane = tid & 31, warp = tid >> 5;
    int wr = warp >> 2, wc = warp & 3;
    int g  = lane >> 2, tg = lane & 3;
    int ar = tid >> 1, ak = (tid & 1) * 8;
    int bk = tid >> 4, bn = (tid & 15) * 8;

    float acc[4][4][4];
#pragma unroll
    for (int mb = 0; mb < 4; mb++)
#pragma unroll
        for (int nb = 0; nb < 4; nb++)
#pragma unroll
            for (int r = 0; r < 4; r++) acc[mb][nb][r] = 0.f;

    for (int k0 = 0; k0 < K; k0 += 16){
        const float* ap = &A[(size_t)(m0+ar)*K + k0 + ak];
        float4 a0 = *(const float4*)ap;
        float4 a1 = *(const float4*)(ap+4);
        sA[ak+0][ar]=f2tf32(a0.x); sA[ak+1][ar]=f2tf32(a0.y);
        sA[ak+2][ar]=f2tf32(a0.z); sA[ak+3][ar]=f2tf32(a0.w);
        sA[ak+4][ar]=f2tf32(a1.x); sA[ak+5][ar]=f2tf32(a1.y);
        sA[ak+6][ar]=f2tf32(a1.z); sA[ak+7][ar]=f2tf32(a1.w);
        const float* bp = &Bm[(size_t)(k0+bk)*N + n0 + bn];
        float4 b0 = *(const float4*)bp;
        float4 b1 = *(const float4*)(bp+4);
        sB[bk][bn+0]=f2tf32(b0.x); sB[bk][bn+1]=f2tf32(b0.y);
        sB[bk][bn+2]=f2tf32(b0.z); sB[bk][bn+3]=f2tf32(b0.w);
        sB[bk][bn+4]=f2tf32(b1.x); sB[bk][bn+5]=f2tf32(b1.y);
        sB[bk][bn+6]=f2tf32(b1.z); sB[bk][bn+7]=f2tf32(b1.w);
        __syncthreads();
#pragma unroll
        for (int ks = 0; ks < 16; ks += 8){
            uint32_t af[4][4], bf[4][2];
#pragma unroll
            for (int mb = 0; mb < 4; mb++){
                int mrow = wr*64 + mb*16 + g;
                af[mb][0] = sA[ks+tg  ][mrow];
                af[mb][1] = sA[ks+tg  ][mrow+8];
                af[mb][2] = sA[ks+tg+4][mrow];
                af[mb][3] = sA[ks+tg+4][mrow+8];
            }
#pragma unroll
            for (int nb = 0; nb < 4; nb++){
                int ncol = wc*32 + nb*8 + g;
                bf[nb][0] = sB[ks+tg  ][ncol];
                bf[nb][1] = sB[ks+tg+4][ncol];
            }
#pragma unroll
            for (int mb = 0; mb < 4; mb++)
#pragma unroll
                for (int nb = 0; nb < 4; nb++)
                    mma_tf32(acc[mb][nb], af[mb], bf[nb]);
        }
        __syncthreads();
    }
#pragma unroll
    for (int mb = 0; mb < 4; mb++){
#pragma unroll
        for (int nb = 0; nb < 4; nb++){
            int col = n0 + wc*32 + nb*8 + tg*2;
            float bv0 = bias[col], bv1 = bias[col+1];
#pragma unroll
            for (int hf = 0; hf < 2; hf++){
                int row = m0 + wr*64 + mb*16 + g + hf*8;
                float v0 = acc[mb][nb][hf*2+0] + bv0;
                float v1 = acc[mb][nb][hf*2+1] + bv1;
                if (EPI == 1){ v0 = gelu_tanh(v0); v1 = gelu_tanh(v1); }
                if (R){
                    v0 += R[(size_t)row*N + col];
                    v1 += R[(size_t)row*N + col + 1];
                }
                *(float2*)&C[(size_t)row*N + col] = make_float2(v0, v1);
            }
        }
    }
}

// ---------------- tf32 QKV GEMM with head-transposed scatter ----------------
__global__ __launch_bounds__(256) void gemm_qkv_tf32(
    const float* __restrict__ A, const float* __restrict__ Bm,
    const float* __restrict__ bias,
    float* __restrict__ qt, float* __restrict__ kt, float* __restrict__ vt)
{
    const int N = 2304, K = 768;
    __shared__ uint32_t sA[16][136];
    __shared__ uint32_t sB[16][136];
    int tid = threadIdx.x;
    int m0 = blockIdx.y * 128, n0 = blockIdx.x * 128;
    int lane = tid & 31, warp = tid >> 5;
    int wr = warp >> 2, wc = warp & 3;
    int g  = lane >> 2, tg = lane & 3;
    int ar = tid >> 1, ak = (tid & 1) * 8;
    int bk = tid >> 4, bn = (tid & 15) * 8;

    float acc[4][4][4];
#pragma unroll
    for (int mb = 0; mb < 4; mb++)
#pragma unroll
        for (int nb = 0; nb < 4; nb++)
#pragma unroll
            for (int r = 0; r < 4; r++) acc[mb][nb][r] = 0.f;

    for (int k0 = 0; k0 < K; k0 += 16){
        const float* ap = &A[(size_t)(m0+ar)*K + k0 + ak];
        float4 a0 = *(const float4*)ap;
        float4 a1 = *(const float4*)(ap+4);
        sA[ak+0][ar]=f2tf32(a0.x); sA[ak+1][ar]=f2tf32(a0.y);
        sA[ak+2][ar]=f2tf32(a0.z); sA[ak+3][ar]=f2tf32(a0.w);
        sA[ak+4][ar]=f2tf32(a1.x); sA[ak+5][ar]=f2tf32(a1.y);
        sA[ak+6][ar]=f2tf32(a1.z); sA[ak+7][ar]=f2tf32(a1.w);
        const float* bp = &Bm[(size_t)(k0+bk)*N + n0 + bn];
        float4 b0 = *(const float4*)bp;
        float4 b1 = *(const float4*)(bp+4);
        sB[bk][bn+0]=f2tf32(b0.x); sB[bk][bn+1]=f2tf32(b0.y);
        sB[bk][bn+2]=f2tf32(b0.z); sB[bk][bn+3]=f2tf32(b0.w);
        sB[bk][bn+4]=f2tf32(b1.x); sB[bk][bn+5]=f2tf32(b1.y);
        sB[bk][bn+6]=f2tf32(b1.z); sB[bk][bn+7]=f2tf32(b1.w);
        __syncthreads();
#pragma unroll
        for (int ks = 0; ks < 16; ks += 8){
            uint32_t af[4][4], bf[4][2];
#pragma unroll
            for (int mb = 0; mb < 4; mb++){
                int mrow = wr*64 + mb*16 + g;
                af[mb][0] = sA[ks+tg  ][mrow];
                af[mb][1] = sA[ks+tg  ][mrow+8];
                af[mb][2] = sA[ks+tg+4][mrow];
                af[mb][3] = sA[ks+tg+4][mrow+8];
            }
#pragma unroll
            for (int nb = 0; nb < 4; nb++){
                int ncol = wc*32 + nb*8 + g;
                bf[nb][0] = sB[ks+tg  ][ncol];
                bf[nb][1] = sB[ks+tg+4][ncol];
            }
#pragma unroll
            for (int mb = 0; mb < 4; mb++)
#pragma unroll
                for (int nb = 0; nb < 4; nb++)
                    mma_tf32(acc[mb][nb], af[mb], bf[nb]);
        }
        __syncthreads();
    }
#pragma unroll
    for (int mb = 0; mb < 4; mb++){
#pragma unroll
        for (int hf = 0; hf < 2; hf++){
            int m = m0 + wr*64 + mb*16 + g + hf*8;
            int b = m >> 8, l = m & 255;
#pragma unroll
            for (int nb = 0; nb < 4; nb++){
#pragma unroll
                for (int e = 0; e < 2; e++){
                    int n = n0 + wc*32 + nb*8 + tg*2 + e;
                    float v = acc[mb][nb][hf*2+e] + bias[n];
                    int seg = n / 768;
                    int nn = n - seg*768;
                    int dd = nn >> 5, h = nn & 31;
                    size_t idx = (((size_t)(b*32 + h))*256 + l)*24 + dd;
                    if (seg == 0)      qt[idx] = v * SCALE_Q;
                    else if (seg == 1) kt[idx] = v;
                    else               vt[idx] = v;
                }
            }
        }
    }
}

// ---------------- QK kernel ----------------
__global__ __launch_bounds__(256) void qk_kernel(
    const float* __restrict__ qt, const float* __restrict__ kt,
    float* __restrict__ qk)
{
    int bh = blockIdx.y;
    int l0 = (blockIdx.x >> 1) * 128;
    int m0 = (blockIdx.x & 1) * 128;
    __shared__ float sQ[24*132];
    __shared__ float sK[24*132];
    int tid = threadIdx.x;
    const float* qb = qt + (size_t)bh*6144 + (size_t)l0*24;
    const float* kb = kt + (size_t)bh*6144 + (size_t)m0*24;
    for (int i = tid; i < 3072; i += 256){
        int r = i / 24, d = i - r*24;
        sQ[d*132 + r] = qb[i];
        sK[d*132 + r] = kb[i];
    }
    __syncthreads();
    int tx = tid & 15, ty = tid >> 4;
    float acc[8][8];
#pragma unroll
    for (int i = 0; i < 8; i++)
#pragma unroll
        for (int j = 0; j < 8; j++) acc[i][j] = 0.f;
#pragma unroll 6
    for (int k = 0; k < 24; k++){
        float4 a0 = *(const float4*)&sQ[k*132 + ty*8];
        float4 a1 = *(const float4*)&sQ[k*132 + ty*8 + 4];
        float4 b0 = *(const float4*)&sK[k*132 + tx*8];
        float4 b1 = *(const float4*)&sK[k*132 + tx*8 + 4];
        float a[8] = {a0.x,a0.y,a0.z,a0.w,a1.x,a1.y,a1.z,a1.w};
        float b[8] = {b0.x,b0.y,b0.z,b0.w,b1.x,b1.y,b1.z,b1.w};
#pragma unroll
        for (int i = 0; i < 8; i++)
#pragma unroll
            for (int j = 0; j < 8; j++) acc[i][j] += a[i]*b[j];
    }
    float* out = qk + (size_t)bh*65536 + (size_t)l0*256 + m0;
#pragma unroll
    for (int i = 0; i < 8; i++){
        float* orow = out + (size_t)(ty*8 + i)*256 + tx*8;
        *(float4*)orow     = make_float4(acc[i][0],acc[i][1],acc[i][2],acc[i][3]);
        *(float4*)(orow+4) = make_float4(acc[i][4],acc[i][5],acc[i][6],acc[i][7]);
    }
}

// ---------------- fused edge kernel: fp16 mma.sync version ----------------
// One CTA per (b,l), 512 threads, 2 groups of 8 warps; group owns 128 edges.
// smem float layout:
//   sPar   [512]            @0
//   sHhat  [32][260] f32    @512
//   sGate  [32][260] f32    @8832
//   sMask  [256]            @17152
//   weights fp16 (16384 h = 8192 f) @17408:
//     Weg_t[64][72]h, W1_t[64][72]h, W2_t[64][72]h, Woe_t[64][40]h
//   per group (10112 f) @25600 + grp*10112:
//     sQKc [32][132] f32 (4224), sX16 [128][72]h (2304 f),
//     sH16 [128][40]h (2560 f), sRed [128][4] float2 (1024 f)
#define EK_FLOATS 45824
__global__ __launch_bounds__(512, 1) void edge_attn_kernel(
    const float* __restrict__ e_in, const float* __restrict__ mask,
    const float* __restrict__ qk,
    const float* __restrict__ W_eg, const float* __restrict__ b_eg,
    const float* __restrict__ W_oe, const float* __restrict__ b_oe,
    const float* __restrict__ eln_g, const float* __restrict__ eln_b,
    const float* __restrict__ ffn_g, const float* __restrict__ ffn_b,
    const float* __restrict__ eW1, const float* __restrict__ eb1,
    const float* __restrict__ eW2, const float* __restrict__ eb2,
    float* __restrict__ e_out, float* __restrict__ a_all)
{
    extern __shared__ float sm[];
    float* sPar  = sm;
    float* sHhat = sm + 512;
    float* sGate = sm + 8832;
    float* sMask = sm + 17152;
    __half* sW16 = (__half*)(sm + 17408);
    __half* Weg_t = sW16;           // [64][72]
    __half* W1_t  = sW16 + 4608;    // [64][72]
    __half* W2_t  = sW16 + 9216;    // [64][72]
    __half* Woe_t = sW16 + 13824;   // [64][40]

    int tid  = threadIdx.x;
    int grp  = tid >> 8;
    int t    = tid & 255;
    int lane = tid & 31;
    int g    = lane >> 2;
    int tq   = lane & 3;
    int wg8  = (tid >> 5) & 7;             // warp within group
    int wm   = (wg8 >> 2) * 64;            // warp m offset (0/64)
    int wn   = (wg8 & 3) * 16;             // warp n offset (0/16/32/48)
    int w    = tid >> 5;                   // 0..15 (for softmax)
    int row  = blockIdx.x;
    int b    = row >> 8;
    int l    = row & 255;
    int m0g  = grp * 128;

    float* grpBase = sm + 25600 + grp*10112;
    float* sQKc = grpBase;                       // [32][132]
    __half* sX16 = (__half*)(grpBase + 4224);    // [128][72]
    __half* sH16 = (__half*)(grpBase + 6528);    // [128][40]
    float*  sRed = grpBase + 9088;               // [128][4] float2

    size_t qkbase = ((size_t)b*32)*65536 + (size_t)l*256;

    // ---- stage weights (fp16 transposed), params, qk, mask ----
    for (int i = tid; i < 4096; i += 512){
        int k = i >> 6, n = i & 63;
        Weg_t[n*72 + k] = __float2half(W_eg[i]);
        W1_t [n*72 + k] = __float2half(eW1[i]);
        W2_t [n*72 + k] = __float2half(eW2[i]);
    }
    for (int i = tid; i < 2048; i += 512){
        int k = i >> 6, n = i & 63;
        Woe_t[n*40 + k] = __float2half(W_oe[i]);
    }
    if (tid < 64){
        sPar[tid]     = b_eg[tid];
        sPar[64+tid]  = b_oe[tid];
        sPar[128+tid] = eb1[tid];
        sPar[192+tid] = eb2[tid];
        sPar[256+tid] = eln_g[tid];
        sPar[320+tid] = eln_b[tid];
        sPar[384+tid] = ffn_g[tid];
        sPar[448+tid] = ffn_b[tid];
    }
    for (int i = t; i < 1024; i += 256){
        int h = i >> 5, mq = (i & 31) * 4;
        *(float4*)&sQKc[h*132 + mq] =
            *(const float4*)&qk[qkbase + (size_t)h*65536 + m0g + mq];
    }
    if (t < 128) sMask[m0g + t] = mask[(size_t)row*256 + m0g + t];
    __syncthreads();

    // ---- LN1: thread-mapped, store fp16 X[m][k] ----
    {
        int ty = t >> 4, tx = t & 15;
        float lg0 = sPar[256+tx*4], lg1 = sPar[257+tx*4], lg2 = sPar[258+tx*4], lg3 = sPar[259+tx*4];
        float lb0 = sPar[320+tx*4], lb1 = sPar[321+tx*4], lb2 = sPar[322+tx*4], lb3 = sPar[323+tx*4];
        __half2* xp = (__half2*)sX16;
#pragma unroll
        for (int i = 0; i < 8; i++){
            int r = ty*8 + i;
            float4 e4 = *(const float4*)&e_in[((size_t)row*256 + m0g + r)*64 + tx*4];
            float s = sum16(e4.x + e4.y + e4.z + e4.w);
            float mean = s * (1.f/64.f);
            float d0=e4.x-mean, d1=e4.y-mean, d2=e4.z-mean, d3=e4.w-mean;
            float q = sum16(d0*d0 + d1*d1 + d2*d2 + d3*d3);
            float rs = rsqrtf(q * (1.f/64.f) + 1e-5f);
            xp[r*36 + tx*2    ] = __floats2half2_rn(d0*rs*lg0 + lb0, d1*rs*lg1 + lb1);
            xp[r*36 + tx*2 + 1] = __floats2half2_rn(d2*rs*lg2 + lb2, d3*rs*lg3 + lb3);
        }
    }
    __syncthreads();

    float acc[4][2][4];
    const uint32_t* Xu  = (const uint32_t*)sX16;
    const uint32_t* Hu  = (const uint32_t*)sH16;

    // ---- GEMM1: EG = X @ W_eg (K=64) ----
#pragma unroll
    for (int mt=0;mt<4;mt++)
#pragma unroll
        for (int nt=0;nt<2;nt++)
#pragma unroll
            for (int c=0;c<4;c++) acc[mt][nt][c]=0.f;
    warp_gemm_f16<4>(Xu, 36, (const uint32_t*)Weg_t, 36, wm, wn, g, tq, acc);

    if (wn < 32){
        // E columns -> H_hat (fp32 h-major + fp16 m-major)
        __half2* hp = (__half2*)sH16;
#pragma unroll
        for (int mt=0;mt<4;mt++)
#pragma unroll
            for (int nt=0;nt<2;nt++){
                int nc = wn + nt*8 + 2*tq;
#pragma unroll
                for (int rh=0;rh<2;rh++){
                    int m = wm + mt*16 + g + rh*8;
                    float v0 = acc[mt][nt][rh*2+0] + sPar[nc]   + sQKc[nc*132 + m];
                    float v1 = acc[mt][nt][rh*2+1] + sPar[nc+1] + sQKc[(nc+1)*132 + m];
                    sHhat[nc*260 + m0g + m]     = v0;
                    sHhat[(nc+1)*260 + m0g + m] = v1;
                    hp[m*20 + (nc>>1)] = __floats2half2_rn(v0, v1);
                }
            }
    } else {
        // G columns -> gates
#pragma unroll
        for (int mt=0;mt<4;mt++)
#pragma unroll
            for (int nt=0;nt<2;nt++){
                int nc = wn + nt*8 + 2*tq;
#pragma unroll
                for (int rh=0;rh<2;rh++){
                    int m = wm + mt*16 + g + rh*8;
                    float mk = sMask[m0g + m];
                    sGate[(nc-32)*260 + m0g + m]   = sigmoidf_(acc[mt][nt][rh*2+0] + sPar[nc]   + mk);
                    sGate[(nc-31)*260 + m0g + m]   = sigmoidf_(acc[mt][nt][rh*2+1] + sPar[nc+1] + mk);
                }
            }
    }
    __syncthreads();

    // ---- GEMM2: e_att = H_hat @ W_oe (K=32); r = e + e_att + b_oe ----
#pragma unroll
    for (int mt=0;mt<4;mt++)
#pragma unroll
        for (int nt=0;nt<2;nt++)
#pragma unroll
            for (int c=0;c<4;c++) acc[mt][nt][c]=0.f;
    warp_gemm_f16<2>(Hu, 20, (const uint32_t*)Woe_t, 20, wm, wn, g, tq, acc);

    float r_[4][2][4];
#pragma unroll
    for (int mt=0;mt<4;mt++)
#pragma unroll
        for (int nt=0;nt<2;nt++){
            int nc = wn + nt*8 + 2*tq;
            int m  = wm + mt*16 + g;
            const float* ep = &e_in[((size_t)row*256 + m0g + m)*64 + nc];
            float2 ea = *(const float2*)ep;
            float2 eb = *(const float2*)(ep + 8*64);
            r_[mt][nt][0] = ea.x + acc[mt][nt][0] + sPar[64+nc];
            r_[mt][nt][1] = ea.y + acc[mt][nt][1] + sPar[64+nc+1];
            r_[mt][nt][2] = eb.x + acc[mt][nt][2] + sPar[64+nc];
            r_[mt][nt][3] = eb.y + acc[mt][nt][3] + sPar[64+nc+1];
        }

    // ---- LN2 on r (fragments): quad-reduce + cross-warp smem reduce ----
    {
        float2* rp = (float2*)sRed;
#pragma unroll
        for (int mt=0;mt<4;mt++)
#pragma unroll
            for (int rh=0;rh<2;rh++){
                float ps = r_[mt][0][rh*2] + r_[mt][0][rh*2+1]
                         + r_[mt][1][rh*2] + r_[mt][1][rh*2+1];
                float pq = r_[mt][0][rh*2]*r_[mt][0][rh*2] + r_[mt][0][rh*2+1]*r_[mt][0][rh*2+1]
                         + r_[mt][1][rh*2]*r_[mt][1][rh*2] + r_[mt][1][rh*2+1]*r_[mt][1][rh*2+1];
                ps += __shfl_xor_sync(FULLMASK, ps, 1);
                ps += __shfl_xor_sync(FULLMASK, ps, 2);
                pq += __shfl_xor_sync(FULLMASK, pq, 1);
                pq += __shfl_xor_sync(FULLMASK, pq, 2);
                if (tq == 0){
                    int m = wm + mt*16 + g + rh*8;
                    rp[m*4 + (wg8 & 3)] = make_float2(ps, pq);
                }
            }
    }
    __syncthreads();
    {
        __half2* xp = (__half2*)sX16;
        const float2* rp = (const float2*)sRed;
#pragma unroll
        for (int mt=0;mt<4;mt++)
#pragma unroll
            for (int rh=0;rh<2;rh++){
                int m = wm + mt*16 + g + rh*8;
                float2 p0 = rp[m*4+0], p1 = rp[m*4+1], p2 = rp[m*4+2], p3 = rp[m*4+3];
                float mu = (p0.x+p1.x+p2.x+p3.x) * (1.f/64.f);
                float vq = (p0.y+p1.y+p2.y+p3.y) * (1.f/64.f) - mu*mu;
                float rs = rsqrtf(vq + 1e-5f);
#pragma unroll
                for (int nt=0;nt<2;nt++){
                    int nc = wn + nt*8 + 2*tq;
                    float v0 = (r_[mt][nt][rh*2+0]-mu)*rs*sPar[384+nc]   + sPar[448+nc];
                    float v1 = (r_[mt][nt][rh*2+1]-mu)*rs*sPar[384+nc+1] + sPar[448+nc+1];
                    xp[m*36 + (nc>>1)] = __floats2half2_rn(v0, v1);
                }
            }
    }
    __syncthreads();

    // ---- GEMM3: T = gelu(X2 @ eW1 + b1) ----
#pragma unroll
    for (int mt=0;mt<4;mt++)
#pragma unroll
        for (int nt=0;nt<2;nt++)
#pragma unroll
            for (int c=0;c<4;c++) acc[mt][nt][c]=0.f;
    warp_gemm_f16<4>(Xu, 36, (const uint32_t*)W1_t, 36, wm, wn, g, tq, acc);
    __syncthreads();   // all X2 reads complete before overwrite
    {
        __half2* xp = (__half2*)sX16;
#pragma unroll
        for (int mt=0;mt<4;mt++)
#pragma unroll
            for (int nt=0;nt<2;nt++){
                int nc = wn + nt*8 + 2*tq;
#pragma unroll
                for (int rh=0;rh<2;rh++){
                    int m = wm + mt*16 + g + rh*8;
                    float v0 = gelu_tanh(acc[mt][nt][rh*2+0] + sPar[128+nc]);
                    float v1 = gelu_tanh(acc[mt][nt][rh*2+1] + sPar[128+nc+1]);
                    xp[m*36 + (nc>>1)] = __floats2half2_rn(v0, v1);
                }
            }
    }
    __syncthreads();

    // ---- GEMM4: O = T @ eW2 + b2 ; e_out = r + O ----
#pragma unroll
    for (int mt=0;mt<4;mt++)
#pragma unroll
        for (int nt=0;nt<2;nt++)
#pragma unroll
            for (int c=0;c<4;c++) acc[mt][nt][c]=0.f;
    warp_gemm_f16<4>(Xu, 36, (const uint32_t*)W2_t, 36, wm, wn, g, tq, acc);
#pragma unroll
    for (int mt=0;mt<4;mt++)
#pragma unroll
        for (int nt=0;nt<2;nt++){
            int nc = wn + nt*8 + 2*tq;
            int m  = wm + mt*16 + g;
            float* op = &e_out[((size_t)row*256 + m0g + m)*64 + nc];
            *(float2*)op = make_float2(
                r_[mt][nt][0] + acc[mt][nt][0] + sPar[192+nc],
                r_[mt][nt][1] + acc[mt][nt][1] + sPar[192+nc+1]);
            *(float2*)(op + 8*64) = make_float2(
                r_[mt][nt][2] + acc[mt][nt][2] + sPar[192+nc],
                r_[mt][nt][3] + acc[mt][nt][3] + sPar[192+nc+1]);
        }

    // ---- softmax over m per head, fold gates & degree ----
    // (sHhat/sGate written before the GEMM2 barrier by both groups)
#pragma unroll
    for (int hi = 0; hi < 2; hi++){
        int h = w + hi*16;
        float p[8], gg[8];
        float mx = -3.4e38f;
#pragma unroll
        for (int j = 0; j < 8; j++){
            int m = j*32 + lane;
            p[j] = sHhat[h*260 + m] + sMask[m];
            mx = fmaxf(mx, p[j]);
        }
        mx = warpMax(mx);
        float s = 0.f, gs = 0.f;
#pragma unroll
        for (int j = 0; j < 8; j++){
            p[j] = __expf(p[j] - mx);
            s += p[j];
            gg[j] = sGate[h*260 + j*32 + lane];
            gs += gg[j];
        }
        s = warpSum(s); gs = warpSum(gs);
        float c = (1.f / s) * log1pf(gs);
        float* ao = a_all + (((size_t)(b*32 + h))*256 + l)*256;
#pragma unroll
        for (int j = 0; j < 8; j++)
            ao[j*32 + lane] = p[j] * gg[j] * c;
    }
}

// ---------------- AV kernel ----------------
#define AV_FLOATS (64*260 + 24*260)
__global__ __launch_bounds__(256) void av_kernel(
    const float* __restrict__ a_all, const float* __restrict__ vt,
    float* __restrict__ vatt)
{
    extern __shared__ float sm[];
    float* sA = sm;
    float* sV = sm + 64*260;
    int bh = blockIdx.y;
    int l0 = blockIdx.x * 64;
    int b = bh >> 5, h = bh & 31;
    int tid = threadIdx.x;
    const float* ab = a_all + (size_t)bh*65536 + (size_t)l0*256;
    for (int i = tid; i < 4096; i += 256){
        int ll = i >> 6, m = (i & 63) * 4;
        *(float4*)&sA[ll*260 + m] = *(const float4*)&ab[(size_t)ll*256 + m];
    }
    const float* vb = vt + (size_t)bh*6144;
    for (int i = tid; i < 6144; i += 256){
        int m = i / 24, dd = i - m*24;
        sV[dd*260 + m] = vb[i];
    }
    __syncthreads();
    int w = tid >> 5, lane = tid & 31;
    if (lane < 24){
        const float* vr = &sV[lane*260];
#pragma unroll
        for (int j = 0; j < 8; j++){
            int ll = w*8 + j;
            const float* ar = &sA[ll*260];
            float acc = 0.f;
#pragma unroll 8
            for (int m = 0; m < 256; m += 4){
                float4 a = *(const float4*)&ar[m];
                float4 v = *(const float4*)&vr[m];
                acc += a.x*v.x + a.y*v.y + a.z*v.z + a.w*v.w;
            }
            vatt[(size_t)(b*256 + l0 + ll)*768 + lane*32 + h] = acc;
        }
    }
}

// ---------------- host ----------------
extern "C" void kernel_launch(void* const* d_in, const int* in_sizes, int n_in,
                              void* d_out, int out_size)
{
    const float* h_in   = (const float*)d_in[0];
    const float* e_in   = (const float*)d_in[1];
    const float* mask   = (const float*)d_in[2];
    const float* ln_h_g = (const float*)d_in[3];
    const float* ln_h_b = (const float*)d_in[4];
    const float* ln_e_g = (const float*)d_in[5];
    const float* ln_e_b = (const float*)d_in[6];
    const float* W_qkv  = (const float*)d_in[7];
    const float* b_qkv  = (const float*)d_in[8];
    const float* W_eg   = (const float*)d_in[9];
    const float* b_eg   = (const float*)d_in[10];
    const float* W_oh   = (const float*)d_in[11];
    const float* b_oh   = (const float*)d_in[12];
    const float* W_oe   = (const float*)d_in[13];
    const float* b_oe   = (const float*)d_in[14];
    const float* nffn_g = (const float*)d_in[15];
    const float* nffn_b = (const float*)d_in[16];
    const float* nW1    = (const float*)d_in[17];
    const float* nb1    = (const float*)d_in[18];
    const float* nW2    = (const float*)d_in[19];
    const float* nb2    = (const float*)d_in[20];
    const float* effn_g = (const float*)d_in[21];
    const float* effn_b = (const float*)d_in[22];
    const float* eW1    = (const float*)d_in[23];
    const float* eb1    = (const float*)d_in[24];
    const float* eW2    = (const float*)d_in[25];
    const float* eb2    = (const float*)d_in[26];

    float* out_h = (float*)d_out;
    float* out_e = out_h + (size_t)ROWS * DD_;

    float *hln, *qt, *kt, *vt, *qk, *aa, *vatt, *hmid, *hln2, *tbuf;
    cudaGetSymbolAddress((void**)&hln,  g_hln);
    cudaGetSymbolAddress((void**)&qt,   g_qt);
    cudaGetSymbolAddress((void**)&kt,   g_kt);
    cudaGetSymbolAddress((void**)&vt,   g_vt);
    cudaGetSymbolAddress((void**)&qk,   g_qk);
    cudaGetSymbolAddress((void**)&aa,   g_a);
    cudaGetSymbolAddress((void**)&vatt, g_vatt);
    cudaGetSymbolAddress((void**)&hmid, g_hmid);
    cudaGetSymbolAddress((void**)&hln2, g_hln2);
    cudaGetSymbolAddress((void**)&tbuf, g_t);

    cudaFuncSetAttribute(edge_attn_kernel,
                         cudaFuncAttributeMaxDynamicSharedMemorySize,
                         EK_FLOATS * 4);
    cudaFuncSetAttribute(av_kernel,
                         cudaFuncAttributeMaxDynamicSharedMemorySize,
                         AV_FLOATS * 4);

    // 1) h layernorm
    ln768_kernel<<<ROWS, 256>>>(h_in, ln_h_g, ln_h_b, hln);

    // 2) QKV GEMM (tf32) with transposed scatter
    gemm_qkv_tf32<<<dim3(18, 16), 256>>>(hln, W_qkv, b_qkv, qt, kt, vt);

    // 3) QK = Q K^T per head
    qk_kernel<<<dim3(4, 256), 256>>>(qt, kt, qk);

    // 4) fused edge attention + edge FFN (fp16 mma) -> e_out, A'
    edge_attn_kernel<<<ROWS, 512, EK_FLOATS * 4>>>(
        e_in, mask, qk,
        W_eg, b_eg, W_oe, b_oe,
        ln_e_g, ln_e_b, effn_g, effn_b,
        eW1, eb1, eW2, eb2,
        out_e, aa);

    // 5) V_att = A' @ V
    av_kernel<<<dim3(4, 256), 256, AV_FLOATS * 4>>>(aa, vt, vatt);

    // 6) h_mid = h + V_att @ W_oh + b_oh   (tf32)
    gemm_tf32<0><<<dim3(6, 16), 256>>>(vatt, W_oh, b_oh, h_in, hmid,
                                       ROWS, DD_, DD_);

    // 7) node FFN (tf32)
    ln768_kernel<<<ROWS, 256>>>(hmid, nffn_g, nffn_b, hln2);
    gemm_tf32<1><<<dim3(6, 16), 256>>>(hln2, nW1, nb1, nullptr, tbuf,
                                       ROWS, DD_, DD_);
    gemm_tf32<0><<<dim3(6, 16), 256>>>(tbuf, nW2, nb2, hmid, out_h,
                                       ROWS, DD_, DD_);
}

// round 8
// speedup vs baseline: 2.4033x; 1.1785x over previous
#include <cuda_runtime.h>
#include <cuda_fp16.h>
#include <cstddef>
#include <cstdint>

// ---------------- problem constants ----------------
#define BB 8
#define NN 256
#define DD_ 768
#define ROWS (BB*NN)     // 2048
#define SCALE_Q 0.20412414523193154f   // 24^-0.5
#define FULLMASK 0xffffffffu

// ---------------- scratch (device globals; no allocation) ----------------
__device__ float  g_qt  [8*32*256*24];
__device__ float  g_kt  [8*32*256*24];
__device__ float  g_vt  [8*32*256*24];
__device__ float  g_qk  [8*32*256*256];
__device__ float  g_a   [8*32*256*256];
__device__ float  g_hmid[ROWS*DD_];
__device__ __half g_hln16 [ROWS*DD_];
__device__ __half g_hln216[ROWS*DD_];
__device__ __half g_t16   [ROWS*DD_];
__device__ __half g_vatt16[ROWS*DD_];
__device__ __half g_wqkv16[2304*768];
__device__ __half g_woh16 [768*768];
__device__ __half g_nw116 [768*768];
__device__ __half g_nw216 [768*768];

// ---------------- helpers ----------------
__device__ __forceinline__ float warpSum(float v){
#pragma unroll
    for (int o = 16; o; o >>= 1) v += __shfl_xor_sync(FULLMASK, v, o);
    return v;
}
__device__ __forceinline__ float warpMax(float v){
#pragma unroll
    for (int o = 16; o; o >>= 1) v = fmaxf(v, __shfl_xor_sync(FULLMASK, v, o));
    return v;
}
__device__ __forceinline__ float sum16(float v){
#pragma unroll
    for (int o = 8; o; o >>= 1) v += __shfl_xor_sync(FULLMASK, v, o);
    return v;
}
__device__ __forceinline__ float gelu_tanh(float x){
    float y = 0.7978845608028654f * (x + 0.044715f * x * x * x);
    y = fminf(fmaxf(y, -30.f), 30.f);
    float t = __expf(2.f * y);
    float th = (t - 1.f) / (t + 1.f);
    return 0.5f * x * (1.f + th);
}
__device__ __forceinline__ float sigmoidf_(float x){
    return 1.f / (1.f + __expf(-x));
}
__device__ __forceinline__ void mma_f16(float* c, const uint32_t* a, const uint32_t* b){
    asm volatile("mma.sync.aligned.m16n8k16.row.col.f32.f16.f16.f32 "
        "{%0,%1,%2,%3}, {%4,%5,%6,%7}, {%8,%9}, {%0,%1,%2,%3};"
        : "+f"(c[0]), "+f"(c[1]), "+f"(c[2]), "+f"(c[3])
        : "r"(a[0]), "r"(a[1]), "r"(a[2]), "r"(a[3]), "r"(b[0]), "r"(b[1]));
}

// fp16 mma over smem: A [m][k] (strideA2 half2), B [n][k] (strideB2 half2).
// Warp tile 64x16: 4 m-tiles x 2 n-tiles of m16n8k16.
template<int KS>
__device__ __forceinline__ void warp_gemm_f16(
    const uint32_t* __restrict__ Xu, int strideA2,
    const uint32_t* __restrict__ Wu, int strideB2,
    int wm, int wn, int g, int tq, float acc[4][2][4])
{
#pragma unroll
    for (int ks = 0; ks < KS; ks++){
        int kh = ks*8;
        uint32_t a[4][4], b[2][2];
#pragma unroll
        for (int mt = 0; mt < 4; mt++){
            int rm = wm + mt*16 + g;
            a[mt][0] = Xu[rm*strideA2 + kh + tq];
            a[mt][1] = Xu[(rm+8)*strideA2 + kh + tq];
            a[mt][2] = Xu[rm*strideA2 + kh + tq + 4];
            a[mt][3] = Xu[(rm+8)*strideA2 + kh + tq + 4];
        }
#pragma unroll
        for (int nt = 0; nt < 2; nt++){
            int n = wn + nt*8 + g;
            b[nt][0] = Wu[n*strideB2 + kh + tq];
            b[nt][1] = Wu[n*strideB2 + kh + tq + 4];
        }
#pragma unroll
        for (int mt = 0; mt < 4; mt++)
#pragma unroll
            for (int nt = 0; nt < 2; nt++)
                mma_f16(acc[mt][nt], a[mt], b[nt]);
    }
}

// ---------------- weight transpose fp32 [K][N] -> fp16 [N][K] ----------------
__global__ __launch_bounds__(256) void transpose_f16(
    const float* __restrict__ W, __half* __restrict__ Wt, int K, int N)
{
    __shared__ float tile[32][33];
    int k0 = blockIdx.y*32, n0 = blockIdx.x*32;
    int tx = threadIdx.x & 31, ty = threadIdx.x >> 5;   // 32 x 8
    for (int i = ty; i < 32; i += 8)
        tile[i][tx] = W[(size_t)(k0+i)*N + n0 + tx];
    __syncthreads();
    for (int i = ty; i < 32; i += 8)
        Wt[(size_t)(n0+i)*K + k0 + tx] = __float2half(tile[tx][i]);
}

// ---------------- LayerNorm over 768, fp16 out ----------------
__global__ __launch_bounds__(256) void ln768_kernel(
    const float* __restrict__ x, const float* __restrict__ g,
    const float* __restrict__ b, __half* __restrict__ y)
{
    int row = blockIdx.x;
    int tid = threadIdx.x;
    const float* xr = x + (size_t)row * DD_;
    __half*      yr = y + (size_t)row * DD_;
    float v0 = xr[tid], v1 = xr[tid+256], v2 = xr[tid+512];
    __shared__ float red[8];
    float s = warpSum(v0 + v1 + v2);
    if ((tid & 31) == 0) red[tid >> 5] = s;
    __syncthreads();
    float tot = 0.f;
#pragma unroll
    for (int i = 0; i < 8; i++) tot += red[i];
    __syncthreads();
    float mean = tot * (1.f/768.f);
    float d0 = v0-mean, d1 = v1-mean, d2 = v2-mean;
    float q = warpSum(d0*d0 + d1*d1 + d2*d2);
    if ((tid & 31) == 0) red[tid >> 5] = q;
    __syncthreads();
    float vt = 0.f;
#pragma unroll
    for (int i = 0; i < 8; i++) vt += red[i];
    float rstd = rsqrtf(vt * (1.f/768.f) + 1e-5f);
    yr[tid]     = __float2half(d0*rstd*g[tid]     + b[tid]);
    yr[tid+256] = __float2half(d1*rstd*g[tid+256] + b[tid+256]);
    yr[tid+512] = __float2half(d2*rstd*g[tid+512] + b[tid+512]);
}

// ---------------- fp16 tensor-core GEMM, CTA 128x128, warp 64x32, BK=64 ----------------
template<int EPI, int OUTH>
__global__ __launch_bounds__(256) void gemm_f16k(
    const __half* __restrict__ A, const __half* __restrict__ Bt,
    const float* __restrict__ bias, const float* __restrict__ R,
    float* __restrict__ C, __half* __restrict__ Ch, int M, int N, int K)
{
    __shared__ __half sA[128*72];
    __shared__ __half sB[128*72];
    int tid = threadIdx.x;
    int m0 = blockIdx.y * 128, n0 = blockIdx.x * 128;
    int lane = tid & 31, warp = tid >> 5;
    int wm = (warp >> 2) * 64, wn = (warp & 3) * 32;
    int g = lane >> 2, tq = lane & 3;
    int ar = tid >> 1, ac = (tid & 1) * 32;

    const uint32_t* Au = (const uint32_t*)sA;
    const uint32_t* Bu = (const uint32_t*)sB;

    float acc[4][4][4];
#pragma unroll
    for (int mt=0;mt<4;mt++)
#pragma unroll
        for (int nt=0;nt<4;nt++)
#pragma unroll
            for (int c=0;c<4;c++) acc[mt][nt][c]=0.f;

    for (int k0 = 0; k0 < K; k0 += 64){
        const uint4* ap = (const uint4*)&A[(size_t)(m0+ar)*K + k0 + ac];
        uint4* asp = (uint4*)&sA[ar*72 + ac];
        asp[0]=ap[0]; asp[1]=ap[1]; asp[2]=ap[2]; asp[3]=ap[3];
        const uint4* bp = (const uint4*)&Bt[(size_t)(n0+ar)*K + k0 + ac];
        uint4* bsp = (uint4*)&sB[ar*72 + ac];
        bsp[0]=bp[0]; bsp[1]=bp[1]; bsp[2]=bp[2]; bsp[3]=bp[3];
        __syncthreads();
#pragma unroll
        for (int ks = 0; ks < 4; ks++){
            int kh = ks*8;
            uint32_t a[4][4], b[4][2];
#pragma unroll
            for (int mt = 0; mt < 4; mt++){
                int rm = wm + mt*16 + g;
                a[mt][0] = Au[rm*36 + kh + tq];
                a[mt][1] = Au[(rm+8)*36 + kh + tq];
                a[mt][2] = Au[rm*36 + kh + tq + 4];
                a[mt][3] = Au[(rm+8)*36 + kh + tq + 4];
            }
#pragma unroll
            for (int nt = 0; nt < 4; nt++){
                int n = wn + nt*8 + g;
                b[nt][0] = Bu[n*36 + kh + tq];
                b[nt][1] = Bu[n*36 + kh + tq + 4];
            }
#pragma unroll
            for (int mt = 0; mt < 4; mt++)
#pragma unroll
                for (int nt = 0; nt < 4; nt++)
                    mma_f16(acc[mt][nt], a[mt], b[nt]);
        }
        __syncthreads();
    }
#pragma unroll
    for (int mt = 0; mt < 4; mt++){
#pragma unroll
        for (int nt = 0; nt < 4; nt++){
            int n = n0 + wn + nt*8 + 2*tq;
            float b0 = bias[n], b1 = bias[n+1];
#pragma unroll
            for (int rh = 0; rh < 2; rh++){
                int m = m0 + wm + mt*16 + g + rh*8;
                float v0 = acc[mt][nt][rh*2+0] + b0;
                float v1 = acc[mt][nt][rh*2+1] + b1;
                if (EPI == 1){ v0 = gelu_tanh(v0); v1 = gelu_tanh(v1); }
                if (OUTH){
                    *(__half2*)&Ch[(size_t)m*N + n] = __floats2half2_rn(v0, v1);
                } else {
                    if (R){
                        v0 += R[(size_t)m*N + n];
                        v1 += R[(size_t)m*N + n + 1];
                    }
                    *(float2*)&C[(size_t)m*N + n] = make_float2(v0, v1);
                }
            }
        }
    }
}

// ---------------- fp16 QKV GEMM with head-transposed scatter ----------------
__global__ __launch_bounds__(256) void gemm_qkv_f16(
    const __half* __restrict__ A, const __half* __restrict__ Bt,
    const float* __restrict__ bias,
    float* __restrict__ qt, float* __restrict__ kt, float* __restrict__ vt)
{
    const int N = 2304, K = 768;
    __shared__ __half sA[128*72];
    __shared__ __half sB[128*72];
    int tid = threadIdx.x;
    int m0 = blockIdx.y * 128, n0 = blockIdx.x * 128;
    int lane = tid & 31, warp = tid >> 5;
    int wm = (warp >> 2) * 64, wn = (warp & 3) * 32;
    int g = lane >> 2, tq = lane & 3;
    int ar = tid >> 1, ac = (tid & 1) * 32;

    const uint32_t* Au = (const uint32_t*)sA;
    const uint32_t* Bu = (const uint32_t*)sB;

    float acc[4][4][4];
#pragma unroll
    for (int mt=0;mt<4;mt++)
#pragma unroll
        for (int nt=0;nt<4;nt++)
#pragma unroll
            for (int c=0;c<4;c++) acc[mt][nt][c]=0.f;

    for (int k0 = 0; k0 < K; k0 += 64){
        const uint4* ap = (const uint4*)&A[(size_t)(m0+ar)*K + k0 + ac];
        uint4* asp = (uint4*)&sA[ar*72 + ac];
        asp[0]=ap[0]; asp[1]=ap[1]; asp[2]=ap[2]; asp[3]=ap[3];
        const uint4* bp = (const uint4*)&Bt[(size_t)(n0+ar)*K + k0 + ac];
        uint4* bsp = (uint4*)&sB[ar*72 + ac];
        bsp[0]=bp[0]; bsp[1]=bp[1]; bsp[2]=bp[2]; bsp[3]=bp[3];
        __syncthreads();
#pragma unroll
        for (int ks = 0; ks < 4; ks++){
            int kh = ks*8;
            uint32_t a[4][4], b[4][2];
#pragma unroll
            for (int mt = 0; mt < 4; mt++){
                int rm = wm + mt*16 + g;
                a[mt][0] = Au[rm*36 + kh + tq];
                a[mt][1] = Au[(rm+8)*36 + kh + tq];
                a[mt][2] = Au[rm*36 + kh + tq + 4];
                a[mt][3] = Au[(rm+8)*36 + kh + tq + 4];
            }
#pragma unroll
            for (int nt = 0; nt < 4; nt++){
                int n = wn + nt*8 + g;
                b[nt][0] = Bu[n*36 + kh + tq];
                b[nt][1] = Bu[n*36 + kh + tq + 4];
            }
#pragma unroll
            for (int mt = 0; mt < 4; mt++)
#pragma unroll
                for (int nt = 0; nt < 4; nt++)
                    mma_f16(acc[mt][nt], a[mt], b[nt]);
        }
        __syncthreads();
    }
#pragma unroll
    for (int mt = 0; mt < 4; mt++){
#pragma unroll
        for (int rh = 0; rh < 2; rh++){
            int m = m0 + wm + mt*16 + g + rh*8;
            int b = m >> 8, l = m & 255;
#pragma unroll
            for (int nt = 0; nt < 4; nt++){
#pragma unroll
                for (int e = 0; e < 2; e++){
                    int n = n0 + wn + nt*8 + 2*tq + e;
                    float v = acc[mt][nt][rh*2+e] + bias[n];
                    int seg = n / 768;
                    int nn = n - seg*768;
                    int dd = nn >> 5, h = nn & 31;
                    size_t idx = (((size_t)(b*32 + h))*256 + l)*24 + dd;
                    if (seg == 0)      qt[idx] = v * SCALE_Q;
                    else if (seg == 1) kt[idx] = v;
                    else               vt[idx] = v;
                }
            }
        }
    }
}

// ---------------- QK kernel ----------------
__global__ __launch_bounds__(256) void qk_kernel(
    const float* __restrict__ qt, const float* __restrict__ kt,
    float* __restrict__ qk)
{
    int bh = blockIdx.y;
    int l0 = (blockIdx.x >> 1) * 128;
    int m0 = (blockIdx.x & 1) * 128;
    __shared__ float sQ[24*132];
    __shared__ float sK[24*132];
    int tid = threadIdx.x;
    const float* qb = qt + (size_t)bh*6144 + (size_t)l0*24;
    const float* kb = kt + (size_t)bh*6144 + (size_t)m0*24;
    for (int i = tid; i < 3072; i += 256){
        int r = i / 24, d = i - r*24;
        sQ[d*132 + r] = qb[i];
        sK[d*132 + r] = kb[i];
    }
    __syncthreads();
    int tx = tid & 15, ty = tid >> 4;
    float acc[8][8];
#pragma unroll
    for (int i = 0; i < 8; i++)
#pragma unroll
        for (int j = 0; j < 8; j++) acc[i][j] = 0.f;
#pragma unroll 6
    for (int k = 0; k < 24; k++){
        float4 a0 = *(const float4*)&sQ[k*132 + ty*8];
        float4 a1 = *(const float4*)&sQ[k*132 + ty*8 + 4];
        float4 b0 = *(const float4*)&sK[k*132 + tx*8];
        float4 b1 = *(const float4*)&sK[k*132 + tx*8 + 4];
        float a[8] = {a0.x,a0.y,a0.z,a0.w,a1.x,a1.y,a1.z,a1.w};
        float b[8] = {b0.x,b0.y,b0.z,b0.w,b1.x,b1.y,b1.z,b1.w};
#pragma unroll
        for (int i = 0; i < 8; i++)
#pragma unroll
            for (int j = 0; j < 8; j++) acc[i][j] += a[i]*b[j];
    }
    float* out = qk + (size_t)bh*65536 + (size_t)l0*256 + m0;
#pragma unroll
    for (int i = 0; i < 8; i++){
        float* orow = out + (size_t)(ty*8 + i)*256 + tx*8;
        *(float4*)orow     = make_float4(acc[i][0],acc[i][1],acc[i][2],acc[i][3]);
        *(float4*)(orow+4) = make_float4(acc[i][4],acc[i][5],acc[i][6],acc[i][7]);
    }
}

// ---------------- fused edge kernel: fp16 mma.sync (unchanged from R7) ----------------
#define EK_FLOATS 45824
__global__ __launch_bounds__(512, 1) void edge_attn_kernel(
    const float* __restrict__ e_in, const float* __restrict__ mask,
    const float* __restrict__ qk,
    const float* __restrict__ W_eg, const float* __restrict__ b_eg,
    const float* __restrict__ W_oe, const float* __restrict__ b_oe,
    const float* __restrict__ eln_g, const float* __restrict__ eln_b,
    const float* __restrict__ ffn_g, const float* __restrict__ ffn_b,
    const float* __restrict__ eW1, const float* __restrict__ eb1,
    const float* __restrict__ eW2, const float* __restrict__ eb2,
    float* __restrict__ e_out, float* __restrict__ a_all)
{
    extern __shared__ float sm[];
    float* sPar  = sm;
    float* sHhat = sm + 512;
    float* sGate = sm + 8832;
    float* sMask = sm + 17152;
    __half* sW16 = (__half*)(sm + 17408);
    __half* Weg_t = sW16;           // [64][72]
    __half* W1_t  = sW16 + 4608;    // [64][72]
    __half* W2_t  = sW16 + 9216;    // [64][72]
    __half* Woe_t = sW16 + 13824;   // [64][40]

    int tid  = threadIdx.x;
    int grp  = tid >> 8;
    int t    = tid & 255;
    int lane = tid & 31;
    int g    = lane >> 2;
    int tq   = lane & 3;
    int wg8  = (tid >> 5) & 7;
    int wm   = (wg8 >> 2) * 64;
    int wn   = (wg8 & 3) * 16;
    int w    = tid >> 5;
    int row  = blockIdx.x;
    int b    = row >> 8;
    int l    = row & 255;
    int m0g  = grp * 128;

    float* grpBase = sm + 25600 + grp*10112;
    float* sQKc = grpBase;                       // [32][132]
    __half* sX16 = (__half*)(grpBase + 4224);    // [128][72]
    __half* sH16 = (__half*)(grpBase + 6528);    // [128][40]
    float*  sRed = grpBase + 9088;               // [128][4] float2

    size_t qkbase = ((size_t)b*32)*65536 + (size_t)l*256;

    for (int i = tid; i < 4096; i += 512){
        int k = i >> 6, n = i & 63;
        Weg_t[n*72 + k] = __float2half(W_eg[i]);
        W1_t [n*72 + k] = __float2half(eW1[i]);
        W2_t [n*72 + k] = __float2half(eW2[i]);
    }
    for (int i = tid; i < 2048; i += 512){
        int k = i >> 6, n = i & 63;
        Woe_t[n*40 + k] = __float2half(W_oe[i]);
    }
    if (tid < 64){
        sPar[tid]     = b_eg[tid];
        sPar[64+tid]  = b_oe[tid];
        sPar[128+tid] = eb1[tid];
        sPar[192+tid] = eb2[tid];
        sPar[256+tid] = eln_g[tid];
        sPar[320+tid] = eln_b[tid];
        sPar[384+tid] = ffn_g[tid];
        sPar[448+tid] = ffn_b[tid];
    }
    for (int i = t; i < 1024; i += 256){
        int h = i >> 5, mq = (i & 31) * 4;
        *(float4*)&sQKc[h*132 + mq] =
            *(const float4*)&qk[qkbase + (size_t)h*65536 + m0g + mq];
    }
    if (t < 128) sMask[m0g + t] = mask[(size_t)row*256 + m0g + t];
    __syncthreads();

    {
        int ty = t >> 4, tx = t & 15;
        float lg0 = sPar[256+tx*4], lg1 = sPar[257+tx*4], lg2 = sPar[258+tx*4], lg3 = sPar[259+tx*4];
        float lb0 = sPar[320+tx*4], lb1 = sPar[321+tx*4], lb2 = sPar[322+tx*4], lb3 = sPar[323+tx*4];
        __half2* xp = (__half2*)sX16;
#pragma unroll
        for (int i = 0; i < 8; i++){
            int r = ty*8 + i;
            float4 e4 = *(const float4*)&e_in[((size_t)row*256 + m0g + r)*64 + tx*4];
            float s = sum16(e4.x + e4.y + e4.z + e4.w);
            float mean = s * (1.f/64.f);
            float d0=e4.x-mean, d1=e4.y-mean, d2=e4.z-mean, d3=e4.w-mean;
            float q = sum16(d0*d0 + d1*d1 + d2*d2 + d3*d3);
            float rs = rsqrtf(q * (1.f/64.f) + 1e-5f);
            xp[r*36 + tx*2    ] = __floats2half2_rn(d0*rs*lg0 + lb0, d1*rs*lg1 + lb1);
            xp[r*36 + tx*2 + 1] = __floats2half2_rn(d2*rs*lg2 + lb2, d3*rs*lg3 + lb3);
        }
    }
    __syncthreads();

    float acc[4][2][4];
    const uint32_t* Xu  = (const uint32_t*)sX16;
    const uint32_t* Hu  = (const uint32_t*)sH16;

#pragma unroll
    for (int mt=0;mt<4;mt++)
#pragma unroll
        for (int nt=0;nt<2;nt++)
#pragma unroll
            for (int c=0;c<4;c++) acc[mt][nt][c]=0.f;
    warp_gemm_f16<4>(Xu, 36, (const uint32_t*)Weg_t, 36, wm, wn, g, tq, acc);

    if (wn < 32){
        __half2* hp = (__half2*)sH16;
#pragma unroll
        for (int mt=0;mt<4;mt++)
#pragma unroll
            for (int nt=0;nt<2;nt++){
                int nc = wn + nt*8 + 2*tq;
#pragma unroll
                for (int rh=0;rh<2;rh++){
                    int m = wm + mt*16 + g + rh*8;
                    float v0 = acc[mt][nt][rh*2+0] + sPar[nc]   + sQKc[nc*132 + m];
                    float v1 = acc[mt][nt][rh*2+1] + sPar[nc+1] + sQKc[(nc+1)*132 + m];
                    sHhat[nc*260 + m0g + m]     = v0;
                    sHhat[(nc+1)*260 + m0g + m] = v1;
                    hp[m*20 + (nc>>1)] = __floats2half2_rn(v0, v1);
                }
            }
    } else {
#pragma unroll
        for (int mt=0;mt<4;mt++)
#pragma unroll
            for (int nt=0;nt<2;nt++){
                int nc = wn + nt*8 + 2*tq;
#pragma unroll
                for (int rh=0;rh<2;rh++){
                    int m = wm + mt*16 + g + rh*8;
                    float mk = sMask[m0g + m];
                    sGate[(nc-32)*260 + m0g + m] = sigmoidf_(acc[mt][nt][rh*2+0] + sPar[nc]   + mk);
                    sGate[(nc-31)*260 + m0g + m] = sigmoidf_(acc[mt][nt][rh*2+1] + sPar[nc+1] + mk);
                }
            }
    }
    __syncthreads();

#pragma unroll
    for (int mt=0;mt<4;mt++)
#pragma unroll
        for (int nt=0;nt<2;nt++)
#pragma unroll
            for (int c=0;c<4;c++) acc[mt][nt][c]=0.f;
    warp_gemm_f16<2>(Hu, 20, (const uint32_t*)Woe_t, 20, wm, wn, g, tq, acc);

    float r_[4][2][4];
#pragma unroll
    for (int mt=0;mt<4;mt++)
#pragma unroll
        for (int nt=0;nt<2;nt++){
            int nc = wn + nt*8 + 2*tq;
            int m  = wm + mt*16 + g;
            const float* ep = &e_in[((size_t)row*256 + m0g + m)*64 + nc];
            float2 ea = *(const float2*)ep;
            float2 eb = *(const float2*)(ep + 8*64);
            r_[mt][nt][0] = ea.x + acc[mt][nt][0] + sPar[64+nc];
            r_[mt][nt][1] = ea.y + acc[mt][nt][1] + sPar[64+nc+1];
            r_[mt][nt][2] = eb.x + acc[mt][nt][2] + sPar[64+nc];
            r_[mt][nt][3] = eb.y + acc[mt][nt][3] + sPar[64+nc+1];
        }

    {
        float2* rp = (float2*)sRed;
#pragma unroll
        for (int mt=0;mt<4;mt++)
#pragma unroll
            for (int rh=0;rh<2;rh++){
                float ps = r_[mt][0][rh*2] + r_[mt][0][rh*2+1]
                         + r_[mt][1][rh*2] + r_[mt][1][rh*2+1];
                float pq = r_[mt][0][rh*2]*r_[mt][0][rh*2] + r_[mt][0][rh*2+1]*r_[mt][0][rh*2+1]
                         + r_[mt][1][rh*2]*r_[mt][1][rh*2] + r_[mt][1][rh*2+1]*r_[mt][1][rh*2+1];
                ps += __shfl_xor_sync(FULLMASK, ps, 1);
                ps += __shfl_xor_sync(FULLMASK, ps, 2);
                pq += __shfl_xor_sync(FULLMASK, pq, 1);
                pq += __shfl_xor_sync(FULLMASK, pq, 2);
                if (tq == 0){
                    int m = wm + mt*16 + g + rh*8;
                    rp[m*4 + (wg8 & 3)] = make_float2(ps, pq);
                }
            }
    }
    __syncthreads();
    {
        __half2* xp = (__half2*)sX16;
        const float2* rp = (const float2*)sRed;
#pragma unroll
        for (int mt=0;mt<4;mt++)
#pragma unroll
            for (int rh=0;rh<2;rh++){
                int m = wm + mt*16 + g + rh*8;
                float2 p0 = rp[m*4+0], p1 = rp[m*4+1], p2 = rp[m*4+2], p3 = rp[m*4+3];
                float mu = (p0.x+p1.x+p2.x+p3.x) * (1.f/64.f);
                float vq = (p0.y+p1.y+p2.y+p3.y) * (1.f/64.f) - mu*mu;
                float rs = rsqrtf(vq + 1e-5f);
#pragma unroll
                for (int nt=0;nt<2;nt++){
                    int nc = wn + nt*8 + 2*tq;
                    float v0 = (r_[mt][nt][rh*2+0]-mu)*rs*sPar[384+nc]   + sPar[448+nc];
                    float v1 = (r_[mt][nt][rh*2+1]-mu)*rs*sPar[384+nc+1] + sPar[448+nc+1];
                    xp[m*36 + (nc>>1)] = __floats2half2_rn(v0, v1);
                }
            }
    }
    __syncthreads();

#pragma unroll
    for (int mt=0;mt<4;mt++)
#pragma unroll
        for (int nt=0;nt<2;nt++)
#pragma unroll
            for (int c=0;c<4;c++) acc[mt][nt][c]=0.f;
    warp_gemm_f16<4>(Xu, 36, (const uint32_t*)W1_t, 36, wm, wn, g, tq, acc);
    __syncthreads();
    {
        __half2* xp = (__half2*)sX16;
#pragma unroll
        for (int mt=0;mt<4;mt++)
#pragma unroll
            for (int nt=0;nt<2;nt++){
                int nc = wn + nt*8 + 2*tq;
#pragma unroll
                for (int rh=0;rh<2;rh++){
                    int m = wm + mt*16 + g + rh*8;
                    float v0 = gelu_tanh(acc[mt][nt][rh*2+0] + sPar[128+nc]);
                    float v1 = gelu_tanh(acc[mt][nt][rh*2+1] + sPar[128+nc+1]);
                    xp[m*36 + (nc>>1)] = __floats2half2_rn(v0, v1);
                }
            }
    }
    __syncthreads();

#pragma unroll
    for (int mt=0;mt<4;mt++)
#pragma unroll
        for (int nt=0;nt<2;nt++)
#pragma unroll
            for (int c=0;c<4;c++) acc[mt][nt][c]=0.f;
    warp_gemm_f16<4>(Xu, 36, (const uint32_t*)W2_t, 36, wm, wn, g, tq, acc);
#pragma unroll
    for (int mt=0;mt<4;mt++)
#pragma unroll
        for (int nt=0;nt<2;nt++){
            int nc = wn + nt*8 + 2*tq;
            int m  = wm + mt*16 + g;
            float* op = &e_out[((size_t)row*256 + m0g + m)*64 + nc];
            *(float2*)op = make_float2(
                r_[mt][nt][0] + acc[mt][nt][0] + sPar[192+nc],
                r_[mt][nt][1] + acc[mt][nt][1] + sPar[192+nc+1]);
            *(float2*)(op + 8*64) = make_float2(
                r_[mt][nt][2] + acc[mt][nt][2] + sPar[192+nc],
                r_[mt][nt][3] + acc[mt][nt][3] + sPar[192+nc+1]);
        }

#pragma unroll
    for (int hi = 0; hi < 2; hi++){
        int h = w + hi*16;
        float p[8], gg[8];
        float mx = -3.4e38f;
#pragma unroll
        for (int j = 0; j < 8; j++){
            int m = j*32 + lane;
            p[j] = sHhat[h*260 + m] + sMask[m];
            mx = fmaxf(mx, p[j]);
        }
        mx = warpMax(mx);
        float s = 0.f, gs = 0.f;
#pragma unroll
        for (int j = 0; j < 8; j++){
            p[j] = __expf(p[j] - mx);
            s += p[j];
            gg[j] = sGate[h*260 + j*32 + lane];
            gs += gg[j];
        }
        s = warpSum(s); gs = warpSum(gs);
        float c = (1.f / s) * log1pf(gs);
        float* ao = a_all + (((size_t)(b*32 + h))*256 + l)*256;
#pragma unroll
        for (int j = 0; j < 8; j++)
            ao[j*32 + lane] = p[j] * gg[j] * c;
    }
}

// ---------------- AV kernel (fp16 out) ----------------
#define AV_FLOATS (64*260 + 24*260)
__global__ __launch_bounds__(256) void av_kernel(
    const float* __restrict__ a_all, const float* __restrict__ vt,
    __half* __restrict__ vatt)
{
    extern __shared__ float sm[];
    float* sA = sm;
    float* sV = sm + 64*260;
    int bh = blockIdx.y;
    int l0 = blockIdx.x * 64;
    int b = bh >> 5, h = bh & 31;
    int tid = threadIdx.x;
    const float* ab = a_all + (size_t)bh*65536 + (size_t)l0*256;
    for (int i = tid; i < 4096; i += 256){
        int ll = i >> 6, m = (i & 63) * 4;
        *(float4*)&sA[ll*260 + m] = *(const float4*)&ab[(size_t)ll*256 + m];
    }
    const float* vb = vt + (size_t)bh*6144;
    for (int i = tid; i < 6144; i += 256){
        int m = i / 24, dd = i - m*24;
        sV[dd*260 + m] = vb[i];
    }
    __syncthreads();
    int w = tid >> 5, lane = tid & 31;
    if (lane < 24){
        const float* vr = &sV[lane*260];
#pragma unroll
        for (int j = 0; j < 8; j++){
            int ll = w*8 + j;
            const float* ar = &sA[ll*260];
            float acc = 0.f;
#pragma unroll 8
            for (int m = 0; m < 256; m += 4){
                float4 a = *(const float4*)&ar[m];
                float4 v = *(const float4*)&vr[m];
                acc += a.x*v.x + a.y*v.y + a.z*v.z + a.w*v.w;
            }
            vatt[(size_t)(b*256 + l0 + ll)*768 + lane*32 + h] = __float2half(acc);
        }
    }
}

// ---------------- host ----------------
extern "C" void kernel_launch(void* const* d_in, const int* in_sizes, int n_in,
                              void* d_out, int out_size)
{
    const float* h_in   = (const float*)d_in[0];
    const float* e_in   = (const float*)d_in[1];
    const float* mask   = (const float*)d_in[2];
    const float* ln_h_g = (const float*)d_in[3];
    const float* ln_h_b = (const float*)d_in[4];
    const float* ln_e_g = (const float*)d_in[5];
    const float* ln_e_b = (const float*)d_in[6];
    const float* W_qkv  = (const float*)d_in[7];
    const float* b_qkv  = (const float*)d_in[8];
    const float* W_eg   = (const float*)d_in[9];
    const float* b_eg   = (const float*)d_in[10];
    const float* W_oh   = (const float*)d_in[11];
    const float* b_oh   = (const float*)d_in[12];
    const float* W_oe   = (const float*)d_in[13];
    const float* b_oe   = (const float*)d_in[14];
    const float* nffn_g = (const float*)d_in[15];
    const float* nffn_b = (const float*)d_in[16];
    const float* nW1    = (const float*)d_in[17];
    const float* nb1    = (const float*)d_in[18];
    const float* nW2    = (const float*)d_in[19];
    const float* nb2    = (const float*)d_in[20];
    const float* effn_g = (const float*)d_in[21];
    const float* effn_b = (const float*)d_in[22];
    const float* eW1    = (const float*)d_in[23];
    const float* eb1    = (const float*)d_in[24];
    const float* eW2    = (const float*)d_in[25];
    const float* eb2    = (const float*)d_in[26];

    float* out_h = (float*)d_out;
    float* out_e = out_h + (size_t)ROWS * DD_;

    float *qt, *kt, *vt, *qk, *aa, *hmid;
    __half *hln16, *hln216, *t16, *vatt16, *wqkv16, *woh16, *nw116, *nw216;
    cudaGetSymbolAddress((void**)&qt,     g_qt);
    cudaGetSymbolAddress((void**)&kt,     g_kt);
    cudaGetSymbolAddress((void**)&vt,     g_vt);
    cudaGetSymbolAddress((void**)&qk,     g_qk);
    cudaGetSymbolAddress((void**)&aa,     g_a);
    cudaGetSymbolAddress((void**)&hmid,   g_hmid);
    cudaGetSymbolAddress((void**)&hln16,  g_hln16);
    cudaGetSymbolAddress((void**)&hln216, g_hln216);
    cudaGetSymbolAddress((void**)&t16,    g_t16);
    cudaGetSymbolAddress((void**)&vatt16, g_vatt16);
    cudaGetSymbolAddress((void**)&wqkv16, g_wqkv16);
    cudaGetSymbolAddress((void**)&woh16,  g_woh16);
    cudaGetSymbolAddress((void**)&nw116,  g_nw116);
    cudaGetSymbolAddress((void**)&nw216,  g_nw216);

    cudaFuncSetAttribute(edge_attn_kernel,
                         cudaFuncAttributeMaxDynamicSharedMemorySize,
                         EK_FLOATS * 4);
    cudaFuncSetAttribute(av_kernel,
                         cudaFuncAttributeMaxDynamicSharedMemorySize,
                         AV_FLOATS * 4);

    // 0) weight transposes to fp16 [N][K]
    transpose_f16<<<dim3(72, 24), 256>>>(W_qkv, wqkv16, 768, 2304);
    transpose_f16<<<dim3(24, 24), 256>>>(W_oh,  woh16,  768, 768);
    transpose_f16<<<dim3(24, 24), 256>>>(nW1,   nw116,  768, 768);
    transpose_f16<<<dim3(24, 24), 256>>>(nW2,   nw216,  768, 768);

    // 1) h layernorm -> fp16
    ln768_kernel<<<ROWS, 256>>>(h_in, ln_h_g, ln_h_b, hln16);

    // 2) QKV GEMM (fp16 mma) with transposed scatter
    gemm_qkv_f16<<<dim3(18, 16), 256>>>(hln16, wqkv16, b_qkv, qt, kt, vt);

    // 3) QK = Q K^T per head
    qk_kernel<<<dim3(4, 256), 256>>>(qt, kt, qk);

    // 4) fused edge attention + edge FFN (fp16 mma) -> e_out, A'
    edge_attn_kernel<<<ROWS, 512, EK_FLOATS * 4>>>(
        e_in, mask, qk,
        W_eg, b_eg, W_oe, b_oe,
        ln_e_g, ln_e_b, effn_g, effn_b,
        eW1, eb1, eW2, eb2,
        out_e, aa);

    // 5) V_att = A' @ V -> fp16
    av_kernel<<<dim3(4, 256), 256, AV_FLOATS * 4>>>(aa, vt, vatt16);

    // 6) h_mid = h + V_att @ W_oh + b_oh (fp16 mma)
    gemm_f16k<0,0><<<dim3(6, 16), 256>>>(vatt16, woh16, b_oh, h_in,
                                         hmid, nullptr, ROWS, DD_, DD_);

    // 7) node FFN (fp16 mma)
    ln768_kernel<<<ROWS, 256>>>(hmid, nffn_g, nffn_b, hln216);
    gemm_f16k<1,1><<<dim3(6, 16), 256>>>(hln216, nw116, nb1, nullptr,
                                         nullptr, t16, ROWS, DD_, DD_);
    gemm_f16k<0,0><<<dim3(6, 16), 256>>>(t16, nw216, nb2, hmid,
                                         out_h, nullptr, ROWS, DD_, DD_);
}

// round 12
// speedup vs baseline: 2.4729x; 1.0290x over previous
#include <cuda_runtime.h>
#include <cuda_fp16.h>
#include <cstddef>
#include <cstdint>

// ---------------- problem constants ----------------
#define BB 8
#define NN 256
#define DD_ 768
#define ROWS (BB*NN)     // 2048
#define SCALE_Q 0.20412414523193154f   // 24^-0.5
#define FULLMASK 0xffffffffu

// ---------------- scratch (device globals; no allocation) ----------------
__device__ float  g_qt  [8*32*256*24];
__device__ float  g_kt  [8*32*256*24];
__device__ float  g_vt  [8*32*256*24];
__device__ float  g_qk  [8*32*256*256];    // qk, then H_hat in-place
__device__ __half g_gate16[8*32*256*256];
__device__ float  g_hmid[ROWS*DD_];
__device__ __half g_hln16 [ROWS*DD_];
__device__ __half g_hln216[ROWS*DD_];
__device__ __half g_t16   [ROWS*DD_];
__device__ __half g_vatt16[ROWS*DD_];
__device__ __half g_wqkv16[2304*768];
__device__ __half g_woh16 [768*768];
__device__ __half g_nw116 [768*768];
__device__ __half g_nw216 [768*768];

// ---------------- helpers ----------------
__device__ __forceinline__ float warpSum(float v){
#pragma unroll
    for (int o = 16; o; o >>= 1) v += __shfl_xor_sync(FULLMASK, v, o);
    return v;
}
__device__ __forceinline__ float warpMax(float v){
#pragma unroll
    for (int o = 16; o; o >>= 1) v = fmaxf(v, __shfl_xor_sync(FULLMASK, v, o));
    return v;
}
__device__ __forceinline__ float sum16(float v){
#pragma unroll
    for (int o = 8; o; o >>= 1) v += __shfl_xor_sync(FULLMASK, v, o);
    return v;
}
__device__ __forceinline__ float gelu_tanh(float x){
    float y = 0.7978845608028654f * (x + 0.044715f * x * x * x);
    y = fminf(fmaxf(y, -30.f), 30.f);
    float t = __expf(2.f * y);
    float th = (t - 1.f) / (t + 1.f);
    return 0.5f * x * (1.f + th);
}
__device__ __forceinline__ float sigmoidf_(float x){
    return 1.f / (1.f + __expf(-x));
}
__device__ __forceinline__ void mma_f16(float* c, const uint32_t* a, const uint32_t* b){
    asm volatile("mma.sync.aligned.m16n8k16.row.col.f32.f16.f16.f32 "
        "{%0,%1,%2,%3}, {%4,%5,%6,%7}, {%8,%9}, {%0,%1,%2,%3};"
        : "+f"(c[0]), "+f"(c[1]), "+f"(c[2]), "+f"(c[3])
        : "r"(a[0]), "r"(a[1]), "r"(a[2]), "r"(a[3]), "r"(b[0]), "r"(b[1]));
}

// fp16 mma over smem: A [m][k] (strideA2 half2), B [n][k] (strideB2 half2).
// Warp tile 64x16: 4 m-tiles x 2 n-tiles of m16n8k16.
template<int KS>
__device__ __forceinline__ void warp_gemm_f16(
    const uint32_t* __restrict__ Xu, int strideA2,
    const uint32_t* __restrict__ Wu, int strideB2,
    int wm, int wn, int g, int tq, float acc[4][2][4])
{
#pragma unroll
    for (int ks = 0; ks < KS; ks++){
        int kh = ks*8;
        uint32_t a[4][4], b[2][2];
#pragma unroll
        for (int mt = 0; mt < 4; mt++){
            int rm = wm + mt*16 + g;
            a[mt][0] = Xu[rm*strideA2 + kh + tq];
            a[mt][1] = Xu[(rm+8)*strideA2 + kh + tq];
            a[mt][2] = Xu[rm*strideA2 + kh + tq + 4];
            a[mt][3] = Xu[(rm+8)*strideA2 + kh + tq + 4];
        }
#pragma unroll
        for (int nt = 0; nt < 2; nt++){
            int n = wn + nt*8 + g;
            b[nt][0] = Wu[n*strideB2 + kh + tq];
            b[nt][1] = Wu[n*strideB2 + kh + tq + 4];
        }
#pragma unroll
        for (int mt = 0; mt < 4; mt++)
#pragma unroll
            for (int nt = 0; nt < 2; nt++)
                mma_f16(acc[mt][nt], a[mt], b[nt]);
    }
}

// ---------------- weight transpose fp32 [K][N] -> fp16 [N][K] ----------------
__global__ __launch_bounds__(256) void transpose_f16(
    const float* __restrict__ W, __half* __restrict__ Wt, int K, int N)
{
    __shared__ float tile[32][33];
    int k0 = blockIdx.y*32, n0 = blockIdx.x*32;
    int tx = threadIdx.x & 31, ty = threadIdx.x >> 5;
    for (int i = ty; i < 32; i += 8)
        tile[i][tx] = W[(size_t)(k0+i)*N + n0 + tx];
    __syncthreads();
    for (int i = ty; i < 32; i += 8)
        Wt[(size_t)(n0+i)*K + k0 + tx] = __float2half(tile[tx][i]);
}

// ---------------- LayerNorm over 768, fp16 out ----------------
__global__ __launch_bounds__(256) void ln768_kernel(
    const float* __restrict__ x, const float* __restrict__ g,
    const float* __restrict__ b, __half* __restrict__ y)
{
    int row = blockIdx.x;
    int tid = threadIdx.x;
    const float* xr = x + (size_t)row * DD_;
    __half*      yr = y + (size_t)row * DD_;
    float v0 = xr[tid], v1 = xr[tid+256], v2 = xr[tid+512];
    __shared__ float red[8];
    float s = warpSum(v0 + v1 + v2);
    if ((tid & 31) == 0) red[tid >> 5] = s;
    __syncthreads();
    float tot = 0.f;
#pragma unroll
    for (int i = 0; i < 8; i++) tot += red[i];
    __syncthreads();
    float mean = tot * (1.f/768.f);
    float d0 = v0-mean, d1 = v1-mean, d2 = v2-mean;
    float q = warpSum(d0*d0 + d1*d1 + d2*d2);
    if ((tid & 31) == 0) red[tid >> 5] = q;
    __syncthreads();
    float vt = 0.f;
#pragma unroll
    for (int i = 0; i < 8; i++) vt += red[i];
    float rstd = rsqrtf(vt * (1.f/768.f) + 1e-5f);
    yr[tid]     = __float2half(d0*rstd*g[tid]     + b[tid]);
    yr[tid+256] = __float2half(d1*rstd*g[tid+256] + b[tid+256]);
    yr[tid+512] = __float2half(d2*rstd*g[tid+512] + b[tid+512]);
}

// ---------------- fp16 tensor-core GEMM, CTA 128x128, warp 64x32, BK=64 ----------------
template<int EPI, int OUTH>
__global__ __launch_bounds__(256) void gemm_f16k(
    const __half* __restrict__ A, const __half* __restrict__ Bt,
    const float* __restrict__ bias, const float* __restrict__ R,
    float* __restrict__ C, __half* __restrict__ Ch, int M, int N, int K)
{
    __shared__ __half sA[128*72];
    __shared__ __half sB[128*72];
    int tid = threadIdx.x;
    int m0 = blockIdx.y * 128, n0 = blockIdx.x * 128;
    int lane = tid & 31, warp = tid >> 5;
    int wm = (warp >> 2) * 64, wn = (warp & 3) * 32;
    int g = lane >> 2, tq = lane & 3;
    int ar = tid >> 1, ac = (tid & 1) * 32;

    const uint32_t* Au = (const uint32_t*)sA;
    const uint32_t* Bu = (const uint32_t*)sB;

    float acc[4][4][4];
#pragma unroll
    for (int mt=0;mt<4;mt++)
#pragma unroll
        for (int nt=0;nt<4;nt++)
#pragma unroll
            for (int c=0;c<4;c++) acc[mt][nt][c]=0.f;

    for (int k0 = 0; k0 < K; k0 += 64){
        const uint4* ap = (const uint4*)&A[(size_t)(m0+ar)*K + k0 + ac];
        uint4* asp = (uint4*)&sA[ar*72 + ac];
        asp[0]=ap[0]; asp[1]=ap[1]; asp[2]=ap[2]; asp[3]=ap[3];
        const uint4* bp = (const uint4*)&Bt[(size_t)(n0+ar)*K + k0 + ac];
        uint4* bsp = (uint4*)&sB[ar*72 + ac];
        bsp[0]=bp[0]; bsp[1]=bp[1]; bsp[2]=bp[2]; bsp[3]=bp[3];
        __syncthreads();
#pragma unroll
        for (int ks = 0; ks < 4; ks++){
            int kh = ks*8;
            uint32_t a[4][4], b[4][2];
#pragma unroll
            for (int mt = 0; mt < 4; mt++){
                int rm = wm + mt*16 + g;
                a[mt][0] = Au[rm*36 + kh + tq];
                a[mt][1] = Au[(rm+8)*36 + kh + tq];
                a[mt][2] = Au[rm*36 + kh + tq + 4];
                a[mt][3] = Au[(rm+8)*36 + kh + tq + 4];
            }
#pragma unroll
            for (int nt = 0; nt < 4; nt++){
                int n = wn + nt*8 + g;
                b[nt][0] = Bu[n*36 + kh + tq];
                b[nt][1] = Bu[n*36 + kh + tq + 4];
            }
#pragma unroll
            for (int mt = 0; mt < 4; mt++)
#pragma unroll
                for (int nt = 0; nt < 4; nt++)
                    mma_f16(acc[mt][nt], a[mt], b[nt]);
        }
        __syncthreads();
    }
#pragma unroll
    for (int mt = 0; mt < 4; mt++){
#pragma unroll
        for (int nt = 0; nt < 4; nt++){
            int n = n0 + wn + nt*8 + 2*tq;
            float b0 = bias[n], b1 = bias[n+1];
#pragma unroll
            for (int rh = 0; rh < 2; rh++){
                int m = m0 + wm + mt*16 + g + rh*8;
                float v0 = acc[mt][nt][rh*2+0] + b0;
                float v1 = acc[mt][nt][rh*2+1] + b1;
                if (EPI == 1){ v0 = gelu_tanh(v0); v1 = gelu_tanh(v1); }
                if (OUTH){
                    *(__half2*)&Ch[(size_t)m*N + n] = __floats2half2_rn(v0, v1);
                } else {
                    if (R){
                        v0 += R[(size_t)m*N + n];
                        v1 += R[(size_t)m*N + n + 1];
                    }
                    *(float2*)&C[(size_t)m*N + n] = make_float2(v0, v1);
                }
            }
        }
    }
}

// ---------------- fp16 QKV GEMM with head-transposed scatter ----------------
__global__ __launch_bounds__(256) void gemm_qkv_f16(
    const __half* __restrict__ A, const __half* __restrict__ Bt,
    const float* __restrict__ bias,
    float* __restrict__ qt, float* __restrict__ kt, float* __restrict__ vt)
{
    const int N = 2304, K = 768;
    __shared__ __half sA[128*72];
    __shared__ __half sB[128*72];
    int tid = threadIdx.x;
    int m0 = blockIdx.y * 128, n0 = blockIdx.x * 128;
    int lane = tid & 31, warp = tid >> 5;
    int wm = (warp >> 2) * 64, wn = (warp & 3) * 32;
    int g = lane >> 2, tq = lane & 3;
    int ar = tid >> 1, ac = (tid & 1) * 32;

    const uint32_t* Au = (const uint32_t*)sA;
    const uint32_t* Bu = (const uint32_t*)sB;

    float acc[4][4][4];
#pragma unroll
    for (int mt=0;mt<4;mt++)
#pragma unroll
        for (int nt=0;nt<4;nt++)
#pragma unroll
            for (int c=0;c<4;c++) acc[mt][nt][c]=0.f;

    for (int k0 = 0; k0 < K; k0 += 64){
        const uint4* ap = (const uint4*)&A[(size_t)(m0+ar)*K + k0 + ac];
        uint4* asp = (uint4*)&sA[ar*72 + ac];
        asp[0]=ap[0]; asp[1]=ap[1]; asp[2]=ap[2]; asp[3]=ap[3];
        const uint4* bp = (const uint4*)&Bt[(size_t)(n0+ar)*K + k0 + ac];
        uint4* bsp = (uint4*)&sB[ar*72 + ac];
        bsp[0]=bp[0]; bsp[1]=bp[1]; bsp[2]=bp[2]; bsp[3]=bp[3];
        __syncthreads();
#pragma unroll
        for (int ks = 0; ks < 4; ks++){
            int kh = ks*8;
            uint32_t a[4][4], b[4][2];
#pragma unroll
            for (int mt = 0; mt < 4; mt++){
                int rm = wm + mt*16 + g;
                a[mt][0] = Au[rm*36 + kh + tq];
                a[mt][1] = Au[(rm+8)*36 + kh + tq];
                a[mt][2] = Au[rm*36 + kh + tq + 4];
                a[mt][3] = Au[(rm+8)*36 + kh + tq + 4];
            }
#pragma unroll
            for (int nt = 0; nt < 4; nt++){
                int n = wn + nt*8 + g;
                b[nt][0] = Bu[n*36 + kh + tq];
                b[nt][1] = Bu[n*36 + kh + tq + 4];
            }
#pragma unroll
            for (int mt = 0; mt < 4; mt++)
#pragma unroll
                for (int nt = 0; nt < 4; nt++)
                    mma_f16(acc[mt][nt], a[mt], b[nt]);
        }
        __syncthreads();
    }
#pragma unroll
    for (int mt = 0; mt < 4; mt++){
#pragma unroll
        for (int rh = 0; rh < 2; rh++){
            int m = m0 + wm + mt*16 + g + rh*8;
            int b = m >> 8, l = m & 255;
#pragma unroll
            for (int nt = 0; nt < 4; nt++){
#pragma unroll
                for (int e = 0; e < 2; e++){
                    int n = n0 + wn + nt*8 + 2*tq + e;
                    float v = acc[mt][nt][rh*2+e] + bias[n];
                    int seg = n / 768;
                    int nn = n - seg*768;
                    int dd = nn >> 5, h = nn & 31;
                    size_t idx = (((size_t)(b*32 + h))*256 + l)*24 + dd;
                    if (seg == 0)      qt[idx] = v * SCALE_Q;
                    else if (seg == 1) kt[idx] = v;
                    else               vt[idx] = v;
                }
            }
        }
    }
}

// ---------------- QK kernel ----------------
__global__ __launch_bounds__(256) void qk_kernel(
    const float* __restrict__ qt, const float* __restrict__ kt,
    float* __restrict__ qk)
{
    int bh = blockIdx.y;
    int l0 = (blockIdx.x >> 1) * 128;
    int m0 = (blockIdx.x & 1) * 128;
    __shared__ float sQ[24*132];
    __shared__ float sK[24*132];
    int tid = threadIdx.x;
    const float* qb = qt + (size_t)bh*6144 + (size_t)l0*24;
    const float* kb = kt + (size_t)bh*6144 + (size_t)m0*24;
    for (int i = tid; i < 3072; i += 256){
        int r = i / 24, d = i - r*24;
        sQ[d*132 + r] = qb[i];
        sK[d*132 + r] = kb[i];
    }
    __syncthreads();
    int tx = tid & 15, ty = tid >> 4;
    float acc[8][8];
#pragma unroll
    for (int i = 0; i < 8; i++)
#pragma unroll
        for (int j = 0; j < 8; j++) acc[i][j] = 0.f;
#pragma unroll 6
    for (int k = 0; k < 24; k++){
        float4 a0 = *(const float4*)&sQ[k*132 + ty*8];
        float4 a1 = *(const float4*)&sQ[k*132 + ty*8 + 4];
        float4 b0 = *(const float4*)&sK[k*132 + tx*8];
        float4 b1 = *(const float4*)&sK[k*132 + tx*8 + 4];
        float a[8] = {a0.x,a0.y,a0.z,a0.w,a1.x,a1.y,a1.z,a1.w};
        float b[8] = {b0.x,b0.y,b0.z,b0.w,b1.x,b1.y,b1.z,b1.w};
#pragma unroll
        for (int i = 0; i < 8; i++)
#pragma unroll
            for (int j = 0; j < 8; j++) acc[i][j] += a[i]*b[j];
    }
    float* out = qk + (size_t)bh*65536 + (size_t)l0*256 + m0;
#pragma unroll
    for (int i = 0; i < 8; i++){
        float* orow = out + (size_t)(ty*8 + i)*256 + tx*8;
        *(float4*)orow     = make_float4(acc[i][0],acc[i][1],acc[i][2],acc[i][3]);
        *(float4*)(orow+4) = make_float4(acc[i][4],acc[i][5],acc[i][6],acc[i][7]);
    }
}

// ---------------- fused edge kernel: per (row, half) CTA, 256 threads, 2 CTAs/SM ----------------
// smem (floats, CORRECTED sizes):
//   sPar 512 @0 ; sMask 128 @512 ;
//   weights fp16 @640: Weg_t[64][72] + W1_t[64][72] + W2_t[64][72] + Woe_t[64][40]
//     = 16384 halves = 8192 floats -> ends 8832 ;
//   sX16 [128][72] halves = 9216 h = 4608 floats @8832 -> ends 13440 ;
//   sRed [128][4] float2 = 1024 floats @13440 -> ends 14464
#define EK_FLOATS 14464
__global__ __launch_bounds__(256, 2) void edge_attn_kernel(
    const float* __restrict__ e_in, const float* __restrict__ mask,
    float* __restrict__ qk,               // in: QK ; out: H_hat (in-place)
    const float* __restrict__ W_eg, const float* __restrict__ b_eg,
    const float* __restrict__ W_oe, const float* __restrict__ b_oe,
    const float* __restrict__ eln_g, const float* __restrict__ eln_b,
    const float* __restrict__ ffn_g, const float* __restrict__ ffn_b,
    const float* __restrict__ eW1, const float* __restrict__ eb1,
    const float* __restrict__ eW2, const float* __restrict__ eb2,
    float* __restrict__ e_out, __half* __restrict__ gate16)
{
    extern __shared__ float sm[];
    float* sPar  = sm;
    float* sMask = sm + 512;
    __half* sW16 = (__half*)(sm + 640);
    __half* Weg_t = sW16;           // [64][72]
    __half* W1_t  = sW16 + 4608;    // [64][72]
    __half* W2_t  = sW16 + 9216;    // [64][72]
    __half* Woe_t = sW16 + 13824;   // [64][40]
    __half* sX16  = (__half*)(sm + 8832);   // [128][72] halves
    float*  sRed  = sm + 13440;             // [128][4] float2

    int tid  = threadIdx.x;
    int lane = tid & 31;
    int g    = lane >> 2;
    int tq   = lane & 3;
    int wg8  = tid >> 5;                 // 0..7
    int wm   = (wg8 >> 2) * 64;
    int wn   = (wg8 & 3) * 16;
    int bid  = blockIdx.x;
    int row  = bid >> 1;
    int grp  = bid & 1;
    int b    = row >> 8;
    int l    = row & 255;
    int m0g  = grp * 128;

    // ---- stage weights (fp16 transposed), params, mask ----
    for (int i = tid; i < 4096; i += 256){
        int k = i >> 6, n = i & 63;
        Weg_t[n*72 + k] = __float2half(W_eg[i]);
        W1_t [n*72 + k] = __float2half(eW1[i]);
        W2_t [n*72 + k] = __float2half(eW2[i]);
    }
    for (int i = tid; i < 2048; i += 256){
        int k = i >> 6, n = i & 63;
        Woe_t[n*40 + k] = __float2half(W_oe[i]);
    }
    if (tid < 64){
        sPar[tid]     = b_eg[tid];
        sPar[64+tid]  = b_oe[tid];
        sPar[128+tid] = eb1[tid];
        sPar[192+tid] = eb2[tid];
        sPar[256+tid] = eln_g[tid];
        sPar[320+tid] = eln_b[tid];
        sPar[384+tid] = ffn_g[tid];
        sPar[448+tid] = ffn_b[tid];
    }
    if (tid < 128) sMask[tid] = mask[(size_t)row*256 + m0g + tid];
    __syncthreads();

    // ---- LN1: thread-mapped, store fp16 X[m][k] ----
    {
        int ty = tid >> 4, tx = tid & 15;
        float lg0 = sPar[256+tx*4], lg1 = sPar[257+tx*4], lg2 = sPar[258+tx*4], lg3 = sPar[259+tx*4];
        float lb0 = sPar[320+tx*4], lb1 = sPar[321+tx*4], lb2 = sPar[322+tx*4], lb3 = sPar[323+tx*4];
        __half2* xp = (__half2*)sX16;
#pragma unroll
        for (int i = 0; i < 8; i++){
            int r = ty*8 + i;
            float4 e4 = *(const float4*)&e_in[((size_t)row*256 + m0g + r)*64 + tx*4];
            float s = sum16(e4.x + e4.y + e4.z + e4.w);
            float mean = s * (1.f/64.f);
            float d0=e4.x-mean, d1=e4.y-mean, d2=e4.z-mean, d3=e4.w-mean;
            float q = sum16(d0*d0 + d1*d1 + d2*d2 + d3*d3);
            float rs = rsqrtf(q * (1.f/64.f) + 1e-5f);
            xp[r*36 + tx*2    ] = __floats2half2_rn(d0*rs*lg0 + lb0, d1*rs*lg1 + lb1);
            xp[r*36 + tx*2 + 1] = __floats2half2_rn(d2*rs*lg2 + lb2, d3*rs*lg3 + lb3);
        }
    }
    __syncthreads();

    float acc[4][2][4];
    const uint32_t* Xu = (const uint32_t*)sX16;

    // ---- GEMM1: EG = X @ W_eg (K=64) ----
#pragma unroll
    for (int mt=0;mt<4;mt++)
#pragma unroll
        for (int nt=0;nt<2;nt++)
#pragma unroll
            for (int c=0;c<4;c++) acc[mt][nt][c]=0.f;
    warp_gemm_f16<4>(Xu, 36, (const uint32_t*)Weg_t, 36, wm, wn, g, tq, acc);
    __syncthreads();   // all X reads done before H overwrites sX16

    size_t qkbase = ((size_t)(b*32))*65536 + (size_t)l*256 + m0g;
    if (wn < 32){
        // E columns -> H_hat: in-place into qk (fp32) + fp16 m-major into sX16
        __half2* hp = (__half2*)sX16;
#pragma unroll
        for (int mt=0;mt<4;mt++)
#pragma unroll
            for (int nt=0;nt<2;nt++){
                int nc = wn + nt*8 + 2*tq;
#pragma unroll
                for (int rh=0;rh<2;rh++){
                    int m = wm + mt*16 + g + rh*8;
                    size_t qi = qkbase + (size_t)nc*65536 + m;
                    float v0 = acc[mt][nt][rh*2+0] + sPar[nc]   + qk[qi];
                    float v1 = acc[mt][nt][rh*2+1] + sPar[nc+1] + qk[qi + 65536];
                    qk[qi]         = v0;
                    qk[qi + 65536] = v1;
                    hp[m*36 + (nc>>1)] = __floats2half2_rn(v0, v1);
                }
            }
    } else {
        // G columns -> gates (fp16 to gmem)
#pragma unroll
        for (int mt=0;mt<4;mt++)
#pragma unroll
            for (int nt=0;nt<2;nt++){
                int nc = wn + nt*8 + 2*tq;
                int h0 = nc - 32;
#pragma unroll
                for (int rh=0;rh<2;rh++){
                    int m = wm + mt*16 + g + rh*8;
                    float mk = sMask[m];
                    size_t gi = qkbase + (size_t)h0*65536 + m;
                    gate16[gi]         = __float2half(sigmoidf_(acc[mt][nt][rh*2+0] + sPar[nc]   + mk));
                    gate16[gi + 65536] = __float2half(sigmoidf_(acc[mt][nt][rh*2+1] + sPar[nc+1] + mk));
                }
            }
    }
    __syncthreads();

    // ---- GEMM2: e_att = H_hat @ W_oe (K=32, A = H fp16 in sX16) ; r = e + e_att + b_oe ----
#pragma unroll
    for (int mt=0;mt<4;mt++)
#pragma unroll
        for (int nt=0;nt<2;nt++)
#pragma unroll
            for (int c=0;c<4;c++) acc[mt][nt][c]=0.f;
    warp_gemm_f16<2>(Xu, 36, (const uint32_t*)Woe_t, 20, wm, wn, g, tq, acc);

    float r_[4][2][4];
#pragma unroll
    for (int mt=0;mt<4;mt++)
#pragma unroll
        for (int nt=0;nt<2;nt++){
            int nc = wn + nt*8 + 2*tq;
            int m  = wm + mt*16 + g;
            const float* ep = &e_in[((size_t)row*256 + m0g + m)*64 + nc];
            float2 ea = *(const float2*)ep;
            float2 eb = *(const float2*)(ep + 8*64);
            r_[mt][nt][0] = ea.x + acc[mt][nt][0] + sPar[64+nc];
            r_[mt][nt][1] = ea.y + acc[mt][nt][1] + sPar[64+nc+1];
            r_[mt][nt][2] = eb.x + acc[mt][nt][2] + sPar[64+nc];
            r_[mt][nt][3] = eb.y + acc[mt][nt][3] + sPar[64+nc+1];
        }

    // ---- LN2 on r (fragments): quad-reduce + cross-warp smem reduce ----
    {
        float2* rp = (float2*)sRed;
#pragma unroll
        for (int mt=0;mt<4;mt++)
#pragma unroll
            for (int rh=0;rh<2;rh++){
                float ps = r_[mt][0][rh*2] + r_[mt][0][rh*2+1]
                         + r_[mt][1][rh*2] + r_[mt][1][rh*2+1];
                float pq = r_[mt][0][rh*2]*r_[mt][0][rh*2] + r_[mt][0][rh*2+1]*r_[mt][0][rh*2+1]
                         + r_[mt][1][rh*2]*r_[mt][1][rh*2] + r_[mt][1][rh*2+1]*r_[mt][1][rh*2+1];
                ps += __shfl_xor_sync(FULLMASK, ps, 1);
                ps += __shfl_xor_sync(FULLMASK, ps, 2);
                pq += __shfl_xor_sync(FULLMASK, pq, 1);
                pq += __shfl_xor_sync(FULLMASK, pq, 2);
                if (tq == 0){
                    int m = wm + mt*16 + g + rh*8;
                    rp[m*4 + (wg8 & 3)] = make_float2(ps, pq);
                }
            }
    }
    __syncthreads();
    {
        __half2* xp = (__half2*)sX16;
        const float2* rp = (const float2*)sRed;
#pragma unroll
        for (int mt=0;mt<4;mt++)
#pragma unroll
            for (int rh=0;rh<2;rh++){
                int m = wm + mt*16 + g + rh*8;
                float2 p0 = rp[m*4+0], p1 = rp[m*4+1], p2 = rp[m*4+2], p3 = rp[m*4+3];
                float mu = (p0.x+p1.x+p2.x+p3.x) * (1.f/64.f);
                float vq = (p0.y+p1.y+p2.y+p3.y) * (1.f/64.f) - mu*mu;
                float rs = rsqrtf(vq + 1e-5f);
#pragma unroll
                for (int nt=0;nt<2;nt++){
                    int nc = wn + nt*8 + 2*tq;
                    float v0 = (r_[mt][nt][rh*2+0]-mu)*rs*sPar[384+nc]   + sPar[448+nc];
                    float v1 = (r_[mt][nt][rh*2+1]-mu)*rs*sPar[384+nc+1] + sPar[448+nc+1];
                    xp[m*36 + (nc>>1)] = __floats2half2_rn(v0, v1);
                }
            }
    }
    __syncthreads();

    // ---- GEMM3: T = gelu(X2 @ eW1 + b1) ----
#pragma unroll
    for (int mt=0;mt<4;mt++)
#pragma unroll
        for (int nt=0;nt<2;nt++)
#pragma unroll
            for (int c=0;c<4;c++) acc[mt][nt][c]=0.f;
    warp_gemm_f16<4>(Xu, 36, (const uint32_t*)W1_t, 36, wm, wn, g, tq, acc);
    __syncthreads();
    {
        __half2* xp = (__half2*)sX16;
#pragma unroll
        for (int mt=0;mt<4;mt++)
#pragma unroll
            for (int nt=0;nt<2;nt++){
                int nc = wn + nt*8 + 2*tq;
#pragma unroll
                for (int rh=0;rh<2;rh++){
                    int m = wm + mt*16 + g + rh*8;
                    float v0 = gelu_tanh(acc[mt][nt][rh*2+0] + sPar[128+nc]);
                    float v1 = gelu_tanh(acc[mt][nt][rh*2+1] + sPar[128+nc+1]);
                    xp[m*36 + (nc>>1)] = __floats2half2_rn(v0, v1);
                }
            }
    }
    __syncthreads();

    // ---- GEMM4: O = T @ eW2 + b2 ; e_out = r + O ----
#pragma unroll
    for (int mt=0;mt<4;mt++)
#pragma unroll
        for (int nt=0;nt<2;nt++)
#pragma unroll
            for (int c=0;c<4;c++) acc[mt][nt][c]=0.f;
    warp_gemm_f16<4>(Xu, 36, (const uint32_t*)W2_t, 36, wm, wn, g, tq, acc);
#pragma unroll
    for (int mt=0;mt<4;mt++)
#pragma unroll
        for (int nt=0;nt<2;nt++){
            int nc = wn + nt*8 + 2*tq;
            int m  = wm + mt*16 + g;
            float* op = &e_out[((size_t)row*256 + m0g + m)*64 + nc];
            *(float2*)op = make_float2(
                r_[mt][nt][0] + acc[mt][nt][0] + sPar[192+nc],
                r_[mt][nt][1] + acc[mt][nt][1] + sPar[192+nc+1]);
            *(float2*)(op + 8*64) = make_float2(
                r_[mt][nt][2] + acc[mt][nt][2] + sPar[192+nc],
                r_[mt][nt][3] + acc[mt][nt][3] + sPar[192+nc+1]);
        }
}

// ---------------- softmax + AV kernel: per (bh, 32-l tile) ----------------
// smem: sL [32][260] f32 (8320) ; sV [24][260] f32 (6240) ; sG [32][264]h (4224 f)
#define AV_FLOATS (8320 + 6240 + 4224)
__global__ __launch_bounds__(256) void av_softmax_kernel(
    const float* __restrict__ logits, const __half* __restrict__ gate16,
    const float* __restrict__ mask, const float* __restrict__ vt,
    __half* __restrict__ vatt)
{
    extern __shared__ float sm[];
    float* sL = sm;                    // [32][260]
    float* sV = sm + 8320;             // [24][260]
    __half* sG = (__half*)(sm + 14560);// [32][264]
    int bh = blockIdx.y;
    int l0 = blockIdx.x * 32;
    int b = bh >> 5, h = bh & 31;
    int tid = threadIdx.x;

    const float* lb = logits + (size_t)bh*65536 + (size_t)l0*256;
    const float* mb = mask + ((size_t)b*256 + l0)*256;
    for (int i = tid; i < 2048; i += 256){
        int ll = i >> 6, m = (i & 63) * 4;
        float4 lg = *(const float4*)&lb[(size_t)ll*256 + m];
        float4 mk = *(const float4*)&mb[(size_t)ll*256 + m];
        lg.x += mk.x; lg.y += mk.y; lg.z += mk.z; lg.w += mk.w;
        *(float4*)&sL[ll*260 + m] = lg;
    }
    const __half* gb = gate16 + (size_t)bh*65536 + (size_t)l0*256;
    for (int i = tid; i < 1024; i += 256){
        int ll = i >> 5, m = (i & 31) * 8;
        *(uint4*)&sG[ll*264 + m] = *(const uint4*)&gb[(size_t)ll*256 + m];
    }
    const float* vb = vt + (size_t)bh*6144;
    for (int i = tid; i < 6144; i += 256){
        int m = i / 24, dd = i - m*24;
        sV[dd*260 + m] = vb[i];
    }
    __syncthreads();

    int w = tid >> 5, lane = tid & 31;
    // softmax + gate fold: warp w -> rows w*4..w*4+3
#pragma unroll
    for (int rr = 0; rr < 4; rr++){
        int row = w*4 + rr;
        float p[8], gg[8];
        float mx = -3.4e38f;
#pragma unroll
        for (int j = 0; j < 8; j++){
            p[j] = sL[row*260 + j*32 + lane];
            mx = fmaxf(mx, p[j]);
        }
        mx = warpMax(mx);
        float s = 0.f, gs = 0.f;
#pragma unroll
        for (int j = 0; j < 8; j++){
            p[j] = __expf(p[j] - mx);
            s += p[j];
            gg[j] = __half2float(sG[row*264 + j*32 + lane]);
            gs += gg[j];
        }
        s = warpSum(s); gs = warpSum(gs);
        float c = (1.f / s) * log1pf(gs);
#pragma unroll
        for (int j = 0; j < 8; j++)
            sL[row*260 + j*32 + lane] = p[j] * gg[j] * c;
    }
    __syncthreads();

    // AV: warp w -> rows w*4..+3, lanes < 24 = dims
    if (lane < 24){
        const float* vr = &sV[lane*260];
#pragma unroll
        for (int j = 0; j < 4; j++){
            int ll = w*4 + j;
            const float* ar = &sL[ll*260];
            float acc = 0.f;
#pragma unroll 8
            for (int m = 0; m < 256; m += 4){
                float4 a = *(const float4*)&ar[m];
                float4 v = *(const float4*)&vr[m];
                acc += a.x*v.x + a.y*v.y + a.z*v.z + a.w*v.w;
            }
            vatt[(size_t)(b*256 + l0 + ll)*768 + lane*32 + h] = __float2half(acc);
        }
    }
}

// ---------------- host ----------------
extern "C" void kernel_launch(void* const* d_in, const int* in_sizes, int n_in,
                              void* d_out, int out_size)
{
    const float* h_in   = (const float*)d_in[0];
    const float* e_in   = (const float*)d_in[1];
    const float* mask   = (const float*)d_in[2];
    const float* ln_h_g = (const float*)d_in[3];
    const float* ln_h_b = (const float*)d_in[4];
    const float* ln_e_g = (const float*)d_in[5];
    const float* ln_e_b = (const float*)d_in[6];
    const float* W_qkv  = (const float*)d_in[7];
    const float* b_qkv  = (const float*)d_in[8];
    const float* W_eg   = (const float*)d_in[9];
    const float* b_eg   = (const float*)d_in[10];
    const float* W_oh   = (const float*)d_in[11];
    const float* b_oh   = (const float*)d_in[12];
    const float* W_oe   = (const float*)d_in[13];
    const float* b_oe   = (const float*)d_in[14];
    const float* nffn_g = (const float*)d_in[15];
    const float* nffn_b = (const float*)d_in[16];
    const float* nW1    = (const float*)d_in[17];
    const float* nb1    = (const float*)d_in[18];
    const float* nW2    = (const float*)d_in[19];
    const float* nb2    = (const float*)d_in[20];
    const float* effn_g = (const float*)d_in[21];
    const float* effn_b = (const float*)d_in[22];
    const float* eW1    = (const float*)d_in[23];
    const float* eb1    = (const float*)d_in[24];
    const float* eW2    = (const float*)d_in[25];
    const float* eb2    = (const float*)d_in[26];

    float* out_h = (float*)d_out;
    float* out_e = out_h + (size_t)ROWS * DD_;

    float *qt, *kt, *vt, *qk, *hmid;
    __half *gate16, *hln16, *hln216, *t16, *vatt16, *wqkv16, *woh16, *nw116, *nw216;
    cudaGetSymbolAddress((void**)&qt,     g_qt);
    cudaGetSymbolAddress((void**)&kt,     g_kt);
    cudaGetSymbolAddress((void**)&vt,     g_vt);
    cudaGetSymbolAddress((void**)&qk,     g_qk);
    cudaGetSymbolAddress((void**)&gate16, g_gate16);
    cudaGetSymbolAddress((void**)&hmid,   g_hmid);
    cudaGetSymbolAddress((void**)&hln16,  g_hln16);
    cudaGetSymbolAddress((void**)&hln216, g_hln216);
    cudaGetSymbolAddress((void**)&t16,    g_t16);
    cudaGetSymbolAddress((void**)&vatt16, g_vatt16);
    cudaGetSymbolAddress((void**)&wqkv16, g_wqkv16);
    cudaGetSymbolAddress((void**)&woh16,  g_woh16);
    cudaGetSymbolAddress((void**)&nw116,  g_nw116);
    cudaGetSymbolAddress((void**)&nw216,  g_nw216);

    cudaFuncSetAttribute(edge_attn_kernel,
                         cudaFuncAttributeMaxDynamicSharedMemorySize,
                         EK_FLOATS * 4);
    cudaFuncSetAttribute(av_softmax_kernel,
                         cudaFuncAttributeMaxDynamicSharedMemorySize,
                         AV_FLOATS * 4);

    // 0) weight transposes to fp16 [N][K]
    transpose_f16<<<dim3(72, 24), 256>>>(W_qkv, wqkv16, 768, 2304);
    transpose_f16<<<dim3(24, 24), 256>>>(W_oh,  woh16,  768, 768);
    transpose_f16<<<dim3(24, 24), 256>>>(nW1,   nw116,  768, 768);
    transpose_f16<<<dim3(24, 24), 256>>>(nW2,   nw216,  768, 768);

    // 1) h layernorm -> fp16
    ln768_kernel<<<ROWS, 256>>>(h_in, ln_h_g, ln_h_b, hln16);

    // 2) QKV GEMM (fp16 mma) with transposed scatter
    gemm_qkv_f16<<<dim3(18, 16), 256>>>(hln16, wqkv16, b_qkv, qt, kt, vt);

    // 3) QK = Q K^T per head (into qk buffer)
    qk_kernel<<<dim3(4, 256), 256>>>(qt, kt, qk);

    // 4) edge attention + edge FFN: H_hat in-place into qk, gates -> gate16
    edge_attn_kernel<<<2*ROWS, 256, EK_FLOATS * 4>>>(
        e_in, mask, qk,
        W_eg, b_eg, W_oe, b_oe,
        ln_e_g, ln_e_b, effn_g, effn_b,
        eW1, eb1, eW2, eb2,
        out_e, gate16);

    // 5) softmax + V_att = A' @ V -> fp16
    av_softmax_kernel<<<dim3(8, 256), 256, AV_FLOATS * 4>>>(
        qk, gate16, mask, vt, vatt16);

    // 6) h_mid = h + V_att @ W_oh + b_oh (fp16 mma)
    gemm_f16k<0,0><<<dim3(6, 16), 256>>>(vatt16, woh16, b_oh, h_in,
                                         hmid, nullptr, ROWS, DD_, DD_);

    // 7) node FFN (fp16 mma)
    ln768_kernel<<<ROWS, 256>>>(hmid, nffn_g, nffn_b, hln216);
    gemm_f16k<1,1><<<dim3(6, 16), 256>>>(hln216, nw116, nb1, nullptr,
                                         nullptr, t16, ROWS, DD_, DD_);
    gemm_f16k<0,0><<<dim3(6, 16), 256>>>(t16, nw216, nb2, hmid,
                                         out_h, nullptr, ROWS, DD_, DD_);
}

// round 13
// speedup vs baseline: 2.7547x; 1.1139x over previous
#include <cuda_runtime.h>
#include <cuda_fp16.h>
#include <cstddef>
#include <cstdint>

// ---------------- problem constants ----------------
#define BB 8
#define NN 256
#define DD_ 768
#define ROWS (BB*NN)     // 2048
#define SCALE_Q 0.20412414523193154f   // 24^-0.5
#define FULLMASK 0xffffffffu

// ---------------- scratch (device globals; no allocation) ----------------
__device__ float  g_qt  [8*32*256*24];
__device__ float  g_kt  [8*32*256*24];
__device__ float  g_vt  [8*32*24*256];     // d-major: [bh][24][256]
__device__ float  g_qk  [8*32*256*256];    // qk, then H_hat in-place
__device__ __half g_gate16[8*32*256*256];
__device__ float  g_hmid[ROWS*DD_];
__device__ __half g_hln16 [ROWS*DD_];
__device__ __half g_hln216[ROWS*DD_];
__device__ __half g_t16   [ROWS*DD_];
__device__ __half g_vatt16[ROWS*DD_];
__device__ __half g_wqkv16[2304*768];
__device__ __half g_woh16 [768*768];
__device__ __half g_nw116 [768*768];
__device__ __half g_nw216 [768*768];
__device__ __half g_ew16  [16384];         // packed edge weights (smem image)

// ---------------- helpers ----------------
__device__ __forceinline__ float warpSum(float v){
#pragma unroll
    for (int o = 16; o; o >>= 1) v += __shfl_xor_sync(FULLMASK, v, o);
    return v;
}
__device__ __forceinline__ float warpMax(float v){
#pragma unroll
    for (int o = 16; o; o >>= 1) v = fmaxf(v, __shfl_xor_sync(FULLMASK, v, o));
    return v;
}
__device__ __forceinline__ float sum16(float v){
#pragma unroll
    for (int o = 8; o; o >>= 1) v += __shfl_xor_sync(FULLMASK, v, o);
    return v;
}
__device__ __forceinline__ float gelu_tanh(float x){
    float y = 0.7978845608028654f * (x + 0.044715f * x * x * x);
    y = fminf(fmaxf(y, -30.f), 30.f);
    float t = __expf(2.f * y);
    float th = (t - 1.f) / (t + 1.f);
    return 0.5f * x * (1.f + th);
}
__device__ __forceinline__ float sigmoidf_(float x){
    return 1.f / (1.f + __expf(-x));
}
__device__ __forceinline__ void mma_f16(float* c, const uint32_t* a, const uint32_t* b){
    asm volatile("mma.sync.aligned.m16n8k16.row.col.f32.f16.f16.f32 "
        "{%0,%1,%2,%3}, {%4,%5,%6,%7}, {%8,%9}, {%0,%1,%2,%3};"
        : "+f"(c[0]), "+f"(c[1]), "+f"(c[2]), "+f"(c[3])
        : "r"(a[0]), "r"(a[1]), "r"(a[2]), "r"(a[3]), "r"(b[0]), "r"(b[1]));
}

// fp16 mma over smem: A [m][k] (strideA2 half2), B [n][k] (strideB2 half2).
// Warp tile 64x16: 4 m-tiles x 2 n-tiles of m16n8k16.
template<int KS>
__device__ __forceinline__ void warp_gemm_f16(
    const uint32_t* __restrict__ Xu, int strideA2,
    const uint32_t* __restrict__ Wu, int strideB2,
    int wm, int wn, int g, int tq, float acc[4][2][4])
{
#pragma unroll
    for (int ks = 0; ks < KS; ks++){
        int kh = ks*8;
        uint32_t a[4][4], b[2][2];
#pragma unroll
        for (int mt = 0; mt < 4; mt++){
            int rm = wm + mt*16 + g;
            a[mt][0] = Xu[rm*strideA2 + kh + tq];
            a[mt][1] = Xu[(rm+8)*strideA2 + kh + tq];
            a[mt][2] = Xu[rm*strideA2 + kh + tq + 4];
            a[mt][3] = Xu[(rm+8)*strideA2 + kh + tq + 4];
        }
#pragma unroll
        for (int nt = 0; nt < 2; nt++){
            int n = wn + nt*8 + g;
            b[nt][0] = Wu[n*strideB2 + kh + tq];
            b[nt][1] = Wu[n*strideB2 + kh + tq + 4];
        }
#pragma unroll
        for (int mt = 0; mt < 4; mt++)
#pragma unroll
            for (int nt = 0; nt < 2; nt++)
                mma_f16(acc[mt][nt], a[mt], b[nt]);
    }
}

// ---------------- weight transpose fp32 [K][N] -> fp16 [N][K] ----------------
__global__ __launch_bounds__(256) void transpose_f16(
    const float* __restrict__ W, __half* __restrict__ Wt, int K, int N)
{
    __shared__ float tile[32][33];
    int k0 = blockIdx.y*32, n0 = blockIdx.x*32;
    int tx = threadIdx.x & 31, ty = threadIdx.x >> 5;
    for (int i = ty; i < 32; i += 8)
        tile[i][tx] = W[(size_t)(k0+i)*N + n0 + tx];
    __syncthreads();
    for (int i = ty; i < 32; i += 8)
        Wt[(size_t)(n0+i)*K + k0 + tx] = __float2half(tile[tx][i]);
}

// ---------------- pack edge weights fp16, smem image layout ----------------
// layout: Weg_t [64][72] @0 ; W1_t [64][72] @4608 ; W2_t [64][72] @9216 ; Woe_t [64][40] @13824
__global__ __launch_bounds__(256) void pack_edge_w(
    const float* __restrict__ W_eg, const float* __restrict__ eW1,
    const float* __restrict__ eW2, const float* __restrict__ W_oe,
    __half* __restrict__ ew)
{
    int i = blockIdx.x*256 + threadIdx.x;     // 0..4095
    if (i < 4096){
        int k = i >> 6, n = i & 63;
        ew[n*72 + k]         = __float2half(W_eg[i]);
        ew[4608 + n*72 + k]  = __float2half(eW1[i]);
        ew[9216 + n*72 + k]  = __float2half(eW2[i]);
    }
    if (i < 2048){
        int k = i >> 6, n = i & 63;
        ew[13824 + n*40 + k] = __float2half(W_oe[i]);
    }
}

// ---------------- LayerNorm over 768, fp16 out ----------------
__global__ __launch_bounds__(256) void ln768_kernel(
    const float* __restrict__ x, const float* __restrict__ g,
    const float* __restrict__ b, __half* __restrict__ y)
{
    int row = blockIdx.x;
    int tid = threadIdx.x;
    const float* xr = x + (size_t)row * DD_;
    __half*      yr = y + (size_t)row * DD_;
    float v0 = xr[tid], v1 = xr[tid+256], v2 = xr[tid+512];
    __shared__ float red[8];
    float s = warpSum(v0 + v1 + v2);
    if ((tid & 31) == 0) red[tid >> 5] = s;
    __syncthreads();
    float tot = 0.f;
#pragma unroll
    for (int i = 0; i < 8; i++) tot += red[i];
    __syncthreads();
    float mean = tot * (1.f/768.f);
    float d0 = v0-mean, d1 = v1-mean, d2 = v2-mean;
    float q = warpSum(d0*d0 + d1*d1 + d2*d2);
    if ((tid & 31) == 0) red[tid >> 5] = q;
    __syncthreads();
    float vt = 0.f;
#pragma unroll
    for (int i = 0; i < 8; i++) vt += red[i];
    float rstd = rsqrtf(vt * (1.f/768.f) + 1e-5f);
    yr[tid]     = __float2half(d0*rstd*g[tid]     + b[tid]);
    yr[tid+256] = __float2half(d1*rstd*g[tid+256] + b[tid+256]);
    yr[tid+512] = __float2half(d2*rstd*g[tid+512] + b[tid+512]);
}

// ---------------- fp16 tensor-core GEMM, CTA 128x128, warp 64x32, BK=64 ----------------
template<int EPI, int OUTH>
__global__ __launch_bounds__(256) void gemm_f16k(
    const __half* __restrict__ A, const __half* __restrict__ Bt,
    const float* __restrict__ bias, const float* __restrict__ R,
    float* __restrict__ C, __half* __restrict__ Ch, int M, int N, int K)
{
    __shared__ __half sA[128*72];
    __shared__ __half sB[128*72];
    int tid = threadIdx.x;
    int m0 = blockIdx.y * 128, n0 = blockIdx.x * 128;
    int lane = tid & 31, warp = tid >> 5;
    int wm = (warp >> 2) * 64, wn = (warp & 3) * 32;
    int g = lane >> 2, tq = lane & 3;
    int ar = tid >> 1, ac = (tid & 1) * 32;

    const uint32_t* Au = (const uint32_t*)sA;
    const uint32_t* Bu = (const uint32_t*)sB;

    float acc[4][4][4];
#pragma unroll
    for (int mt=0;mt<4;mt++)
#pragma unroll
        for (int nt=0;nt<4;nt++)
#pragma unroll
            for (int c=0;c<4;c++) acc[mt][nt][c]=0.f;

    for (int k0 = 0; k0 < K; k0 += 64){
        const uint4* ap = (const uint4*)&A[(size_t)(m0+ar)*K + k0 + ac];
        uint4* asp = (uint4*)&sA[ar*72 + ac];
        asp[0]=ap[0]; asp[1]=ap[1]; asp[2]=ap[2]; asp[3]=ap[3];
        const uint4* bp = (const uint4*)&Bt[(size_t)(n0+ar)*K + k0 + ac];
        uint4* bsp = (uint4*)&sB[ar*72 + ac];
        bsp[0]=bp[0]; bsp[1]=bp[1]; bsp[2]=bp[2]; bsp[3]=bp[3];
        __syncthreads();
#pragma unroll
        for (int ks = 0; ks < 4; ks++){
            int kh = ks*8;
            uint32_t a[4][4], b[4][2];
#pragma unroll
            for (int mt = 0; mt < 4; mt++){
                int rm = wm + mt*16 + g;
                a[mt][0] = Au[rm*36 + kh + tq];
                a[mt][1] = Au[(rm+8)*36 + kh + tq];
                a[mt][2] = Au[rm*36 + kh + tq + 4];
                a[mt][3] = Au[(rm+8)*36 + kh + tq + 4];
            }
#pragma unroll
            for (int nt = 0; nt < 4; nt++){
                int n = wn + nt*8 + g;
                b[nt][0] = Bu[n*36 + kh + tq];
                b[nt][1] = Bu[n*36 + kh + tq + 4];
            }
#pragma unroll
            for (int mt = 0; mt < 4; mt++)
#pragma unroll
                for (int nt = 0; nt < 4; nt++)
                    mma_f16(acc[mt][nt], a[mt], b[nt]);
        }
        __syncthreads();
    }
#pragma unroll
    for (int mt = 0; mt < 4; mt++){
#pragma unroll
        for (int nt = 0; nt < 4; nt++){
            int n = n0 + wn + nt*8 + 2*tq;
            float b0 = bias[n], b1 = bias[n+1];
#pragma unroll
            for (int rh = 0; rh < 2; rh++){
                int m = m0 + wm + mt*16 + g + rh*8;
                float v0 = acc[mt][nt][rh*2+0] + b0;
                float v1 = acc[mt][nt][rh*2+1] + b1;
                if (EPI == 1){ v0 = gelu_tanh(v0); v1 = gelu_tanh(v1); }
                if (OUTH){
                    *(__half2*)&Ch[(size_t)m*N + n] = __floats2half2_rn(v0, v1);
                } else {
                    if (R){
                        v0 += R[(size_t)m*N + n];
                        v1 += R[(size_t)m*N + n + 1];
                    }
                    *(float2*)&C[(size_t)m*N + n] = make_float2(v0, v1);
                }
            }
        }
    }
}

// ---------------- fp16 QKV GEMM with head-transposed scatter ----------------
// V written d-major: vt[bh][dd][l]
__global__ __launch_bounds__(256) void gemm_qkv_f16(
    const __half* __restrict__ A, const __half* __restrict__ Bt,
    const float* __restrict__ bias,
    float* __restrict__ qt, float* __restrict__ kt, float* __restrict__ vt)
{
    const int N = 2304, K = 768;
    __shared__ __half sA[128*72];
    __shared__ __half sB[128*72];
    int tid = threadIdx.x;
    int m0 = blockIdx.y * 128, n0 = blockIdx.x * 128;
    int lane = tid & 31, warp = tid >> 5;
    int wm = (warp >> 2) * 64, wn = (warp & 3) * 32;
    int g = lane >> 2, tq = lane & 3;
    int ar = tid >> 1, ac = (tid & 1) * 32;

    const uint32_t* Au = (const uint32_t*)sA;
    const uint32_t* Bu = (const uint32_t*)sB;

    float acc[4][4][4];
#pragma unroll
    for (int mt=0;mt<4;mt++)
#pragma unroll
        for (int nt=0;nt<4;nt++)
#pragma unroll
            for (int c=0;c<4;c++) acc[mt][nt][c]=0.f;

    for (int k0 = 0; k0 < K; k0 += 64){
        const uint4* ap = (const uint4*)&A[(size_t)(m0+ar)*K + k0 + ac];
        uint4* asp = (uint4*)&sA[ar*72 + ac];
        asp[0]=ap[0]; asp[1]=ap[1]; asp[2]=ap[2]; asp[3]=ap[3];
        const uint4* bp = (const uint4*)&Bt[(size_t)(n0+ar)*K + k0 + ac];
        uint4* bsp = (uint4*)&sB[ar*72 + ac];
        bsp[0]=bp[0]; bsp[1]=bp[1]; bsp[2]=bp[2]; bsp[3]=bp[3];
        __syncthreads();
#pragma unroll
        for (int ks = 0; ks < 4; ks++){
            int kh = ks*8;
            uint32_t a[4][4], b[4][2];
#pragma unroll
            for (int mt = 0; mt < 4; mt++){
                int rm = wm + mt*16 + g;
                a[mt][0] = Au[rm*36 + kh + tq];
                a[mt][1] = Au[(rm+8)*36 + kh + tq];
                a[mt][2] = Au[rm*36 + kh + tq + 4];
                a[mt][3] = Au[(rm+8)*36 + kh + tq + 4];
            }
#pragma unroll
            for (int nt = 0; nt < 4; nt++){
                int n = wn + nt*8 + g;
                b[nt][0] = Bu[n*36 + kh + tq];
                b[nt][1] = Bu[n*36 + kh + tq + 4];
            }
#pragma unroll
            for (int mt = 0; mt < 4; mt++)
#pragma unroll
                for (int nt = 0; nt < 4; nt++)
                    mma_f16(acc[mt][nt], a[mt], b[nt]);
        }
        __syncthreads();
    }
#pragma unroll
    for (int mt = 0; mt < 4; mt++){
#pragma unroll
        for (int rh = 0; rh < 2; rh++){
            int m = m0 + wm + mt*16 + g + rh*8;
            int b = m >> 8, l = m & 255;
#pragma unroll
            for (int nt = 0; nt < 4; nt++){
#pragma unroll
                for (int e = 0; e < 2; e++){
                    int n = n0 + wn + nt*8 + 2*tq + e;
                    float v = acc[mt][nt][rh*2+e] + bias[n];
                    int seg = n / 768;
                    int nn = n - seg*768;
                    int dd = nn >> 5, h = nn & 31;
                    if (seg == 0){
                        qt[(((size_t)(b*32 + h))*256 + l)*24 + dd] = v * SCALE_Q;
                    } else if (seg == 1){
                        kt[(((size_t)(b*32 + h))*256 + l)*24 + dd] = v;
                    } else {
                        vt[(((size_t)(b*32 + h))*24 + dd)*256 + l] = v;
                    }
                }
            }
        }
    }
}

// ---------------- QK kernel ----------------
__global__ __launch_bounds__(256) void qk_kernel(
    const float* __restrict__ qt, const float* __restrict__ kt,
    float* __restrict__ qk)
{
    int bh = blockIdx.y;
    int l0 = (blockIdx.x >> 1) * 128;
    int m0 = (blockIdx.x & 1) * 128;
    __shared__ float sQ[24*132];
    __shared__ float sK[24*132];
    int tid = threadIdx.x;
    const float* qb = qt + (size_t)bh*6144 + (size_t)l0*24;
    const float* kb = kt + (size_t)bh*6144 + (size_t)m0*24;
    for (int i = tid; i < 3072; i += 256){
        int r = i / 24, d = i - r*24;
        sQ[d*132 + r] = qb[i];
        sK[d*132 + r] = kb[i];
    }
    __syncthreads();
    int tx = tid & 15, ty = tid >> 4;
    float acc[8][8];
#pragma unroll
    for (int i = 0; i < 8; i++)
#pragma unroll
        for (int j = 0; j < 8; j++) acc[i][j] = 0.f;
#pragma unroll 6
    for (int k = 0; k < 24; k++){
        float4 a0 = *(const float4*)&sQ[k*132 + ty*8];
        float4 a1 = *(const float4*)&sQ[k*132 + ty*8 + 4];
        float4 b0 = *(const float4*)&sK[k*132 + tx*8];
        float4 b1 = *(const float4*)&sK[k*132 + tx*8 + 4];
        float a[8] = {a0.x,a0.y,a0.z,a0.w,a1.x,a1.y,a1.z,a1.w};
        float b[8] = {b0.x,b0.y,b0.z,b0.w,b1.x,b1.y,b1.z,b1.w};
#pragma unroll
        for (int i = 0; i < 8; i++)
#pragma unroll
            for (int j = 0; j < 8; j++) acc[i][j] += a[i]*b[j];
    }
    float* out = qk + (size_t)bh*65536 + (size_t)l0*256 + m0;
#pragma unroll
    for (int i = 0; i < 8; i++){
        float* orow = out + (size_t)(ty*8 + i)*256 + tx*8;
        *(float4*)orow     = make_float4(acc[i][0],acc[i][1],acc[i][2],acc[i][3]);
        *(float4*)(orow+4) = make_float4(acc[i][4],acc[i][5],acc[i][6],acc[i][7]);
    }
}

// ---------------- fused edge kernel: per (row, half) CTA, 256 threads, 2 CTAs/SM ----------------
// smem (floats):
//   sPar 512 @0 ; sMask 128 @512 ;
//   weights fp16 @640: packed image (16384 halves = 8192 f) -> ends 8832 ;
//   sX16 [128][72] halves = 4608 floats @8832 -> ends 13440 ;
//   sRed [128][4] float2 = 1024 floats @13440 -> ends 14464
#define EK_FLOATS 14464
__global__ __launch_bounds__(256, 2) void edge_attn_kernel(
    const float* __restrict__ e_in, const float* __restrict__ mask,
    float* __restrict__ qk,               // in: QK ; out: H_hat (in-place)
    const __half* __restrict__ ew16,
    const float* __restrict__ b_eg, const float* __restrict__ b_oe,
    const float* __restrict__ eln_g, const float* __restrict__ eln_b,
    const float* __restrict__ ffn_g, const float* __restrict__ ffn_b,
    const float* __restrict__ eb1, const float* __restrict__ eb2,
    float* __restrict__ e_out, __half* __restrict__ gate16)
{
    extern __shared__ float sm[];
    float* sPar  = sm;
    float* sMask = sm + 512;
    __half* sW16 = (__half*)(sm + 640);
    __half* Weg_t = sW16;           // [64][72]
    __half* W1_t  = sW16 + 4608;    // [64][72]
    __half* W2_t  = sW16 + 9216;    // [64][72]
    __half* Woe_t = sW16 + 13824;   // [64][40]
    __half* sX16  = (__half*)(sm + 8832);   // [128][72] halves
    float*  sRed  = sm + 13440;             // [128][4] float2

    int tid  = threadIdx.x;
    int lane = tid & 31;
    int g    = lane >> 2;
    int tq   = lane & 3;
    int wg8  = tid >> 5;                 // 0..7
    int wm   = (wg8 >> 2) * 64;
    int wn   = (wg8 & 3) * 16;
    int bid  = blockIdx.x;
    int row  = bid >> 1;
    int grp  = bid & 1;
    int b    = row >> 8;
    int l    = row & 255;
    int m0g  = grp * 128;

    // ---- stage packed weights (uint4 copy), params, mask ----
    {
        const uint4* src = (const uint4*)ew16;
        uint4* dst = (uint4*)sW16;
#pragma unroll
        for (int i = 0; i < 8; i++)
            dst[tid + i*256] = src[tid + i*256];
    }
    if (tid < 64){
        sPar[tid]     = b_eg[tid];
        sPar[64+tid]  = b_oe[tid];
        sPar[128+tid] = eb1[tid];
        sPar[192+tid] = eb2[tid];
        sPar[256+tid] = eln_g[tid];
        sPar[320+tid] = eln_b[tid];
        sPar[384+tid] = ffn_g[tid];
        sPar[448+tid] = ffn_b[tid];
    }
    if (tid < 128) sMask[tid] = mask[(size_t)row*256 + m0g + tid];
    __syncthreads();

    // ---- LN1: thread-mapped, store fp16 X[m][k] ----
    {
        int ty = tid >> 4, tx = tid & 15;
        float lg0 = sPar[256+tx*4], lg1 = sPar[257+tx*4], lg2 = sPar[258+tx*4], lg3 = sPar[259+tx*4];
        float lb0 = sPar[320+tx*4], lb1 = sPar[321+tx*4], lb2 = sPar[322+tx*4], lb3 = sPar[323+tx*4];
        __half2* xp = (__half2*)sX16;
#pragma unroll
        for (int i = 0; i < 8; i++){
            int r = ty*8 + i;
            float4 e4 = *(const float4*)&e_in[((size_t)row*256 + m0g + r)*64 + tx*4];
            float s = sum16(e4.x + e4.y + e4.z + e4.w);
            float mean = s * (1.f/64.f);
            float d0=e4.x-mean, d1=e4.y-mean, d2=e4.z-mean, d3=e4.w-mean;
            float q = sum16(d0*d0 + d1*d1 + d2*d2 + d3*d3);
            float rs = rsqrtf(q * (1.f/64.f) + 1e-5f);
            xp[r*36 + tx*2    ] = __floats2half2_rn(d0*rs*lg0 + lb0, d1*rs*lg1 + lb1);
            xp[r*36 + tx*2 + 1] = __floats2half2_rn(d2*rs*lg2 + lb2, d3*rs*lg3 + lb3);
        }
    }
    __syncthreads();

    float acc[4][2][4];
    const uint32_t* Xu = (const uint32_t*)sX16;

    // ---- GEMM1: EG = X @ W_eg (K=64) ----
#pragma unroll
    for (int mt=0;mt<4;mt++)
#pragma unroll
        for (int nt=0;nt<2;nt++)
#pragma unroll
            for (int c=0;c<4;c++) acc[mt][nt][c]=0.f;
    warp_gemm_f16<4>(Xu, 36, (const uint32_t*)Weg_t, 36, wm, wn, g, tq, acc);
    __syncthreads();   // all X reads done before H overwrites sX16

    size_t qkbase = ((size_t)(b*32))*65536 + (size_t)l*256 + m0g;
    if (wn < 32){
        // E columns -> H_hat: in-place into qk (fp32) + fp16 m-major into sX16
        __half2* hp = (__half2*)sX16;
#pragma unroll
        for (int mt=0;mt<4;mt++)
#pragma unroll
            for (int nt=0;nt<2;nt++){
                int nc = wn + nt*8 + 2*tq;
#pragma unroll
                for (int rh=0;rh<2;rh++){
                    int m = wm + mt*16 + g + rh*8;
                    size_t qi = qkbase + (size_t)nc*65536 + m;
                    float v0 = acc[mt][nt][rh*2+0] + sPar[nc]   + qk[qi];
                    float v1 = acc[mt][nt][rh*2+1] + sPar[nc+1] + qk[qi + 65536];
                    qk[qi]         = v0;
                    qk[qi + 65536] = v1;
                    hp[m*36 + (nc>>1)] = __floats2half2_rn(v0, v1);
                }
            }
    } else {
        // G columns -> gates (fp16 to gmem)
#pragma unroll
        for (int mt=0;mt<4;mt++)
#pragma unroll
            for (int nt=0;nt<2;nt++){
                int nc = wn + nt*8 + 2*tq;
                int h0 = nc - 32;
#pragma unroll
                for (int rh=0;rh<2;rh++){
                    int m = wm + mt*16 + g + rh*8;
                    float mk = sMask[m];
                    size_t gi = qkbase + (size_t)h0*65536 + m;
                    gate16[gi]         = __float2half(sigmoidf_(acc[mt][nt][rh*2+0] + sPar[nc]   + mk));
                    gate16[gi + 65536] = __float2half(sigmoidf_(acc[mt][nt][rh*2+1] + sPar[nc+1] + mk));
                }
            }
    }
    __syncthreads();

    // ---- GEMM2: e_att = H_hat @ W_oe (K=32, A = H fp16 in sX16) ; r = e + e_att + b_oe ----
#pragma unroll
    for (int mt=0;mt<4;mt++)
#pragma unroll
        for (int nt=0;nt<2;nt++)
#pragma unroll
            for (int c=0;c<4;c++) acc[mt][nt][c]=0.f;
    warp_gemm_f16<2>(Xu, 36, (const uint32_t*)Woe_t, 20, wm, wn, g, tq, acc);

    float r_[4][2][4];
#pragma unroll
    for (int mt=0;mt<4;mt++)
#pragma unroll
        for (int nt=0;nt<2;nt++){
            int nc = wn + nt*8 + 2*tq;
            int m  = wm + mt*16 + g;
            const float* ep = &e_in[((size_t)row*256 + m0g + m)*64 + nc];
            float2 ea = *(const float2*)ep;
            float2 eb = *(const float2*)(ep + 8*64);
            r_[mt][nt][0] = ea.x + acc[mt][nt][0] + sPar[64+nc];
            r_[mt][nt][1] = ea.y + acc[mt][nt][1] + sPar[64+nc+1];
            r_[mt][nt][2] = eb.x + acc[mt][nt][2] + sPar[64+nc];
            r_[mt][nt][3] = eb.y + acc[mt][nt][3] + sPar[64+nc+1];
        }

    // ---- LN2 on r (fragments): quad-reduce + cross-warp smem reduce ----
    {
        float2* rp = (float2*)sRed;
#pragma unroll
        for (int mt=0;mt<4;mt++)
#pragma unroll
            for (int rh=0;rh<2;rh++){
                float ps = r_[mt][0][rh*2] + r_[mt][0][rh*2+1]
                         + r_[mt][1][rh*2] + r_[mt][1][rh*2+1];
                float pq = r_[mt][0][rh*2]*r_[mt][0][rh*2] + r_[mt][0][rh*2+1]*r_[mt][0][rh*2+1]
                         + r_[mt][1][rh*2]*r_[mt][1][rh*2] + r_[mt][1][rh*2+1]*r_[mt][1][rh*2+1];
                ps += __shfl_xor_sync(FULLMASK, ps, 1);
                ps += __shfl_xor_sync(FULLMASK, ps, 2);
                pq += __shfl_xor_sync(FULLMASK, pq, 1);
                pq += __shfl_xor_sync(FULLMASK, pq, 2);
                if (tq == 0){
                    int m = wm + mt*16 + g + rh*8;
                    rp[m*4 + (wg8 & 3)] = make_float2(ps, pq);
                }
            }
    }
    __syncthreads();
    {
        __half2* xp = (__half2*)sX16;
        const float2* rp = (const float2*)sRed;
#pragma unroll
        for (int mt=0;mt<4;mt++)
#pragma unroll
            for (int rh=0;rh<2;rh++){
                int m = wm + mt*16 + g + rh*8;
                float2 p0 = rp[m*4+0], p1 = rp[m*4+1], p2 = rp[m*4+2], p3 = rp[m*4+3];
                float mu = (p0.x+p1.x+p2.x+p3.x) * (1.f/64.f);
                float vq = (p0.y+p1.y+p2.y+p3.y) * (1.f/64.f) - mu*mu;
                float rs = rsqrtf(vq + 1e-5f);
#pragma unroll
                for (int nt=0;nt<2;nt++){
                    int nc = wn + nt*8 + 2*tq;
                    float v0 = (r_[mt][nt][rh*2+0]-mu)*rs*sPar[384+nc]   + sPar[448+nc];
                    float v1 = (r_[mt][nt][rh*2+1]-mu)*rs*sPar[384+nc+1] + sPar[448+nc+1];
                    xp[m*36 + (nc>>1)] = __floats2half2_rn(v0, v1);
                }
            }
    }
    __syncthreads();

    // ---- GEMM3: T = gelu(X2 @ eW1 + b1) ----
#pragma unroll
    for (int mt=0;mt<4;mt++)
#pragma unroll
        for (int nt=0;nt<2;nt++)
#pragma unroll
            for (int c=0;c<4;c++) acc[mt][nt][c]=0.f;
    warp_gemm_f16<4>(Xu, 36, (const uint32_t*)W1_t, 36, wm, wn, g, tq, acc);
    __syncthreads();
    {
        __half2* xp = (__half2*)sX16;
#pragma unroll
        for (int mt=0;mt<4;mt++)
#pragma unroll
            for (int nt=0;nt<2;nt++){
                int nc = wn + nt*8 + 2*tq;
#pragma unroll
                for (int rh=0;rh<2;rh++){
                    int m = wm + mt*16 + g + rh*8;
                    float v0 = gelu_tanh(acc[mt][nt][rh*2+0] + sPar[128+nc]);
                    float v1 = gelu_tanh(acc[mt][nt][rh*2+1] + sPar[128+nc+1]);
                    xp[m*36 + (nc>>1)] = __floats2half2_rn(v0, v1);
                }
            }
    }
    __syncthreads();

    // ---- GEMM4: O = T @ eW2 + b2 ; e_out = r + O ----
#pragma unroll
    for (int mt=0;mt<4;mt++)
#pragma unroll
        for (int nt=0;nt<2;nt++)
#pragma unroll
            for (int c=0;c<4;c++) acc[mt][nt][c]=0.f;
    warp_gemm_f16<4>(Xu, 36, (const uint32_t*)W2_t, 36, wm, wn, g, tq, acc);
#pragma unroll
    for (int mt=0;mt<4;mt++)
#pragma unroll
        for (int nt=0;nt<2;nt++){
            int nc = wn + nt*8 + 2*tq;
            int m  = wm + mt*16 + g;
            float* op = &e_out[((size_t)row*256 + m0g + m)*64 + nc];
            *(float2*)op = make_float2(
                r_[mt][nt][0] + acc[mt][nt][0] + sPar[192+nc],
                r_[mt][nt][1] + acc[mt][nt][1] + sPar[192+nc+1]);
            *(float2*)(op + 8*64) = make_float2(
                r_[mt][nt][2] + acc[mt][nt][2] + sPar[192+nc],
                r_[mt][nt][3] + acc[mt][nt][3] + sPar[192+nc+1]);
        }
}

// ---------------- softmax + AV kernel: per (bh, 32-l tile) ----------------
// smem: sL [32][260] f32 (8320) ; sV [24][260] f32 (6240) ; sG [32][264]h (4224 f)
#define AV_FLOATS (8320 + 6240 + 4224)
__global__ __launch_bounds__(256) void av_softmax_kernel(
    const float* __restrict__ logits, const __half* __restrict__ gate16,
    const float* __restrict__ mask, const float* __restrict__ vt,
    __half* __restrict__ vatt)
{
    extern __shared__ float sm[];
    float* sL = sm;                    // [32][260]
    float* sV = sm + 8320;             // [24][260]
    __half* sG = (__half*)(sm + 14560);// [32][264]
    int bh = blockIdx.y;
    int l0 = blockIdx.x * 32;
    int b = bh >> 5, h = bh & 31;
    int tid = threadIdx.x;

    const float* lb = logits + (size_t)bh*65536 + (size_t)l0*256;
    const float* mb = mask + ((size_t)b*256 + l0)*256;
    for (int i = tid; i < 2048; i += 256){
        int ll = i >> 6, m = (i & 63) * 4;
        float4 lg = *(const float4*)&lb[(size_t)ll*256 + m];
        float4 mk = *(const float4*)&mb[(size_t)ll*256 + m];
        lg.x += mk.x; lg.y += mk.y; lg.z += mk.z; lg.w += mk.w;
        *(float4*)&sL[ll*260 + m] = lg;
    }
    const __half* gb = gate16 + (size_t)bh*65536 + (size_t)l0*256;
    for (int i = tid; i < 1024; i += 256){
        int ll = i >> 5, m = (i & 31) * 8;
        *(uint4*)&sG[ll*264 + m] = *(const uint4*)&gb[(size_t)ll*256 + m];
    }
    // V d-major: coalesced float4 copy into [24][260]
    const float* vb = vt + (size_t)bh*6144;
    for (int i = tid; i < 1536; i += 256){
        int dd = i >> 6, m = (i & 63) * 4;
        *(float4*)&sV[dd*260 + m] = *(const float4*)&vb[dd*256 + m];
    }
    __syncthreads();

    int w = tid >> 5, lane = tid & 31;
    // softmax + gate fold: warp w -> rows w*4..w*4+3
#pragma unroll
    for (int rr = 0; rr < 4; rr++){
        int row = w*4 + rr;
        float p[8], gg[8];
        float mx = -3.4e38f;
#pragma unroll
        for (int j = 0; j < 8; j++){
            p[j] = sL[row*260 + j*32 + lane];
            mx = fmaxf(mx, p[j]);
        }
        mx = warpMax(mx);
        float s = 0.f, gs = 0.f;
#pragma unroll
        for (int j = 0; j < 8; j++){
            p[j] = __expf(p[j] - mx);
            s += p[j];
            gg[j] = __half2float(sG[row*264 + j*32 + lane]);
            gs += gg[j];
        }
        s = warpSum(s); gs = warpSum(gs);
        float c = (1.f / s) * log1pf(gs);
#pragma unroll
        for (int j = 0; j < 8; j++)
            sL[row*260 + j*32 + lane] = p[j] * gg[j] * c;
    }
    __syncthreads();

    // AV: warp w -> rows w*4..+3, lanes < 24 = dims
    if (lane < 24){
        const float* vr = &sV[lane*260];
#pragma unroll
        for (int j = 0; j < 4; j++){
            int ll = w*4 + j;
            const float* ar = &sL[ll*260];
            float acc = 0.f;
#pragma unroll 8
            for (int m = 0; m < 256; m += 4){
                float4 a = *(const float4*)&ar[m];
                float4 v = *(const float4*)&vr[m];
                acc += a.x*v.x + a.y*v.y + a.z*v.z + a.w*v.w;
            }
            vatt[(size_t)(b*256 + l0 + ll)*768 + lane*32 + h] = __float2half(acc);
        }
    }
}

// ---------------- host ----------------
extern "C" void kernel_launch(void* const* d_in, const int* in_sizes, int n_in,
                              void* d_out, int out_size)
{
    const float* h_in   = (const float*)d_in[0];
    const float* e_in   = (const float*)d_in[1];
    const float* mask   = (const float*)d_in[2];
    const float* ln_h_g = (const float*)d_in[3];
    const float* ln_h_b = (const float*)d_in[4];
    const float* ln_e_g = (const float*)d_in[5];
    const float* ln_e_b = (const float*)d_in[6];
    const float* W_qkv  = (const float*)d_in[7];
    const float* b_qkv  = (const float*)d_in[8];
    const float* W_eg   = (const float*)d_in[9];
    const float* b_eg   = (const float*)d_in[10];
    const float* W_oh   = (const float*)d_in[11];
    const float* b_oh   = (const float*)d_in[12];
    const float* W_oe   = (const float*)d_in[13];
    const float* b_oe   = (const float*)d_in[14];
    const float* nffn_g = (const float*)d_in[15];
    const float* nffn_b = (const float*)d_in[16];
    const float* nW1    = (const float*)d_in[17];
    const float* nb1    = (const float*)d_in[18];
    const float* nW2    = (const float*)d_in[19];
    const float* nb2    = (const float*)d_in[20];
    const float* effn_g = (const float*)d_in[21];
    const float* effn_b = (const float*)d_in[22];
    const float* eW1    = (const float*)d_in[23];
    const float* eb1    = (const float*)d_in[24];
    const float* eW2    = (const float*)d_in[25];
    const float* eb2    = (const float*)d_in[26];

    float* out_h = (float*)d_out;
    float* out_e = out_h + (size_t)ROWS * DD_;

    float *qt, *kt, *vt, *qk, *hmid;
    __half *gate16, *hln16, *hln216, *t16, *vatt16, *wqkv16, *woh16, *nw116, *nw216, *ew16;
    cudaGetSymbolAddress((void**)&qt,     g_qt);
    cudaGetSymbolAddress((void**)&kt,     g_kt);
    cudaGetSymbolAddress((void**)&vt,     g_vt);
    cudaGetSymbolAddress((void**)&qk,     g_qk);
    cudaGetSymbolAddress((void**)&gate16, g_gate16);
    cudaGetSymbolAddress((void**)&hmid,   g_hmid);
    cudaGetSymbolAddress((void**)&hln16,  g_hln16);
    cudaGetSymbolAddress((void**)&hln216, g_hln216);
    cudaGetSymbolAddress((void**)&t16,    g_t16);
    cudaGetSymbolAddress((void**)&vatt16, g_vatt16);
    cudaGetSymbolAddress((void**)&wqkv16, g_wqkv16);
    cudaGetSymbolAddress((void**)&woh16,  g_woh16);
    cudaGetSymbolAddress((void**)&nw116,  g_nw116);
    cudaGetSymbolAddress((void**)&nw216,  g_nw216);
    cudaGetSymbolAddress((void**)&ew16,   g_ew16);

    cudaFuncSetAttribute(edge_attn_kernel,
                         cudaFuncAttributeMaxDynamicSharedMemorySize,
                         EK_FLOATS * 4);
    cudaFuncSetAttribute(av_softmax_kernel,
                         cudaFuncAttributeMaxDynamicSharedMemorySize,
                         AV_FLOATS * 4);

    // 0) weight transposes / packing
    transpose_f16<<<dim3(72, 24), 256>>>(W_qkv, wqkv16, 768, 2304);
    transpose_f16<<<dim3(24, 24), 256>>>(W_oh,  woh16,  768, 768);
    transpose_f16<<<dim3(24, 24), 256>>>(nW1,   nw116,  768, 768);
    transpose_f16<<<dim3(24, 24), 256>>>(nW2,   nw216,  768, 768);
    pack_edge_w<<<16, 256>>>(W_eg, eW1, eW2, W_oe, ew16);

    // 1) h layernorm -> fp16
    ln768_kernel<<<ROWS, 256>>>(h_in, ln_h_g, ln_h_b, hln16);

    // 2) QKV GEMM (fp16 mma) with transposed scatter (V d-major)
    gemm_qkv_f16<<<dim3(18, 16), 256>>>(hln16, wqkv16, b_qkv, qt, kt, vt);

    // 3) QK = Q K^T per head (into qk buffer)
    qk_kernel<<<dim3(4, 256), 256>>>(qt, kt, qk);

    // 4) edge attention + edge FFN: H_hat in-place into qk, gates -> gate16
    edge_attn_kernel<<<2*ROWS, 256, EK_FLOATS * 4>>>(
        e_in, mask, qk, ew16,
        b_eg, b_oe,
        ln_e_g, ln_e_b, effn_g, effn_b,
        eb1, eb2,
        out_e, gate16);

    // 5) softmax + V_att = A' @ V -> fp16
    av_softmax_kernel<<<dim3(8, 256), 256, AV_FLOATS * 4>>>(
        qk, gate16, mask, vt, vatt16);

    // 6) h_mid = h + V_att @ W_oh + b_oh (fp16 mma)
    gemm_f16k<0,0><<<dim3(6, 16), 256>>>(vatt16, woh16, b_oh, h_in,
                                         hmid, nullptr, ROWS, DD_, DD_);

    // 7) node FFN (fp16 mma)
    ln768_kernel<<<ROWS, 256>>>(hmid, nffn_g, nffn_b, hln216);
    gemm_f16k<1,1><<<dim3(6, 16), 256>>>(hln216, nw116, nb1, nullptr,
                                         nullptr, t16, ROWS, DD_, DD_);
    gemm_f16k<0,0><<<dim3(6, 16), 256>>>(t16, nw216, nb2, hmid,
                                         out_h, nullptr, ROWS, DD_, DD_);
}

// round 14
// speedup vs baseline: 2.8068x; 1.0189x over previous
#include <cuda_runtime.h>
#include <cuda_fp16.h>
#include <cstddef>
#include <cstdint>

// ---------------- problem constants ----------------
#define BB 8
#define NN 256
#define DD_ 768
#define ROWS (BB*NN)     // 2048
#define SCALE_Q 0.20412414523193154f   // 24^-0.5
#define FULLMASK 0xffffffffu

// ---------------- scratch (device globals; no allocation) ----------------
__device__ float  g_qt  [8*32*256*24];
__device__ float  g_kt  [8*32*256*24];
__device__ float  g_vt  [8*32*24*256];     // d-major: [bh][24][256]
__device__ float  g_qk  [8*32*256*256];    // qk, then H_hat+mask in-place
__device__ __half g_gate16[8*32*256*256];
__device__ float  g_hmid[ROWS*DD_];
__device__ __half g_hln16 [ROWS*DD_];
__device__ __half g_hln216[ROWS*DD_];
__device__ __half g_t16   [ROWS*DD_];
__device__ __half g_vatt16[ROWS*DD_];
__device__ __half g_wqkv16[2304*768];
__device__ __half g_woh16 [768*768];
__device__ __half g_nw116 [768*768];
__device__ __half g_nw216 [768*768];
__device__ __half g_ew16  [16384];         // packed edge weights (smem image)

// ---------------- helpers ----------------
__device__ __forceinline__ float warpSum(float v){
#pragma unroll
    for (int o = 16; o; o >>= 1) v += __shfl_xor_sync(FULLMASK, v, o);
    return v;
}
__device__ __forceinline__ float warpMax(float v){
#pragma unroll
    for (int o = 16; o; o >>= 1) v = fmaxf(v, __shfl_xor_sync(FULLMASK, v, o));
    return v;
}
__device__ __forceinline__ float sum16(float v){
#pragma unroll
    for (int o = 8; o; o >>= 1) v += __shfl_xor_sync(FULLMASK, v, o);
    return v;
}
__device__ __forceinline__ float gelu_tanh(float x){
    float y = 0.7978845608028654f * (x + 0.044715f * x * x * x);
    y = fminf(fmaxf(y, -30.f), 30.f);
    float t = __expf(2.f * y);
    float th = (t - 1.f) / (t + 1.f);
    return 0.5f * x * (1.f + th);
}
__device__ __forceinline__ float sigmoidf_(float x){
    return 1.f / (1.f + __expf(-x));
}
__device__ __forceinline__ void mma_f16(float* c, const uint32_t* a, const uint32_t* b){
    asm volatile("mma.sync.aligned.m16n8k16.row.col.f32.f16.f16.f32 "
        "{%0,%1,%2,%3}, {%4,%5,%6,%7}, {%8,%9}, {%0,%1,%2,%3};"
        : "+f"(c[0]), "+f"(c[1]), "+f"(c[2]), "+f"(c[3])
        : "r"(a[0]), "r"(a[1]), "r"(a[2]), "r"(a[3]), "r"(b[0]), "r"(b[1]));
}

// fp16 mma over smem: A [m][k] (strideA2 half2), B [n][k] (strideB2 half2).
// Warp tile 64x16: 4 m-tiles x 2 n-tiles of m16n8k16.
template<int KS>
__device__ __forceinline__ void warp_gemm_f16(
    const uint32_t* __restrict__ Xu, int strideA2,
    const uint32_t* __restrict__ Wu, int strideB2,
    int wm, int wn, int g, int tq, float acc[4][2][4])
{
#pragma unroll
    for (int ks = 0; ks < KS; ks++){
        int kh = ks*8;
        uint32_t a[4][4], b[2][2];
#pragma unroll
        for (int mt = 0; mt < 4; mt++){
            int rm = wm + mt*16 + g;
            a[mt][0] = Xu[rm*strideA2 + kh + tq];
            a[mt][1] = Xu[(rm+8)*strideA2 + kh + tq];
            a[mt][2] = Xu[rm*strideA2 + kh + tq + 4];
            a[mt][3] = Xu[(rm+8)*strideA2 + kh + tq + 4];
        }
#pragma unroll
        for (int nt = 0; nt < 2; nt++){
            int n = wn + nt*8 + g;
            b[nt][0] = Wu[n*strideB2 + kh + tq];
            b[nt][1] = Wu[n*strideB2 + kh + tq + 4];
        }
#pragma unroll
        for (int mt = 0; mt < 4; mt++)
#pragma unroll
            for (int nt = 0; nt < 2; nt++)
                mma_f16(acc[mt][nt], a[mt], b[nt]);
    }
}

// ---------------- weight transpose fp32 [K][N] -> fp16 [N][K] ----------------
__global__ __launch_bounds__(256) void transpose_f16(
    const float* __restrict__ W, __half* __restrict__ Wt, int K, int N)
{
    __shared__ float tile[32][33];
    int k0 = blockIdx.y*32, n0 = blockIdx.x*32;
    int tx = threadIdx.x & 31, ty = threadIdx.x >> 5;
    for (int i = ty; i < 32; i += 8)
        tile[i][tx] = W[(size_t)(k0+i)*N + n0 + tx];
    __syncthreads();
    for (int i = ty; i < 32; i += 8)
        Wt[(size_t)(n0+i)*K + k0 + tx] = __float2half(tile[tx][i]);
}

// ---------------- pack edge weights fp16, smem image layout ----------------
__global__ __launch_bounds__(256) void pack_edge_w(
    const float* __restrict__ W_eg, const float* __restrict__ eW1,
    const float* __restrict__ eW2, const float* __restrict__ W_oe,
    __half* __restrict__ ew)
{
    int i = blockIdx.x*256 + threadIdx.x;     // 0..4095
    if (i < 4096){
        int k = i >> 6, n = i & 63;
        ew[n*72 + k]         = __float2half(W_eg[i]);
        ew[4608 + n*72 + k]  = __float2half(eW1[i]);
        ew[9216 + n*72 + k]  = __float2half(eW2[i]);
    }
    if (i < 2048){
        int k = i >> 6, n = i & 63;
        ew[13824 + n*40 + k] = __float2half(W_oe[i]);
    }
}

// ---------------- LayerNorm over 768, fp16 out ----------------
__global__ __launch_bounds__(256) void ln768_kernel(
    const float* __restrict__ x, const float* __restrict__ g,
    const float* __restrict__ b, __half* __restrict__ y)
{
    int row = blockIdx.x;
    int tid = threadIdx.x;
    const float* xr = x + (size_t)row * DD_;
    __half*      yr = y + (size_t)row * DD_;
    float v0 = xr[tid], v1 = xr[tid+256], v2 = xr[tid+512];
    __shared__ float red[8];
    float s = warpSum(v0 + v1 + v2);
    if ((tid & 31) == 0) red[tid >> 5] = s;
    __syncthreads();
    float tot = 0.f;
#pragma unroll
    for (int i = 0; i < 8; i++) tot += red[i];
    __syncthreads();
    float mean = tot * (1.f/768.f);
    float d0 = v0-mean, d1 = v1-mean, d2 = v2-mean;
    float q = warpSum(d0*d0 + d1*d1 + d2*d2);
    if ((tid & 31) == 0) red[tid >> 5] = q;
    __syncthreads();
    float vt = 0.f;
#pragma unroll
    for (int i = 0; i < 8; i++) vt += red[i];
    float rstd = rsqrtf(vt * (1.f/768.f) + 1e-5f);
    yr[tid]     = __float2half(d0*rstd*g[tid]     + b[tid]);
    yr[tid+256] = __float2half(d1*rstd*g[tid+256] + b[tid+256]);
    yr[tid+512] = __float2half(d2*rstd*g[tid+512] + b[tid+512]);
}

// ---------------- fp16 tensor-core GEMM, CTA 128x128, warp 64x32, BK=64 ----------------
template<int EPI, int OUTH>
__global__ __launch_bounds__(256) void gemm_f16k(
    const __half* __restrict__ A, const __half* __restrict__ Bt,
    const float* __restrict__ bias, const float* __restrict__ R,
    float* __restrict__ C, __half* __restrict__ Ch, int M, int N, int K)
{
    __shared__ __half sA[128*72];
    __shared__ __half sB[128*72];
    int tid = threadIdx.x;
    int m0 = blockIdx.y * 128, n0 = blockIdx.x * 128;
    int lane = tid & 31, warp = tid >> 5;
    int wm = (warp >> 2) * 64, wn = (warp & 3) * 32;
    int g = lane >> 2, tq = lane & 3;
    int ar = tid >> 1, ac = (tid & 1) * 32;

    const uint32_t* Au = (const uint32_t*)sA;
    const uint32_t* Bu = (const uint32_t*)sB;

    float acc[4][4][4];
#pragma unroll
    for (int mt=0;mt<4;mt++)
#pragma unroll
        for (int nt=0;nt<4;nt++)
#pragma unroll
            for (int c=0;c<4;c++) acc[mt][nt][c]=0.f;

    for (int k0 = 0; k0 < K; k0 += 64){
        const uint4* ap = (const uint4*)&A[(size_t)(m0+ar)*K + k0 + ac];
        uint4* asp = (uint4*)&sA[ar*72 + ac];
        asp[0]=ap[0]; asp[1]=ap[1]; asp[2]=ap[2]; asp[3]=ap[3];
        const uint4* bp = (const uint4*)&Bt[(size_t)(n0+ar)*K + k0 + ac];
        uint4* bsp = (uint4*)&sB[ar*72 + ac];
        bsp[0]=bp[0]; bsp[1]=bp[1]; bsp[2]=bp[2]; bsp[3]=bp[3];
        __syncthreads();
#pragma unroll
        for (int ks = 0; ks < 4; ks++){
            int kh = ks*8;
            uint32_t a[4][4], b[4][2];
#pragma unroll
            for (int mt = 0; mt < 4; mt++){
                int rm = wm + mt*16 + g;
                a[mt][0] = Au[rm*36 + kh + tq];
                a[mt][1] = Au[(rm+8)*36 + kh + tq];
                a[mt][2] = Au[rm*36 + kh + tq + 4];
                a[mt][3] = Au[(rm+8)*36 + kh + tq + 4];
            }
#pragma unroll
            for (int nt = 0; nt < 4; nt++){
                int n = wn + nt*8 + g;
                b[nt][0] = Bu[n*36 + kh + tq];
                b[nt][1] = Bu[n*36 + kh + tq + 4];
            }
#pragma unroll
            for (int mt = 0; mt < 4; mt++)
#pragma unroll
                for (int nt = 0; nt < 4; nt++)
                    mma_f16(acc[mt][nt], a[mt], b[nt]);
        }
        __syncthreads();
    }
#pragma unroll
    for (int mt = 0; mt < 4; mt++){
#pragma unroll
        for (int nt = 0; nt < 4; nt++){
            int n = n0 + wn + nt*8 + 2*tq;
            float b0 = bias[n], b1 = bias[n+1];
#pragma unroll
            for (int rh = 0; rh < 2; rh++){
                int m = m0 + wm + mt*16 + g + rh*8;
                float v0 = acc[mt][nt][rh*2+0] + b0;
                float v1 = acc[mt][nt][rh*2+1] + b1;
                if (EPI == 1){ v0 = gelu_tanh(v0); v1 = gelu_tanh(v1); }
                if (OUTH){
                    *(__half2*)&Ch[(size_t)m*N + n] = __floats2half2_rn(v0, v1);
                } else {
                    if (R){
                        v0 += R[(size_t)m*N + n];
                        v1 += R[(size_t)m*N + n + 1];
                    }
                    *(float2*)&C[(size_t)m*N + n] = make_float2(v0, v1);
                }
            }
        }
    }
}

// ---------------- fp16 QKV GEMM with head-transposed scatter ----------------
// V written d-major: vt[bh][dd][l]
__global__ __launch_bounds__(256) void gemm_qkv_f16(
    const __half* __restrict__ A, const __half* __restrict__ Bt,
    const float* __restrict__ bias,
    float* __restrict__ qt, float* __restrict__ kt, float* __restrict__ vt)
{
    const int N = 2304, K = 768;
    __shared__ __half sA[128*72];
    __shared__ __half sB[128*72];
    int tid = threadIdx.x;
    int m0 = blockIdx.y * 128, n0 = blockIdx.x * 128;
    int lane = tid & 31, warp = tid >> 5;
    int wm = (warp >> 2) * 64, wn = (warp & 3) * 32;
    int g = lane >> 2, tq = lane & 3;
    int ar = tid >> 1, ac = (tid & 1) * 32;

    const uint32_t* Au = (const uint32_t*)sA;
    const uint32_t* Bu = (const uint32_t*)sB;

    float acc[4][4][4];
#pragma unroll
    for (int mt=0;mt<4;mt++)
#pragma unroll
        for (int nt=0;nt<4;nt++)
#pragma unroll
            for (int c=0;c<4;c++) acc[mt][nt][c]=0.f;

    for (int k0 = 0; k0 < K; k0 += 64){
        const uint4* ap = (const uint4*)&A[(size_t)(m0+ar)*K + k0 + ac];
        uint4* asp = (uint4*)&sA[ar*72 + ac];
        asp[0]=ap[0]; asp[1]=ap[1]; asp[2]=ap[2]; asp[3]=ap[3];
        const uint4* bp = (const uint4*)&Bt[(size_t)(n0+ar)*K + k0 + ac];
        uint4* bsp = (uint4*)&sB[ar*72 + ac];
        bsp[0]=bp[0]; bsp[1]=bp[1]; bsp[2]=bp[2]; bsp[3]=bp[3];
        __syncthreads();
#pragma unroll
        for (int ks = 0; ks < 4; ks++){
            int kh = ks*8;
            uint32_t a[4][4], b[4][2];
#pragma unroll
            for (int mt = 0; mt < 4; mt++){
                int rm = wm + mt*16 + g;
                a[mt][0] = Au[rm*36 + kh + tq];
                a[mt][1] = Au[(rm+8)*36 + kh + tq];
                a[mt][2] = Au[rm*36 + kh + tq + 4];
                a[mt][3] = Au[(rm+8)*36 + kh + tq + 4];
            }
#pragma unroll
            for (int nt = 0; nt < 4; nt++){
                int n = wn + nt*8 + g;
                b[nt][0] = Bu[n*36 + kh + tq];
                b[nt][1] = Bu[n*36 + kh + tq + 4];
            }
#pragma unroll
            for (int mt = 0; mt < 4; mt++)
#pragma unroll
                for (int nt = 0; nt < 4; nt++)
                    mma_f16(acc[mt][nt], a[mt], b[nt]);
        }
        __syncthreads();
    }
#pragma unroll
    for (int mt = 0; mt < 4; mt++){
#pragma unroll
        for (int rh = 0; rh < 2; rh++){
            int m = m0 + wm + mt*16 + g + rh*8;
            int b = m >> 8, l = m & 255;
#pragma unroll
            for (int nt = 0; nt < 4; nt++){
#pragma unroll
                for (int e = 0; e < 2; e++){
                    int n = n0 + wn + nt*8 + 2*tq + e;
                    float v = acc[mt][nt][rh*2+e] + bias[n];
                    int seg = n / 768;
                    int nn = n - seg*768;
                    int dd = nn >> 5, h = nn & 31;
                    if (seg == 0){
                        qt[(((size_t)(b*32 + h))*256 + l)*24 + dd] = v * SCALE_Q;
                    } else if (seg == 1){
                        kt[(((size_t)(b*32 + h))*256 + l)*24 + dd] = v;
                    } else {
                        vt[(((size_t)(b*32 + h))*24 + dd)*256 + l] = v;
                    }
                }
            }
        }
    }
}

// ---------------- QK kernel ----------------
__global__ __launch_bounds__(256) void qk_kernel(
    const float* __restrict__ qt, const float* __restrict__ kt,
    float* __restrict__ qk)
{
    int bh = blockIdx.y;
    int l0 = (blockIdx.x >> 1) * 128;
    int m0 = (blockIdx.x & 1) * 128;
    __shared__ float sQ[24*132];
    __shared__ float sK[24*132];
    int tid = threadIdx.x;
    const float* qb = qt + (size_t)bh*6144 + (size_t)l0*24;
    const float* kb = kt + (size_t)bh*6144 + (size_t)m0*24;
    for (int i = tid; i < 3072; i += 256){
        int r = i / 24, d = i - r*24;
        sQ[d*132 + r] = qb[i];
        sK[d*132 + r] = kb[i];
    }
    __syncthreads();
    int tx = tid & 15, ty = tid >> 4;
    float acc[8][8];
#pragma unroll
    for (int i = 0; i < 8; i++)
#pragma unroll
        for (int j = 0; j < 8; j++) acc[i][j] = 0.f;
#pragma unroll 6
    for (int k = 0; k < 24; k++){
        float4 a0 = *(const float4*)&sQ[k*132 + ty*8];
        float4 a1 = *(const float4*)&sQ[k*132 + ty*8 + 4];
        float4 b0 = *(const float4*)&sK[k*132 + tx*8];
        float4 b1 = *(const float4*)&sK[k*132 + tx*8 + 4];
        float a[8] = {a0.x,a0.y,a0.z,a0.w,a1.x,a1.y,a1.z,a1.w};
        float b[8] = {b0.x,b0.y,b0.z,b0.w,b1.x,b1.y,b1.z,b1.w};
#pragma unroll
        for (int i = 0; i < 8; i++)
#pragma unroll
            for (int j = 0; j < 8; j++) acc[i][j] += a[i]*b[j];
    }
    float* out = qk + (size_t)bh*65536 + (size_t)l0*256 + m0;
#pragma unroll
    for (int i = 0; i < 8; i++){
        float* orow = out + (size_t)(ty*8 + i)*256 + tx*8;
        *(float4*)orow     = make_float4(acc[i][0],acc[i][1],acc[i][2],acc[i][3]);
        *(float4*)(orow+4) = make_float4(acc[i][4],acc[i][5],acc[i][6],acc[i][7]);
    }
}

// ---------------- fused edge kernel: per (row, half) CTA, 256 threads, 2 CTAs/SM ----------------
// smem (floats):
//   sPar 512 @0 ; sMask 128 @512 ;
//   weights fp16 @640: packed image (16384 halves = 8192 f) -> ends 8832 ;
//   sX16 [128][72] halves = 4608 floats @8832 -> ends 13440 ;
//   sRed [128][4] float2 = 1024 floats @13440 -> ends 14464 ;
//   sE [128][68] f32 = 8704 floats @14464 -> ends 23168   (92672 B/CTA, 2 CTAs/SM)
#define EK_FLOATS 23168
__global__ __launch_bounds__(256, 2) void edge_attn_kernel(
    const float* __restrict__ e_in, const float* __restrict__ mask,
    float* __restrict__ qk,               // in: QK ; out: H_hat + mask (in-place)
    const __half* __restrict__ ew16,
    const float* __restrict__ b_eg, const float* __restrict__ b_oe,
    const float* __restrict__ eln_g, const float* __restrict__ eln_b,
    const float* __restrict__ ffn_g, const float* __restrict__ ffn_b,
    const float* __restrict__ eb1, const float* __restrict__ eb2,
    float* __restrict__ e_out, __half* __restrict__ gate16)
{
    extern __shared__ float sm[];
    float* sPar  = sm;
    float* sMask = sm + 512;
    __half* sW16 = (__half*)(sm + 640);
    __half* Weg_t = sW16;           // [64][72]
    __half* W1_t  = sW16 + 4608;    // [64][72]
    __half* W2_t  = sW16 + 9216;    // [64][72]
    __half* Woe_t = sW16 + 13824;   // [64][40]
    __half* sX16  = (__half*)(sm + 8832);   // [128][72] halves
    float*  sRed  = sm + 13440;             // [128][4] float2
    float*  sE    = sm + 14464;             // [128][68] f32

    int tid  = threadIdx.x;
    int lane = tid & 31;
    int g    = lane >> 2;
    int tq   = lane & 3;
    int wg8  = tid >> 5;                 // 0..7
    int wm   = (wg8 >> 2) * 64;
    int wn   = (wg8 & 3) * 16;
    int bid  = blockIdx.x;
    int row  = bid >> 1;
    int grp  = bid & 1;
    int b    = row >> 8;
    int l    = row & 255;
    int m0g  = grp * 128;

    // ---- stage packed weights (uint4 copy), params, mask ----
    {
        const uint4* src = (const uint4*)ew16;
        uint4* dst = (uint4*)sW16;
#pragma unroll
        for (int i = 0; i < 8; i++)
            dst[tid + i*256] = src[tid + i*256];
    }
    if (tid < 64){
        sPar[tid]     = b_eg[tid];
        sPar[64+tid]  = b_oe[tid];
        sPar[128+tid] = eb1[tid];
        sPar[192+tid] = eb2[tid];
        sPar[256+tid] = eln_g[tid];
        sPar[320+tid] = eln_b[tid];
        sPar[384+tid] = ffn_g[tid];
        sPar[448+tid] = ffn_b[tid];
    }
    if (tid < 128) sMask[tid] = mask[(size_t)row*256 + m0g + tid];
    __syncthreads();

    // ---- LN1: thread-mapped, store fp16 X[m][k] + raw e to sE ----
    {
        int ty = tid >> 4, tx = tid & 15;
        float lg0 = sPar[256+tx*4], lg1 = sPar[257+tx*4], lg2 = sPar[258+tx*4], lg3 = sPar[259+tx*4];
        float lb0 = sPar[320+tx*4], lb1 = sPar[321+tx*4], lb2 = sPar[322+tx*4], lb3 = sPar[323+tx*4];
        __half2* xp = (__half2*)sX16;
#pragma unroll
        for (int i = 0; i < 8; i++){
            int r = ty*8 + i;
            float4 e4 = *(const float4*)&e_in[((size_t)row*256 + m0g + r)*64 + tx*4];
            *(float4*)&sE[r*68 + tx*4] = e4;
            float s = sum16(e4.x + e4.y + e4.z + e4.w);
            float mean = s * (1.f/64.f);
            float d0=e4.x-mean, d1=e4.y-mean, d2=e4.z-mean, d3=e4.w-mean;
            float q = sum16(d0*d0 + d1*d1 + d2*d2 + d3*d3);
            float rs = rsqrtf(q * (1.f/64.f) + 1e-5f);
            xp[r*36 + tx*2    ] = __floats2half2_rn(d0*rs*lg0 + lb0, d1*rs*lg1 + lb1);
            xp[r*36 + tx*2 + 1] = __floats2half2_rn(d2*rs*lg2 + lb2, d3*rs*lg3 + lb3);
        }
    }
    __syncthreads();

    float acc[4][2][4];
    const uint32_t* Xu = (const uint32_t*)sX16;

    // ---- GEMM1: EG = X @ W_eg (K=64) ----
#pragma unroll
    for (int mt=0;mt<4;mt++)
#pragma unroll
        for (int nt=0;nt<2;nt++)
#pragma unroll
            for (int c=0;c<4;c++) acc[mt][nt][c]=0.f;
    warp_gemm_f16<4>(Xu, 36, (const uint32_t*)Weg_t, 36, wm, wn, g, tq, acc);
    __syncthreads();   // all X reads done before H overwrites sX16

    size_t qkbase = ((size_t)(b*32))*65536 + (size_t)l*256 + m0g;
    if (wn < 32){
        // E columns -> H_hat: fp16 unmasked into sX16 (for e_att) + masked fp32 into qk (for softmax)
        __half2* hp = (__half2*)sX16;
#pragma unroll
        for (int mt=0;mt<4;mt++)
#pragma unroll
            for (int nt=0;nt<2;nt++){
                int nc = wn + nt*8 + 2*tq;
#pragma unroll
                for (int rh=0;rh<2;rh++){
                    int m = wm + mt*16 + g + rh*8;
                    size_t qi = qkbase + (size_t)nc*65536 + m;
                    float v0 = acc[mt][nt][rh*2+0] + sPar[nc]   + qk[qi];
                    float v1 = acc[mt][nt][rh*2+1] + sPar[nc+1] + qk[qi + 65536];
                    float mk = sMask[m];
                    qk[qi]         = v0 + mk;
                    qk[qi + 65536] = v1 + mk;
                    hp[m*36 + (nc>>1)] = __floats2half2_rn(v0, v1);
                }
            }
    } else {
        // G columns -> gates (fp16 to gmem)
#pragma unroll
        for (int mt=0;mt<4;mt++)
#pragma unroll
            for (int nt=0;nt<2;nt++){
                int nc = wn + nt*8 + 2*tq;
                int h0 = nc - 32;
#pragma unroll
                for (int rh=0;rh<2;rh++){
                    int m = wm + mt*16 + g + rh*8;
                    float mk = sMask[m];
                    size_t gi = qkbase + (size_t)h0*65536 + m;
                    gate16[gi]         = __float2half(sigmoidf_(acc[mt][nt][rh*2+0] + sPar[nc]   + mk));
                    gate16[gi + 65536] = __float2half(sigmoidf_(acc[mt][nt][rh*2+1] + sPar[nc+1] + mk));
                }
            }
    }
    __syncthreads();

    // ---- GEMM2: e_att = H_hat @ W_oe (K=32, A = H fp16 in sX16) ; r = e + e_att + b_oe ----
#pragma unroll
    for (int mt=0;mt<4;mt++)
#pragma unroll
        for (int nt=0;nt<2;nt++)
#pragma unroll
            for (int c=0;c<4;c++) acc[mt][nt][c]=0.f;
    warp_gemm_f16<2>(Xu, 36, (const uint32_t*)Woe_t, 20, wm, wn, g, tq, acc);

    float r_[4][2][4];
#pragma unroll
    for (int mt=0;mt<4;mt++)
#pragma unroll
        for (int nt=0;nt<2;nt++){
            int nc = wn + nt*8 + 2*tq;
            int m  = wm + mt*16 + g;
            const float* ep = &sE[m*68 + nc];
            float2 ea = *(const float2*)ep;
            float2 eb = *(const float2*)(ep + 8*68);
            r_[mt][nt][0] = ea.x + acc[mt][nt][0] + sPar[64+nc];
            r_[mt][nt][1] = ea.y + acc[mt][nt][1] + sPar[64+nc+1];
            r_[mt][nt][2] = eb.x + acc[mt][nt][2] + sPar[64+nc];
            r_[mt][nt][3] = eb.y + acc[mt][nt][3] + sPar[64+nc+1];
        }

    // ---- LN2 on r (fragments): quad-reduce + cross-warp smem reduce ----
    {
        float2* rp = (float2*)sRed;
#pragma unroll
        for (int mt=0;mt<4;mt++)
#pragma unroll
            for (int rh=0;rh<2;rh++){
                float ps = r_[mt][0][rh*2] + r_[mt][0][rh*2+1]
                         + r_[mt][1][rh*2] + r_[mt][1][rh*2+1];
                float pq = r_[mt][0][rh*2]*r_[mt][0][rh*2] + r_[mt][0][rh*2+1]*r_[mt][0][rh*2+1]
                         + r_[mt][1][rh*2]*r_[mt][1][rh*2] + r_[mt][1][rh*2+1]*r_[mt][1][rh*2+1];
                ps += __shfl_xor_sync(FULLMASK, ps, 1);
                ps += __shfl_xor_sync(FULLMASK, ps, 2);
                pq += __shfl_xor_sync(FULLMASK, pq, 1);
                pq += __shfl_xor_sync(FULLMASK, pq, 2);
                if (tq == 0){
                    int m = wm + mt*16 + g + rh*8;
                    rp[m*4 + (wg8 & 3)] = make_float2(ps, pq);
                }
            }
    }
    __syncthreads();
    {
        __half2* xp = (__half2*)sX16;
        const float2* rp = (const float2*)sRed;
#pragma unroll
        for (int mt=0;mt<4;mt++)
#pragma unroll
            for (int rh=0;rh<2;rh++){
                int m = wm + mt*16 + g + rh*8;
                float2 p0 = rp[m*4+0], p1 = rp[m*4+1], p2 = rp[m*4+2], p3 = rp[m*4+3];
                float mu = (p0.x+p1.x+p2.x+p3.x) * (1.f/64.f);
                float vq = (p0.y+p1.y+p2.y+p3.y) * (1.f/64.f) - mu*mu;
                float rs = rsqrtf(vq + 1e-5f);
#pragma unroll
                for (int nt=0;nt<2;nt++){
                    int nc = wn + nt*8 + 2*tq;
                    float v0 = (r_[mt][nt][rh*2+0]-mu)*rs*sPar[384+nc]   + sPar[448+nc];
                    float v1 = (r_[mt][nt][rh*2+1]-mu)*rs*sPar[384+nc+1] + sPar[448+nc+1];
                    xp[m*36 + (nc>>1)] = __floats2half2_rn(v0, v1);
                }
            }
    }
    __syncthreads();

    // ---- GEMM3: T = gelu(X2 @ eW1 + b1) ----
#pragma unroll
    for (int mt=0;mt<4;mt++)
#pragma unroll
        for (int nt=0;nt<2;nt++)
#pragma unroll
            for (int c=0;c<4;c++) acc[mt][nt][c]=0.f;
    warp_gemm_f16<4>(Xu, 36, (const uint32_t*)W1_t, 36, wm, wn, g, tq, acc);
    __syncthreads();
    {
        __half2* xp = (__half2*)sX16;
#pragma unroll
        for (int mt=0;mt<4;mt++)
#pragma unroll
            for (int nt=0;nt<2;nt++){
                int nc = wn + nt*8 + 2*tq;
#pragma unroll
                for (int rh=0;rh<2;rh++){
                    int m = wm + mt*16 + g + rh*8;
                    float v0 = gelu_tanh(acc[mt][nt][rh*2+0] + sPar[128+nc]);
                    float v1 = gelu_tanh(acc[mt][nt][rh*2+1] + sPar[128+nc+1]);
                    xp[m*36 + (nc>>1)] = __floats2half2_rn(v0, v1);
                }
            }
    }
    __syncthreads();

    // ---- GEMM4: O = T @ eW2 + b2 ; e_out = r + O ----
#pragma unroll
    for (int mt=0;mt<4;mt++)
#pragma unroll
        for (int nt=0;nt<2;nt++)
#pragma unroll
            for (int c=0;c<4;c++) acc[mt][nt][c]=0.f;
    warp_gemm_f16<4>(Xu, 36, (const uint32_t*)W2_t, 36, wm, wn, g, tq, acc);
#pragma unroll
    for (int mt=0;mt<4;mt++)
#pragma unroll
        for (int nt=0;nt<2;nt++){
            int nc = wn + nt*8 + 2*tq;
            int m  = wm + mt*16 + g;
            float* op = &e_out[((size_t)row*256 + m0g + m)*64 + nc];
            *(float2*)op = make_float2(
                r_[mt][nt][0] + acc[mt][nt][0] + sPar[192+nc],
                r_[mt][nt][1] + acc[mt][nt][1] + sPar[192+nc+1]);
            *(float2*)(op + 8*64) = make_float2(
                r_[mt][nt][2] + acc[mt][nt][2] + sPar[192+nc],
                r_[mt][nt][3] + acc[mt][nt][3] + sPar[192+nc+1]);
        }
}

// ---------------- softmax + AV kernel: per (bh, 32-l tile) ----------------
// logits arrive pre-masked; no mask load here.
// smem: sL [32][260] f32 (8320) ; sV [24][260] f32 (6240) ; sG [32][264]h (4224 f)
#define AV_FLOATS (8320 + 6240 + 4224)
__global__ __launch_bounds__(256) void av_softmax_kernel(
    const float* __restrict__ logits, const __half* __restrict__ gate16,
    const float* __restrict__ vt, __half* __restrict__ vatt)
{
    extern __shared__ float sm[];
    float* sL = sm;                    // [32][260]
    float* sV = sm + 8320;             // [24][260]
    __half* sG = (__half*)(sm + 14560);// [32][264]
    int bh = blockIdx.y;
    int l0 = blockIdx.x * 32;
    int b = bh >> 5, h = bh & 31;
    int tid = threadIdx.x;

    const float* lb = logits + (size_t)bh*65536 + (size_t)l0*256;
    for (int i = tid; i < 2048; i += 256){
        int ll = i >> 6, m = (i & 63) * 4;
        *(float4*)&sL[ll*260 + m] = *(const float4*)&lb[(size_t)ll*256 + m];
    }
    const __half* gb = gate16 + (size_t)bh*65536 + (size_t)l0*256;
    for (int i = tid; i < 1024; i += 256){
        int ll = i >> 5, m = (i & 31) * 8;
        *(uint4*)&sG[ll*264 + m] = *(const uint4*)&gb[(size_t)ll*256 + m];
    }
    // V d-major: coalesced float4 copy into [24][260]
    const float* vb = vt + (size_t)bh*6144;
    for (int i = tid; i < 1536; i += 256){
        int dd = i >> 6, m = (i & 63) * 4;
        *(float4*)&sV[dd*260 + m] = *(const float4*)&vb[dd*256 + m];
    }
    __syncthreads();

    int w = tid >> 5, lane = tid & 31;
    // softmax + gate fold: warp w -> rows w*4..w*4+3
#pragma unroll
    for (int rr = 0; rr < 4; rr++){
        int row = w*4 + rr;
        float p[8], gg[8];
        float mx = -3.4e38f;
#pragma unroll
        for (int j = 0; j < 8; j++){
            p[j] = sL[row*260 + j*32 + lane];
            mx = fmaxf(mx, p[j]);
        }
        mx = warpMax(mx);
        float s = 0.f, gs = 0.f;
#pragma unroll
        for (int j = 0; j < 8; j++){
            p[j] = __expf(p[j] - mx);
            s += p[j];
            gg[j] = __half2float(sG[row*264 + j*32 + lane]);
            gs += gg[j];
        }
        s = warpSum(s); gs = warpSum(gs);
        float c = (1.f / s) * log1pf(gs);
#pragma unroll
        for (int j = 0; j < 8; j++)
            sL[row*260 + j*32 + lane] = p[j] * gg[j] * c;
    }
    __syncthreads();

    // AV: warp w -> rows w*4..+3, lanes < 24 = dims
    if (lane < 24){
        const float* vr = &sV[lane*260];
#pragma unroll
        for (int j = 0; j < 4; j++){
            int ll = w*4 + j;
            const float* ar = &sL[ll*260];
            float acc = 0.f;
#pragma unroll 8
            for (int m = 0; m < 256; m += 4){
                float4 a = *(const float4*)&ar[m];
                float4 v = *(const float4*)&vr[m];
                acc += a.x*v.x + a.y*v.y + a.z*v.z + a.w*v.w;
            }
            vatt[(size_t)(b*256 + l0 + ll)*768 + lane*32 + h] = __float2half(acc);
        }
    }
}

// ---------------- host ----------------
extern "C" void kernel_launch(void* const* d_in, const int* in_sizes, int n_in,
                              void* d_out, int out_size)
{
    const float* h_in   = (const float*)d_in[0];
    const float* e_in   = (const float*)d_in[1];
    const float* mask   = (const float*)d_in[2];
    const float* ln_h_g = (const float*)d_in[3];
    const float* ln_h_b = (const float*)d_in[4];
    const float* ln_e_g = (const float*)d_in[5];
    const float* ln_e_b = (const float*)d_in[6];
    const float* W_qkv  = (const float*)d_in[7];
    const float* b_qkv  = (const float*)d_in[8];
    const float* W_eg   = (const float*)d_in[9];
    const float* b_eg   = (const float*)d_in[10];
    const float* W_oh   = (const float*)d_in[11];
    const float* b_oh   = (const float*)d_in[12];
    const float* W_oe   = (const float*)d_in[13];
    const float* b_oe   = (const float*)d_in[14];
    const float* nffn_g = (const float*)d_in[15];
    const float* nffn_b = (const float*)d_in[16];
    const float* nW1    = (const float*)d_in[17];
    const float* nb1    = (const float*)d_in[18];
    const float* nW2    = (const float*)d_in[19];
    const float* nb2    = (const float*)d_in[20];
    const float* effn_g = (const float*)d_in[21];
    const float* effn_b = (const float*)d_in[22];
    const float* eW1    = (const float*)d_in[23];
    const float* eb1    = (const float*)d_in[24];
    const float* eW2    = (const float*)d_in[25];
    const float* eb2    = (const float*)d_in[26];

    float* out_h = (float*)d_out;
    float* out_e = out_h + (size_t)ROWS * DD_;

    float *qt, *kt, *vt, *qk, *hmid;
    __half *gate16, *hln16, *hln216, *t16, *vatt16, *wqkv16, *woh16, *nw116, *nw216, *ew16;
    cudaGetSymbolAddress((void**)&qt,     g_qt);
    cudaGetSymbolAddress((void**)&kt,     g_kt);
    cudaGetSymbolAddress((void**)&vt,     g_vt);
    cudaGetSymbolAddress((void**)&qk,     g_qk);
    cudaGetSymbolAddress((void**)&gate16, g_gate16);
    cudaGetSymbolAddress((void**)&hmid,   g_hmid);
    cudaGetSymbolAddress((void**)&hln16,  g_hln16);
    cudaGetSymbolAddress((void**)&hln216, g_hln216);
    cudaGetSymbolAddress((void**)&t16,    g_t16);
    cudaGetSymbolAddress((void**)&vatt16, g_vatt16);
    cudaGetSymbolAddress((void**)&wqkv16, g_wqkv16);
    cudaGetSymbolAddress((void**)&woh16,  g_woh16);
    cudaGetSymbolAddress((void**)&nw116,  g_nw116);
    cudaGetSymbolAddress((void**)&nw216,  g_nw216);
    cudaGetSymbolAddress((void**)&ew16,   g_ew16);

    cudaFuncSetAttribute(edge_attn_kernel,
                         cudaFuncAttributeMaxDynamicSharedMemorySize,
                         EK_FLOATS * 4);
    cudaFuncSetAttribute(av_softmax_kernel,
                         cudaFuncAttributeMaxDynamicSharedMemorySize,
                         AV_FLOATS * 4);

    // 0) weight transposes / packing
    transpose_f16<<<dim3(72, 24), 256>>>(W_qkv, wqkv16, 768, 2304);
    transpose_f16<<<dim3(24, 24), 256>>>(W_oh,  woh16,  768, 768);
    transpose_f16<<<dim3(24, 24), 256>>>(nW1,   nw116,  768, 768);
    transpose_f16<<<dim3(24, 24), 256>>>(nW2,   nw216,  768, 768);
    pack_edge_w<<<16, 256>>>(W_eg, eW1, eW2, W_oe, ew16);

    // 1) h layernorm -> fp16
    ln768_kernel<<<ROWS, 256>>>(h_in, ln_h_g, ln_h_b, hln16);

    // 2) QKV GEMM (fp16 mma) with transposed scatter (V d-major)
    gemm_qkv_f16<<<dim3(18, 16), 256>>>(hln16, wqkv16, b_qkv, qt, kt, vt);

    // 3) QK = Q K^T per head (into qk buffer)
    qk_kernel<<<dim3(4, 256), 256>>>(qt, kt, qk);

    // 4) edge attention + edge FFN: masked H_hat in-place into qk, gates -> gate16
    edge_attn_kernel<<<2*ROWS, 256, EK_FLOATS * 4>>>(
        e_in, mask, qk, ew16,
        b_eg, b_oe,
        ln_e_g, ln_e_b, effn_g, effn_b,
        eb1, eb2,
        out_e, gate16);

    // 5) softmax + V_att = A' @ V -> fp16 (logits pre-masked)
    av_softmax_kernel<<<dim3(8, 256), 256, AV_FLOATS * 4>>>(
        qk, gate16, vt, vatt16);

    // 6) h_mid = h + V_att @ W_oh + b_oh (fp16 mma)
    gemm_f16k<0,0><<<dim3(6, 16), 256>>>(vatt16, woh16, b_oh, h_in,
                                         hmid, nullptr, ROWS, DD_, DD_);

    // 7) node FFN (fp16 mma)
    ln768_kernel<<<ROWS, 256>>>(hmid, nffn_g, nffn_b, hln216);
    gemm_f16k<1,1><<<dim3(6, 16), 256>>>(hln216, nw116, nb1, nullptr,
                                         nullptr, t16, ROWS, DD_, DD_);
    gemm_f16k<0,0><<<dim3(6, 16), 256>>>(t16, nw216, nb2, hmid,
                                         out_h, nullptr, ROWS, DD_, DD_);
}

// round 16
// speedup vs baseline: 3.0538x; 1.0880x over previous
#include <cuda_runtime.h>
#include <cuda_fp16.h>
#include <cstddef>
#include <cstdint>

// ---------------- problem constants ----------------
#define BB 8
#define NN 256
#define DD_ 768
#define ROWS (BB*NN)     // 2048
#define SCALE_Q 0.20412414523193154f   // 24^-0.5
#define FULLMASK 0xffffffffu

// ---------------- scratch (device globals; no allocation) ----------------
__device__ float  g_qt  [8*32*256*24];
__device__ float  g_kt  [8*32*256*24];
__device__ float  g_vt  [8*32*24*256];     // d-major: [bh][24][256]
__device__ float  g_qk  [8*32*256*256];    // raw QK (read-only after qk_kernel)
__device__ __half g_logit16[8*32*256*256]; // masked logits (softmax input)
__device__ __half g_gate16 [8*32*256*256];
__device__ float  g_hmid[ROWS*DD_];
__device__ __half g_hln16 [ROWS*DD_];
__device__ __half g_hln216[ROWS*DD_];
__device__ __half g_t16   [ROWS*DD_];
__device__ __half g_vatt16[ROWS*DD_];
__device__ __half g_wqkv16[2304*768];
__device__ __half g_woh16 [768*768];
__device__ __half g_nw116 [768*768];
__device__ __half g_nw216 [768*768];
__device__ __half g_ew16  [16384];         // packed edge weights (smem image)

// ---------------- helpers ----------------
__device__ __forceinline__ float warpSum(float v){
#pragma unroll
    for (int o = 16; o; o >>= 1) v += __shfl_xor_sync(FULLMASK, v, o);
    return v;
}
__device__ __forceinline__ float warpMax(float v){
#pragma unroll
    for (int o = 16; o; o >>= 1) v = fmaxf(v, __shfl_xor_sync(FULLMASK, v, o));
    return v;
}
__device__ __forceinline__ float sum16(float v){
#pragma unroll
    for (int o = 8; o; o >>= 1) v += __shfl_xor_sync(FULLMASK, v, o);
    return v;
}
__device__ __forceinline__ float gelu_tanh(float x){
    float y = 0.7978845608028654f * (x + 0.044715f * x * x * x);
    y = fminf(fmaxf(y, -30.f), 30.f);
    float t = __expf(2.f * y);
    float th = (t - 1.f) / (t + 1.f);
    return 0.5f * x * (1.f + th);
}
__device__ __forceinline__ float sigmoidf_(float x){
    return 1.f / (1.f + __expf(-x));
}
__device__ __forceinline__ void mma_f16(float* c, const uint32_t* a, const uint32_t* b){
    asm volatile("mma.sync.aligned.m16n8k16.row.col.f32.f16.f16.f32 "
        "{%0,%1,%2,%3}, {%4,%5,%6,%7}, {%8,%9}, {%0,%1,%2,%3};"
        : "+f"(c[0]), "+f"(c[1]), "+f"(c[2]), "+f"(c[3])
        : "r"(a[0]), "r"(a[1]), "r"(a[2]), "r"(a[3]), "r"(b[0]), "r"(b[1]));
}

// fp16 mma over smem: A [m][k] (strideA2 half2), B [n][k] (strideB2 half2).
template<int KS>
__device__ __forceinline__ void warp_gemm_f16(
    const uint32_t* __restrict__ Xu, int strideA2,
    const uint32_t* __restrict__ Wu, int strideB2,
    int wm, int wn, int g, int tq, float acc[4][2][4])
{
#pragma unroll
    for (int ks = 0; ks < KS; ks++){
        int kh = ks*8;
        uint32_t a[4][4], b[2][2];
#pragma unroll
        for (int mt = 0; mt < 4; mt++){
            int rm = wm + mt*16 + g;
            a[mt][0] = Xu[rm*strideA2 + kh + tq];
            a[mt][1] = Xu[(rm+8)*strideA2 + kh + tq];
            a[mt][2] = Xu[rm*strideA2 + kh + tq + 4];
            a[mt][3] = Xu[(rm+8)*strideA2 + kh + tq + 4];
        }
#pragma unroll
        for (int nt = 0; nt < 2; nt++){
            int n = wn + nt*8 + g;
            b[nt][0] = Wu[n*strideB2 + kh + tq];
            b[nt][1] = Wu[n*strideB2 + kh + tq + 4];
        }
#pragma unroll
        for (int mt = 0; mt < 4; mt++)
#pragma unroll
            for (int nt = 0; nt < 2; nt++)
                mma_f16(acc[mt][nt], a[mt], b[nt]);
    }
}

// ---------------- merged weight prep: one launch, z-dispatch ----------------
// z=0: W_qkv [768,2304] -> wqkv16 [2304][768]  (tiles 72x24)
// z=1..3: W_oh/nW1/nW2 [768,768] -> *16 [768][768] (tiles 24x24, guard)
// z=4: pack edge weights (first 16 x-blocks used)
__global__ __launch_bounds__(256) void weight_prep(
    const float* __restrict__ W_qkv, const float* __restrict__ W_oh,
    const float* __restrict__ nW1,  const float* __restrict__ nW2,
    const float* __restrict__ W_eg, const float* __restrict__ eW1,
    const float* __restrict__ eW2,  const float* __restrict__ W_oe,
    __half* __restrict__ wqkv16, __half* __restrict__ woh16,
    __half* __restrict__ nw116,  __half* __restrict__ nw216,
    __half* __restrict__ ew)
{
    int z = blockIdx.z;
    if (z == 4){
        int i = blockIdx.x*256 + threadIdx.x;
        if (blockIdx.y != 0) return;
        if (i < 4096){
            int k = i >> 6, n = i & 63;
            ew[n*72 + k]         = __float2half(W_eg[i]);
            ew[4608 + n*72 + k]  = __float2half(eW1[i]);
            ew[9216 + n*72 + k]  = __float2half(eW2[i]);
        }
        if (i < 2048){
            int k = i >> 6, n = i & 63;
            ew[13824 + n*40 + k] = __float2half(W_oe[i]);
        }
        return;
    }
    const float* W; __half* Wt; int K = 768, N;
    if (z == 0){ W = W_qkv; Wt = wqkv16; N = 2304; }
    else if (z == 1){ W = W_oh; Wt = woh16; N = 768; }
    else if (z == 2){ W = nW1; Wt = nw116; N = 768; }
    else { W = nW2; Wt = nw216; N = 768; }
    int n0 = blockIdx.x*32;
    if (n0 >= N) return;
    int k0 = blockIdx.y*32;
    __shared__ float tile[32][33];
    int tx = threadIdx.x & 31, ty = threadIdx.x >> 5;
    for (int i = ty; i < 32; i += 8)
        tile[i][tx] = W[(size_t)(k0+i)*N + n0 + tx];
    __syncthreads();
    for (int i = ty; i < 32; i += 8)
        Wt[(size_t)(n0+i)*K + k0 + tx] = __float2half(tile[tx][i]);
}

// ---------------- LayerNorm over 768, fp16 out ----------------
__global__ __launch_bounds__(256) void ln768_kernel(
    const float* __restrict__ x, const float* __restrict__ g,
    const float* __restrict__ b, __half* __restrict__ y)
{
    int row = blockIdx.x;
    int tid = threadIdx.x;
    const float* xr = x + (size_t)row * DD_;
    __half*      yr = y + (size_t)row * DD_;
    float v0 = xr[tid], v1 = xr[tid+256], v2 = xr[tid+512];
    __shared__ float red[8];
    float s = warpSum(v0 + v1 + v2);
    if ((tid & 31) == 0) red[tid >> 5] = s;
    __syncthreads();
    float tot = 0.f;
#pragma unroll
    for (int i = 0; i < 8; i++) tot += red[i];
    __syncthreads();
    float mean = tot * (1.f/768.f);
    float d0 = v0-mean, d1 = v1-mean, d2 = v2-mean;
    float q = warpSum(d0*d0 + d1*d1 + d2*d2);
    if ((tid & 31) == 0) red[tid >> 5] = q;
    __syncthreads();
    float vt = 0.f;
#pragma unroll
    for (int i = 0; i < 8; i++) vt += red[i];
    float rstd = rsqrtf(vt * (1.f/768.f) + 1e-5f);
    yr[tid]     = __float2half(d0*rstd*g[tid]     + b[tid]);
    yr[tid+256] = __float2half(d1*rstd*g[tid+256] + b[tid+256]);
    yr[tid+512] = __float2half(d2*rstd*g[tid+512] + b[tid+512]);
}

// ---------------- fp16 tensor-core GEMM, CTA 128x128, warp 64x32, BK=64 ----------------
template<int EPI, int OUTH>
__global__ __launch_bounds__(256) void gemm_f16k(
    const __half* __restrict__ A, const __half* __restrict__ Bt,
    const float* __restrict__ bias, const float* __restrict__ R,
    float* __restrict__ C, __half* __restrict__ Ch, int M, int N, int K)
{
    __shared__ __half sA[128*72];
    __shared__ __half sB[128*72];
    int tid = threadIdx.x;
    int m0 = blockIdx.y * 128, n0 = blockIdx.x * 128;
    int lane = tid & 31, warp = tid >> 5;
    int wm = (warp >> 2) * 64, wn = (warp & 3) * 32;
    int g = lane >> 2, tq = lane & 3;
    int ar = tid >> 1, ac = (tid & 1) * 32;

    const uint32_t* Au = (const uint32_t*)sA;
    const uint32_t* Bu = (const uint32_t*)sB;

    float acc[4][4][4];
#pragma unroll
    for (int mt=0;mt<4;mt++)
#pragma unroll
        for (int nt=0;nt<4;nt++)
#pragma unroll
            for (int c=0;c<4;c++) acc[mt][nt][c]=0.f;

    for (int k0 = 0; k0 < K; k0 += 64){
        const uint4* ap = (const uint4*)&A[(size_t)(m0+ar)*K + k0 + ac];
        uint4* asp = (uint4*)&sA[ar*72 + ac];
        asp[0]=ap[0]; asp[1]=ap[1]; asp[2]=ap[2]; asp[3]=ap[3];
        const uint4* bp = (const uint4*)&Bt[(size_t)(n0+ar)*K + k0 + ac];
        uint4* bsp = (uint4*)&sB[ar*72 + ac];
        bsp[0]=bp[0]; bsp[1]=bp[1]; bsp[2]=bp[2]; bsp[3]=bp[3];
        __syncthreads();
#pragma unroll
        for (int ks = 0; ks < 4; ks++){
            int kh = ks*8;
            uint32_t a[4][4], b[4][2];
#pragma unroll
            for (int mt = 0; mt < 4; mt++){
                int rm = wm + mt*16 + g;
                a[mt][0] = Au[rm*36 + kh + tq];
                a[mt][1] = Au[(rm+8)*36 + kh + tq];
                a[mt][2] = Au[rm*36 + kh + tq + 4];
                a[mt][3] = Au[(rm+8)*36 + kh + tq + 4];
            }
#pragma unroll
            for (int nt = 0; nt < 4; nt++){
                int n = wn + nt*8 + g;
                b[nt][0] = Bu[n*36 + kh + tq];
                b[nt][1] = Bu[n*36 + kh + tq + 4];
            }
#pragma unroll
            for (int mt = 0; mt < 4; mt++)
#pragma unroll
                for (int nt = 0; nt < 4; nt++)
                    mma_f16(acc[mt][nt], a[mt], b[nt]);
        }
        __syncthreads();
    }
#pragma unroll
    for (int mt = 0; mt < 4; mt++){
#pragma unroll
        for (int nt = 0; nt < 4; nt++){
            int n = n0 + wn + nt*8 + 2*tq;
            float b0 = bias[n], b1 = bias[n+1];
#pragma unroll
            for (int rh = 0; rh < 2; rh++){
                int m = m0 + wm + mt*16 + g + rh*8;
                float v0 = acc[mt][nt][rh*2+0] + b0;
                float v1 = acc[mt][nt][rh*2+1] + b1;
                if (EPI == 1){ v0 = gelu_tanh(v0); v1 = gelu_tanh(v1); }
                if (OUTH){
                    *(__half2*)&Ch[(size_t)m*N + n] = __floats2half2_rn(v0, v1);
                } else {
                    if (R){
                        v0 += R[(size_t)m*N + n];
                        v1 += R[(size_t)m*N + n + 1];
                    }
                    *(float2*)&C[(size_t)m*N + n] = make_float2(v0, v1);
                }
            }
        }
    }
}

// ---------------- fp16 QKV GEMM with head-transposed scatter ----------------
// V written d-major: vt[bh][dd][l]
__global__ __launch_bounds__(256) void gemm_qkv_f16(
    const __half* __restrict__ A, const __half* __restrict__ Bt,
    const float* __restrict__ bias,
    float* __restrict__ qt, float* __restrict__ kt, float* __restrict__ vt)
{
    const int N = 2304, K = 768;
    __shared__ __half sA[128*72];
    __shared__ __half sB[128*72];
    int tid = threadIdx.x;
    int m0 = blockIdx.y * 128, n0 = blockIdx.x * 128;
    int lane = tid & 31, warp = tid >> 5;
    int wm = (warp >> 2) * 64, wn = (warp & 3) * 32;
    int g = lane >> 2, tq = lane & 3;
    int ar = tid >> 1, ac = (tid & 1) * 32;

    const uint32_t* Au = (const uint32_t*)sA;
    const uint32_t* Bu = (const uint32_t*)sB;

    float acc[4][4][4];
#pragma unroll
    for (int mt=0;mt<4;mt++)
#pragma unroll
        for (int nt=0;nt<4;nt++)
#pragma unroll
            for (int c=0;c<4;c++) acc[mt][nt][c]=0.f;

    for (int k0 = 0; k0 < K; k0 += 64){
        const uint4* ap = (const uint4*)&A[(size_t)(m0+ar)*K + k0 + ac];
        uint4* asp = (uint4*)&sA[ar*72 + ac];
        asp[0]=ap[0]; asp[1]=ap[1]; asp[2]=ap[2]; asp[3]=ap[3];
        const uint4* bp = (const uint4*)&Bt[(size_t)(n0+ar)*K + k0 + ac];
        uint4* bsp = (uint4*)&sB[ar*72 + ac];
        bsp[0]=bp[0]; bsp[1]=bp[1]; bsp[2]=bp[2]; bsp[3]=bp[3];
        __syncthreads();
#pragma unroll
        for (int ks = 0; ks < 4; ks++){
            int kh = ks*8;
            uint32_t a[4][4], b[4][2];
#pragma unroll
            for (int mt = 0; mt < 4; mt++){
                int rm = wm + mt*16 + g;
                a[mt][0] = Au[rm*36 + kh + tq];
                a[mt][1] = Au[(rm+8)*36 + kh + tq];
                a[mt][2] = Au[rm*36 + kh + tq + 4];
                a[mt][3] = Au[(rm+8)*36 + kh + tq + 4];
            }
#pragma unroll
            for (int nt = 0; nt < 4; nt++){
                int n = wn + nt*8 + g;
                b[nt][0] = Bu[n*36 + kh + tq];
                b[nt][1] = Bu[n*36 + kh + tq + 4];
            }
#pragma unroll
            for (int mt = 0; mt < 4; mt++)
#pragma unroll
                for (int nt = 0; nt < 4; nt++)
                    mma_f16(acc[mt][nt], a[mt], b[nt]);
        }
        __syncthreads();
    }
#pragma unroll
    for (int mt = 0; mt < 4; mt++){
#pragma unroll
        for (int rh = 0; rh < 2; rh++){
            int m = m0 + wm + mt*16 + g + rh*8;
            int b = m >> 8, l = m & 255;
#pragma unroll
            for (int nt = 0; nt < 4; nt++){
#pragma unroll
                for (int e = 0; e < 2; e++){
                    int n = n0 + wn + nt*8 + 2*tq + e;
                    float v = acc[mt][nt][rh*2+e] + bias[n];
                    int seg = n / 768;
                    int nn = n - seg*768;
                    int dd = nn >> 5, h = nn & 31;
                    if (seg == 0){
                        qt[(((size_t)(b*32 + h))*256 + l)*24 + dd] = v * SCALE_Q;
                    } else if (seg == 1){
                        kt[(((size_t)(b*32 + h))*256 + l)*24 + dd] = v;
                    } else {
                        vt[(((size_t)(b*32 + h))*24 + dd)*256 + l] = v;
                    }
                }
            }
        }
    }
}

// ---------------- QK kernel ----------------
__global__ __launch_bounds__(256) void qk_kernel(
    const float* __restrict__ qt, const float* __restrict__ kt,
    float* __restrict__ qk)
{
    int bh = blockIdx.y;
    int l0 = (blockIdx.x >> 1) * 128;
    int m0 = (blockIdx.x & 1) * 128;
    __shared__ float sQ[24*132];
    __shared__ float sK[24*132];
    int tid = threadIdx.x;
    const float* qb = qt + (size_t)bh*6144 + (size_t)l0*24;
    const float* kb = kt + (size_t)bh*6144 + (size_t)m0*24;
    for (int i = tid; i < 3072; i += 256){
        int r = i / 24, d = i - r*24;
        sQ[d*132 + r] = qb[i];
        sK[d*132 + r] = kb[i];
    }
    __syncthreads();
    int tx = tid & 15, ty = tid >> 4;
    float acc[8][8];
#pragma unroll
    for (int i = 0; i < 8; i++)
#pragma unroll
        for (int j = 0; j < 8; j++) acc[i][j] = 0.f;
#pragma unroll 6
    for (int k = 0; k < 24; k++){
        float4 a0 = *(const float4*)&sQ[k*132 + ty*8];
        float4 a1 = *(const float4*)&sQ[k*132 + ty*8 + 4];
        float4 b0 = *(const float4*)&sK[k*132 + tx*8];
        float4 b1 = *(const float4*)&sK[k*132 + tx*8 + 4];
        float a[8] = {a0.x,a0.y,a0.z,a0.w,a1.x,a1.y,a1.z,a1.w};
        float b[8] = {b0.x,b0.y,b0.z,b0.w,b1.x,b1.y,b1.z,b1.w};
#pragma unroll
        for (int i = 0; i < 8; i++)
#pragma unroll
            for (int j = 0; j < 8; j++) acc[i][j] += a[i]*b[j];
    }
    float* out = qk + (size_t)bh*65536 + (size_t)l0*256 + m0;
#pragma unroll
    for (int i = 0; i < 8; i++){
        float* orow = out + (size_t)(ty*8 + i)*256 + tx*8;
        *(float4*)orow     = make_float4(acc[i][0],acc[i][1],acc[i][2],acc[i][3]);
        *(float4*)(orow+4) = make_float4(acc[i][4],acc[i][5],acc[i][6],acc[i][7]);
    }
}

// ---------------- fused edge kernel: per (row, half) CTA, 256 threads, 2 CTAs/SM ----------------
// smem (floats):
//   sPar 512 @0 ; sMask 128 @512 ;
//   weights fp16 @640 (8192 f) -> ends 8832 ;
//   sX16 [128][72] halves (4608 f) @8832 -> ends 13440 ;
//   sRed [128][4] float2 (1024 f) @13440 -> ends 14464 ;
//   sE [128][68] f32 (8704 f) @14464 -> ends 23168
#define EK_FLOATS 23168
__global__ __launch_bounds__(256, 2) void edge_attn_kernel(
    const float* __restrict__ e_in, const float* __restrict__ mask,
    const float* __restrict__ qk,         // raw QK, read-only
    const __half* __restrict__ ew16,
    const float* __restrict__ b_eg, const float* __restrict__ b_oe,
    const float* __restrict__ eln_g, const float* __restrict__ eln_b,
    const float* __restrict__ ffn_g, const float* __restrict__ ffn_b,
    const float* __restrict__ eb1, const float* __restrict__ eb2,
    float* __restrict__ e_out, __half* __restrict__ gate16,
    __half* __restrict__ logit16)
{
    extern __shared__ float sm[];
    float* sPar  = sm;
    float* sMask = sm + 512;
    __half* sW16 = (__half*)(sm + 640);
    __half* Weg_t = sW16;           // [64][72]
    __half* W1_t  = sW16 + 4608;    // [64][72]
    __half* W2_t  = sW16 + 9216;    // [64][72]
    __half* Woe_t = sW16 + 13824;   // [64][40]
    __half* sX16  = (__half*)(sm + 8832);   // [128][72] halves
    float*  sRed  = sm + 13440;             // [128][4] float2
    float*  sE    = sm + 14464;             // [128][68] f32

    int tid  = threadIdx.x;
    int lane = tid & 31;
    int g    = lane >> 2;
    int tq   = lane & 3;
    int wg8  = tid >> 5;                 // 0..7
    int wm   = (wg8 >> 2) * 64;
    int wn   = (wg8 & 3) * 16;
    int bid  = blockIdx.x;
    int row  = bid >> 1;
    int grp  = bid & 1;
    int b    = row >> 8;
    int l    = row & 255;
    int m0g  = grp * 128;

    // ---- stage packed weights (uint4 copy), params, mask ----
    {
        const uint4* src = (const uint4*)ew16;
        uint4* dst = (uint4*)sW16;
#pragma unroll
        for (int i = 0; i < 8; i++)
            dst[tid + i*256] = src[tid + i*256];
    }
    if (tid < 64){
        sPar[tid]     = b_eg[tid];
        sPar[64+tid]  = b_oe[tid];
        sPar[128+tid] = eb1[tid];
        sPar[192+tid] = eb2[tid];
        sPar[256+tid] = eln_g[tid];
        sPar[320+tid] = eln_b[tid];
        sPar[384+tid] = ffn_g[tid];
        sPar[448+tid] = ffn_b[tid];
    }
    if (tid < 128) sMask[tid] = mask[(size_t)row*256 + m0g + tid];
    __syncthreads();

    // ---- LN1: thread-mapped, store fp16 X[m][k] + raw e to sE ----
    {
        int ty = tid >> 4, tx = tid & 15;
        float lg0 = sPar[256+tx*4], lg1 = sPar[257+tx*4], lg2 = sPar[258+tx*4], lg3 = sPar[259+tx*4];
        float lb0 = sPar[320+tx*4], lb1 = sPar[321+tx*4], lb2 = sPar[322+tx*4], lb3 = sPar[323+tx*4];
        __half2* xp = (__half2*)sX16;
#pragma unroll
        for (int i = 0; i < 8; i++){
            int r = ty*8 + i;
            float4 e4 = *(const float4*)&e_in[((size_t)row*256 + m0g + r)*64 + tx*4];
            *(float4*)&sE[r*68 + tx*4] = e4;
            float s = sum16(e4.x + e4.y + e4.z + e4.w);
            float mean = s * (1.f/64.f);
            float d0=e4.x-mean, d1=e4.y-mean, d2=e4.z-mean, d3=e4.w-mean;
            float q = sum16(d0*d0 + d1*d1 + d2*d2 + d3*d3);
            float rs = rsqrtf(q * (1.f/64.f) + 1e-5f);
            xp[r*36 + tx*2    ] = __floats2half2_rn(d0*rs*lg0 + lb0, d1*rs*lg1 + lb1);
            xp[r*36 + tx*2 + 1] = __floats2half2_rn(d2*rs*lg2 + lb2, d3*rs*lg3 + lb3);
        }
    }
    __syncthreads();

    float acc[4][2][4];
    const uint32_t* Xu = (const uint32_t*)sX16;

    // ---- GEMM1: EG = X @ W_eg (K=64) ----
#pragma unroll
    for (int mt=0;mt<4;mt++)
#pragma unroll
        for (int nt=0;nt<2;nt++)
#pragma unroll
            for (int c=0;c<4;c++) acc[mt][nt][c]=0.f;
    warp_gemm_f16<4>(Xu, 36, (const uint32_t*)Weg_t, 36, wm, wn, g, tq, acc);
    __syncthreads();   // all X reads done before H overwrites sX16

    size_t qkbase = ((size_t)(b*32))*65536 + (size_t)l*256 + m0g;
    if (wn < 32){
        // E columns -> H_hat: fp16 unmasked into sX16 (for e_att) + masked fp16 logits to gmem
        __half2* hp = (__half2*)sX16;
#pragma unroll
        for (int mt=0;mt<4;mt++)
#pragma unroll
            for (int nt=0;nt<2;nt++){
                int nc = wn + nt*8 + 2*tq;
#pragma unroll
                for (int rh=0;rh<2;rh++){
                    int m = wm + mt*16 + g + rh*8;
                    size_t qi = qkbase + (size_t)nc*65536 + m;
                    float v0 = acc[mt][nt][rh*2+0] + sPar[nc]   + qk[qi];
                    float v1 = acc[mt][nt][rh*2+1] + sPar[nc+1] + qk[qi + 65536];
                    float mk = sMask[m];
                    logit16[qi]         = __float2half(v0 + mk);
                    logit16[qi + 65536] = __float2half(v1 + mk);
                    hp[m*36 + (nc>>1)] = __floats2half2_rn(v0, v1);
                }
            }
    } else {
        // G columns -> gates (fp16 to gmem)
#pragma unroll
        for (int mt=0;mt<4;mt++)
#pragma unroll
            for (int nt=0;nt<2;nt++){
                int nc = wn + nt*8 + 2*tq;
                int h0 = nc - 32;
#pragma unroll
                for (int rh=0;rh<2;rh++){
                    int m = wm + mt*16 + g + rh*8;
                    float mk = sMask[m];
                    size_t gi = qkbase + (size_t)h0*65536 + m;
                    gate16[gi]         = __float2half(sigmoidf_(acc[mt][nt][rh*2+0] + sPar[nc]   + mk));
                    gate16[gi + 65536] = __float2half(sigmoidf_(acc[mt][nt][rh*2+1] + sPar[nc+1] + mk));
                }
            }
    }
    __syncthreads();

    // ---- GEMM2: e_att = H_hat @ W_oe (K=32, A = H fp16 in sX16) ; r = e + e_att + b_oe ----
#pragma unroll
    for (int mt=0;mt<4;mt++)
#pragma unroll
        for (int nt=0;nt<2;nt++)
#pragma unroll
            for (int c=0;c<4;c++) acc[mt][nt][c]=0.f;
    warp_gemm_f16<2>(Xu, 36, (const uint32_t*)Woe_t, 20, wm, wn, g, tq, acc);

    float r_[4][2][4];
#pragma unroll
    for (int mt=0;mt<4;mt++)
#pragma unroll
        for (int nt=0;nt<2;nt++){
            int nc = wn + nt*8 + 2*tq;
            int m  = wm + mt*16 + g;
            const float* ep = &sE[m*68 + nc];
            float2 ea = *(const float2*)ep;
            float2 eb = *(const float2*)(ep + 8*68);
            r_[mt][nt][0] = ea.x + acc[mt][nt][0] + sPar[64+nc];
            r_[mt][nt][1] = ea.y + acc[mt][nt][1] + sPar[64+nc+1];
            r_[mt][nt][2] = eb.x + acc[mt][nt][2] + sPar[64+nc];
            r_[mt][nt][3] = eb.y + acc[mt][nt][3] + sPar[64+nc+1];
        }

    // ---- LN2 on r (fragments): quad-reduce + cross-warp smem reduce ----
    {
        float2* rp = (float2*)sRed;
#pragma unroll
        for (int mt=0;mt<4;mt++)
#pragma unroll
            for (int rh=0;rh<2;rh++){
                float ps = r_[mt][0][rh*2] + r_[mt][0][rh*2+1]
                         + r_[mt][1][rh*2] + r_[mt][1][rh*2+1];
                float pq = r_[mt][0][rh*2]*r_[mt][0][rh*2] + r_[mt][0][rh*2+1]*r_[mt][0][rh*2+1]
                         + r_[mt][1][rh*2]*r_[mt][1][rh*2] + r_[mt][1][rh*2+1]*r_[mt][1][rh*2+1];
                ps += __shfl_xor_sync(FULLMASK, ps, 1);
                ps += __shfl_xor_sync(FULLMASK, ps, 2);
                pq += __shfl_xor_sync(FULLMASK, pq, 1);
                pq += __shfl_xor_sync(FULLMASK, pq, 2);
                if (tq == 0){
                    int m = wm + mt*16 + g + rh*8;
                    rp[m*4 + (wg8 & 3)] = make_float2(ps, pq);
                }
            }
    }
    __syncthreads();
    {
        __half2* xp = (__half2*)sX16;
        const float2* rp = (const float2*)sRed;
#pragma unroll
        for (int mt=0;mt<4;mt++)
#pragma unroll
            for (int rh=0;rh<2;rh++){
                int m = wm + mt*16 + g + rh*8;
                float2 p0 = rp[m*4+0], p1 = rp[m*4+1], p2 = rp[m*4+2], p3 = rp[m*4+3];
                float mu = (p0.x+p1.x+p2.x+p3.x) * (1.f/64.f);
                float vq = (p0.y+p1.y+p2.y+p3.y) * (1.f/64.f) - mu*mu;
                float rs = rsqrtf(vq + 1e-5f);
#pragma unroll
                for (int nt=0;nt<2;nt++){
                    int nc = wn + nt*8 + 2*tq;
                    float v0 = (r_[mt][nt][rh*2+0]-mu)*rs*sPar[384+nc]   + sPar[448+nc];
                    float v1 = (r_[mt][nt][rh*2+1]-mu)*rs*sPar[384+nc+1] + sPar[448+nc+1];
                    xp[m*36 + (nc>>1)] = __floats2half2_rn(v0, v1);
                }
            }
    }
    __syncthreads();

    // ---- GEMM3: T = gelu(X2 @ eW1 + b1) ----
#pragma unroll
    for (int mt=0;mt<4;mt++)
#pragma unroll
        for (int nt=0;nt<2;nt++)
#pragma unroll
            for (int c=0;c<4;c++) acc[mt][nt][c]=0.f;
    warp_gemm_f16<4>(Xu, 36, (const uint32_t*)W1_t, 36, wm, wn, g, tq, acc);
    __syncthreads();
    {
        __half2* xp = (__half2*)sX16;
#pragma unroll
        for (int mt=0;mt<4;mt++)
#pragma unroll
            for (int nt=0;nt<2;nt++){
                int nc = wn + nt*8 + 2*tq;
#pragma unroll
                for (int rh=0;rh<2;rh++){
                    int m = wm + mt*16 + g + rh*8;
                    float v0 = gelu_tanh(acc[mt][nt][rh*2+0] + sPar[128+nc]);
                    float v1 = gelu_tanh(acc[mt][nt][rh*2+1] + sPar[128+nc+1]);
                    xp[m*36 + (nc>>1)] = __floats2half2_rn(v0, v1);
                }
            }
    }
    __syncthreads();

    // ---- GEMM4: O = T @ eW2 + b2 ; e_out = r + O ----
#pragma unroll
    for (int mt=0;mt<4;mt++)
#pragma unroll
        for (int nt=0;nt<2;nt++)
#pragma unroll
            for (int c=0;c<4;c++) acc[mt][nt][c]=0.f;
    warp_gemm_f16<4>(Xu, 36, (const uint32_t*)W2_t, 36, wm, wn, g, tq, acc);
#pragma unroll
    for (int mt=0;mt<4;mt++)
#pragma unroll
        for (int nt=0;nt<2;nt++){
            int nc = wn + nt*8 + 2*tq;
            int m  = wm + mt*16 + g;
            float* op = &e_out[((size_t)row*256 + m0g + m)*64 + nc];
            *(float2*)op = make_float2(
                r_[mt][nt][0] + acc[mt][nt][0] + sPar[192+nc],
                r_[mt][nt][1] + acc[mt][nt][1] + sPar[192+nc+1]);
            *(float2*)(op + 8*64) = make_float2(
                r_[mt][nt][2] + acc[mt][nt][2] + sPar[192+nc],
                r_[mt][nt][3] + acc[mt][nt][3] + sPar[192+nc+1]);
        }
}

// ---------------- softmax + AV kernel: per (bh, 32-l tile) ----------------
// logits arrive pre-masked fp16.
// smem: sL [32][260] f32 (8320) ; sV [24][260] f32 (6240) ; sG [32][264]h (4224 f)
#define AV_FLOATS (8320 + 6240 + 4224)
__global__ __launch_bounds__(256) void av_softmax_kernel(
    const __half* __restrict__ logit16, const __half* __restrict__ gate16,
    const float* __restrict__ vt, __half* __restrict__ vatt)
{
    extern __shared__ float sm[];
    float* sL = sm;                    // [32][260]
    float* sV = sm + 8320;             // [24][260]
    __half* sG = (__half*)(sm + 14560);// [32][264]
    int bh = blockIdx.y;
    int l0 = blockIdx.x * 32;
    int b = bh >> 5, h = bh & 31;
    int tid = threadIdx.x;

    const __half* lb = logit16 + (size_t)bh*65536 + (size_t)l0*256;
    for (int i = tid; i < 1024; i += 256){
        int ll = i >> 5, m = (i & 31) * 8;
        uint4 raw = *(const uint4*)&lb[(size_t)ll*256 + m];
        const __half2* hp = (const __half2*)&raw;
#pragma unroll
        for (int e = 0; e < 4; e++){
            float2 f = __half22float2(hp[e]);
            sL[ll*260 + m + 2*e    ] = f.x;
            sL[ll*260 + m + 2*e + 1] = f.y;
        }
    }
    const __half* gb = gate16 + (size_t)bh*65536 + (size_t)l0*256;
    for (int i = tid; i < 1024; i += 256){
        int ll = i >> 5, m = (i & 31) * 8;
        *(uint4*)&sG[ll*264 + m] = *(const uint4*)&gb[(size_t)ll*256 + m];
    }
    // V d-major: coalesced float4 copy into [24][260]
    const float* vb = vt + (size_t)bh*6144;
    for (int i = tid; i < 1536; i += 256){
        int dd = i >> 6, m = (i & 63) * 4;
        *(float4*)&sV[dd*260 + m] = *(const float4*)&vb[dd*256 + m];
    }
    __syncthreads();

    int w = tid >> 5, lane = tid & 31;
    // softmax + gate fold: warp w -> rows w*4..w*4+3
#pragma unroll
    for (int rr = 0; rr < 4; rr++){
        int row = w*4 + rr;
        float p[8], gg[8];
        float mx = -3.4e38f;
#pragma unroll
        for (int j = 0; j < 8; j++){
            p[j] = sL[row*260 + j*32 + lane];
            mx = fmaxf(mx, p[j]);
        }
        mx = warpMax(mx);
        float s = 0.f, gs = 0.f;
#pragma unroll
        for (int j = 0; j < 8; j++){
            p[j] = __expf(p[j] - mx);
            s += p[j];
            gg[j] = __half2float(sG[row*264 + j*32 + lane]);
            gs += gg[j];
        }
        s = warpSum(s); gs = warpSum(gs);
        float c = (1.f / s) * log1pf(gs);
#pragma unroll
        for (int j = 0; j < 8; j++)
            sL[row*260 + j*32 + lane] = p[j] * gg[j] * c;
    }
    __syncthreads();

    // AV: warp w -> rows w*4..+3, lanes < 24 = dims
    if (lane < 24){
        const float* vr = &sV[lane*260];
#pragma unroll
        for (int j = 0; j < 4; j++){
            int ll = w*4 + j;
            const float* ar = &sL[ll*260];
            float acc = 0.f;
#pragma unroll 8
            for (int m = 0; m < 256; m += 4){
                float4 a = *(const float4*)&ar[m];
                float4 v = *(const float4*)&vr[m];
                acc += a.x*v.x + a.y*v.y + a.z*v.z + a.w*v.w;
            }
            vatt[(size_t)(b*256 + l0 + ll)*768 + lane*32 + h] = __float2half(acc);
        }
    }
}

// ---------------- host ----------------
extern "C" void kernel_launch(void* const* d_in, const int* in_sizes, int n_in,
                              void* d_out, int out_size)
{
    const float* h_in   = (const float*)d_in[0];
    const float* e_in   = (const float*)d_in[1];
    const float* mask   = (const float*)d_in[2];
    const float* ln_h_g = (const float*)d_in[3];
    const float* ln_h_b = (const float*)d_in[4];
    const float* ln_e_g = (const float*)d_in[5];
    const float* ln_e_b = (const float*)d_in[6];
    const float* W_qkv  = (const float*)d_in[7];
    const float* b_qkv  = (const float*)d_in[8];
    const float* W_eg   = (const float*)d_in[9];
    const float* b_eg   = (const float*)d_in[10];
    const float* W_oh   = (const float*)d_in[11];
    const float* b_oh   = (const float*)d_in[12];
    const float* W_oe   = (const float*)d_in[13];
    const float* b_oe   = (const float*)d_in[14];
    const float* nffn_g = (const float*)d_in[15];
    const float* nffn_b = (const float*)d_in[16];
    const float* nW1    = (const float*)d_in[17];
    const float* nb1    = (const float*)d_in[18];
    const float* nW2    = (const float*)d_in[19];
    const float* nb2    = (const float*)d_in[20];
    const float* effn_g = (const float*)d_in[21];
    const float* effn_b = (const float*)d_in[22];
    const float* eW1    = (const float*)d_in[23];
    const float* eb1    = (const float*)d_in[24];
    const float* eW2    = (const float*)d_in[25];
    const float* eb2    = (const float*)d_in[26];

    float* out_h = (float*)d_out;
    float* out_e = out_h + (size_t)ROWS * DD_;

    float *qt, *kt, *vt, *qk, *hmid;
    __half *logit16, *gate16, *hln16, *hln216, *t16, *vatt16;
    __half *wqkv16, *woh16, *nw116, *nw216, *ew16;
    cudaGetSymbolAddress((void**)&qt,      g_qt);
    cudaGetSymbolAddress((void**)&kt,      g_kt);
    cudaGetSymbolAddress((void**)&vt,      g_vt);
    cudaGetSymbolAddress((void**)&qk,      g_qk);
    cudaGetSymbolAddress((void**)&logit16, g_logit16);
    cudaGetSymbolAddress((void**)&gate16,  g_gate16);
    cudaGetSymbolAddress((void**)&hmid,    g_hmid);
    cudaGetSymbolAddress((void**)&hln16,   g_hln16);
    cudaGetSymbolAddress((void**)&hln216,  g_hln216);
    cudaGetSymbolAddress((void**)&t16,     g_t16);
    cudaGetSymbolAddress((void**)&vatt16,  g_vatt16);
    cudaGetSymbolAddress((void**)&wqkv16,  g_wqkv16);
    cudaGetSymbolAddress((void**)&woh16,   g_woh16);
    cudaGetSymbolAddress((void**)&nw116,   g_nw116);
    cudaGetSymbolAddress((void**)&nw216,   g_nw216);
    cudaGetSymbolAddress((void**)&ew16,    g_ew16);

    cudaFuncSetAttribute(edge_attn_kernel,
                         cudaFuncAttributeMaxDynamicSharedMemorySize,
                         EK_FLOATS * 4);
    cudaFuncSetAttribute(av_softmax_kernel,
                         cudaFuncAttributeMaxDynamicSharedMemorySize,
                         AV_FLOATS * 4);

    // 0) all weight prep in one launch
    weight_prep<<<dim3(72, 24, 5), 256>>>(
        W_qkv, W_oh, nW1, nW2, W_eg, eW1, eW2, W_oe,
        wqkv16, woh16, nw116, nw216, ew16);

    // 1) h layernorm -> fp16
    ln768_kernel<<<ROWS, 256>>>(h_in, ln_h_g, ln_h_b, hln16);

    // 2) QKV GEMM (fp16 mma) with transposed scatter (V d-major)
    gemm_qkv_f16<<<dim3(18, 16), 256>>>(hln16, wqkv16, b_qkv, qt, kt, vt);

    // 3) QK = Q K^T per head (into qk buffer)
    qk_kernel<<<dim3(4, 256), 256>>>(qt, kt, qk);

    // 4) edge attention + edge FFN: masked fp16 logits -> logit16, gates -> gate16
    edge_attn_kernel<<<2*ROWS, 256, EK_FLOATS * 4>>>(
        e_in, mask, qk, ew16,
        b_eg, b_oe,
        ln_e_g, ln_e_b, effn_g, effn_b,
        eb1, eb2,
        out_e, gate16, logit16);

    // 5) softmax + V_att = A' @ V -> fp16
    av_softmax_kernel<<<dim3(8, 256), 256, AV_FLOATS * 4>>>(
        logit16, gate16, vt, vatt16);

    // 6) h_mid = h + V_att @ W_oh + b_oh (fp16 mma)
    gemm_f16k<0,0><<<dim3(6, 16), 256>>>(vatt16, woh16, b_oh, h_in,
                                         hmid, nullptr, ROWS, DD_, DD_);

    // 7) node FFN (fp16 mma)
    ln768_kernel<<<ROWS, 256>>>(hmid, nffn_g, nffn_b, hln216);
    gemm_f16k<1,1><<<dim3(6, 16), 256>>>(hln216, nw116, nb1, nullptr,
                                         nullptr, t16, ROWS, DD_, DD_);
    gemm_f16k<0,0><<<dim3(6, 16), 256>>>(t16, nw216, nb2, hmid,
                                         out_h, nullptr, ROWS, DD_, DD_);
}

// round 17
// speedup vs baseline: 3.1911x; 1.0450x over previous
#include <cuda_runtime.h>
#include <cuda_fp16.h>
#include <cstddef>
#include <cstdint>

// ---------------- problem constants ----------------
#define BB 8
#define NN 256
#define DD_ 768
#define ROWS (BB*NN)     // 2048
#define SCALE_Q 0.20412414523193154f   // 24^-0.5
#define FULLMASK 0xffffffffu

// ---------------- scratch (device globals; no allocation) ----------------
__device__ __half g_qt16[8*32*256*32];     // fp16, 24 dims padded to 32
__device__ __half g_kt16[8*32*256*32];
__device__ float  g_vt  [8*32*24*256];     // d-major: [bh][24][256]
__device__ float  g_qk  [8*32*256*256];    // raw QK fp32
__device__ __half g_logit16[8*32*256*256]; // masked logits (softmax input)
__device__ __half g_gate16 [8*32*256*256];
__device__ float  g_hmid[ROWS*DD_];
__device__ __half g_hln16 [ROWS*DD_];
__device__ __half g_hln216[ROWS*DD_];
__device__ __half g_t16   [ROWS*DD_];
__device__ __half g_vatt16[ROWS*DD_];
__device__ __half g_wqkv16[2304*768];
__device__ __half g_woh16 [768*768];
__device__ __half g_nw116 [768*768];
__device__ __half g_nw216 [768*768];
__device__ __half g_ew16  [16384];         // packed edge weights (smem image)

// ---------------- helpers ----------------
__device__ __forceinline__ float warpSum(float v){
#pragma unroll
    for (int o = 16; o; o >>= 1) v += __shfl_xor_sync(FULLMASK, v, o);
    return v;
}
__device__ __forceinline__ float warpMax(float v){
#pragma unroll
    for (int o = 16; o; o >>= 1) v = fmaxf(v, __shfl_xor_sync(FULLMASK, v, o));
    return v;
}
__device__ __forceinline__ float sum16(float v){
#pragma unroll
    for (int o = 8; o; o >>= 1) v += __shfl_xor_sync(FULLMASK, v, o);
    return v;
}
__device__ __forceinline__ float gelu_tanh(float x){
    float y = 0.7978845608028654f * (x + 0.044715f * x * x * x);
    y = fminf(fmaxf(y, -30.f), 30.f);
    float t = __expf(2.f * y);
    float th = (t - 1.f) / (t + 1.f);
    return 0.5f * x * (1.f + th);
}
__device__ __forceinline__ float sigmoidf_(float x){
    return 1.f / (1.f + __expf(-x));
}
__device__ __forceinline__ void mma_f16(float* c, const uint32_t* a, const uint32_t* b){
    asm volatile("mma.sync.aligned.m16n8k16.row.col.f32.f16.f16.f32 "
        "{%0,%1,%2,%3}, {%4,%5,%6,%7}, {%8,%9}, {%0,%1,%2,%3};"
        : "+f"(c[0]), "+f"(c[1]), "+f"(c[2]), "+f"(c[3])
        : "r"(a[0]), "r"(a[1]), "r"(a[2]), "r"(a[3]), "r"(b[0]), "r"(b[1]));
}

// fp16 mma over smem: A [m][k] (strideA2 half2), B [n][k] (strideB2 half2).
template<int KS>
__device__ __forceinline__ void warp_gemm_f16(
    const uint32_t* __restrict__ Xu, int strideA2,
    const uint32_t* __restrict__ Wu, int strideB2,
    int wm, int wn, int g, int tq, float acc[4][2][4])
{
#pragma unroll
    for (int ks = 0; ks < KS; ks++){
        int kh = ks*8;
        uint32_t a[4][4], b[2][2];
#pragma unroll
        for (int mt = 0; mt < 4; mt++){
            int rm = wm + mt*16 + g;
            a[mt][0] = Xu[rm*strideA2 + kh + tq];
            a[mt][1] = Xu[(rm+8)*strideA2 + kh + tq];
            a[mt][2] = Xu[rm*strideA2 + kh + tq + 4];
            a[mt][3] = Xu[(rm+8)*strideA2 + kh + tq + 4];
        }
#pragma unroll
        for (int nt = 0; nt < 2; nt++){
            int n = wn + nt*8 + g;
            b[nt][0] = Wu[n*strideB2 + kh + tq];
            b[nt][1] = Wu[n*strideB2 + kh + tq + 4];
        }
#pragma unroll
        for (int mt = 0; mt < 4; mt++)
#pragma unroll
            for (int nt = 0; nt < 2; nt++)
                mma_f16(acc[mt][nt], a[mt], b[nt]);
    }
}

// ---------------- merged weight prep + padding zero: one launch, z-dispatch ----------------
// z=0: W_qkv transpose ; z=1..3: W_oh/nW1/nW2 ; z=4: edge pack ; z=5: zero qt16/kt16
__global__ __launch_bounds__(256) void weight_prep(
    const float* __restrict__ W_qkv, const float* __restrict__ W_oh,
    const float* __restrict__ nW1,  const float* __restrict__ nW2,
    const float* __restrict__ W_eg, const float* __restrict__ eW1,
    const float* __restrict__ eW2,  const float* __restrict__ W_oe,
    __half* __restrict__ wqkv16, __half* __restrict__ woh16,
    __half* __restrict__ nw116,  __half* __restrict__ nw216,
    __half* __restrict__ ew,
    __half* __restrict__ qt16, __half* __restrict__ kt16)
{
    int z = blockIdx.z;
    if (z == 5){
        // zero Q/K fp16 buffers (padding lanes stay 0 after scatter)
        size_t idx = ((size_t)blockIdx.y*72 + blockIdx.x)*256 + threadIdx.x;
        const size_t N4 = (size_t)8*32*256*32/8;   // 262144 uint4 per buffer
        uint4 z4 = make_uint4(0,0,0,0);
        if (idx < N4){
            ((uint4*)qt16)[idx] = z4;
            ((uint4*)kt16)[idx] = z4;
        }
        return;
    }
    if (z == 4){
        int i = blockIdx.x*256 + threadIdx.x;
        if (blockIdx.y != 0) return;
        if (i < 4096){
            int k = i >> 6, n = i & 63;
            ew[n*72 + k]         = __float2half(W_eg[i]);
            ew[4608 + n*72 + k]  = __float2half(eW1[i]);
            ew[9216 + n*72 + k]  = __float2half(eW2[i]);
        }
        if (i < 2048){
            int k = i >> 6, n = i & 63;
            ew[13824 + n*40 + k] = __float2half(W_oe[i]);
        }
        return;
    }
    const float* W; __half* Wt; int K = 768, N;
    if (z == 0){ W = W_qkv; Wt = wqkv16; N = 2304; }
    else if (z == 1){ W = W_oh; Wt = woh16; N = 768; }
    else if (z == 2){ W = nW1; Wt = nw116; N = 768; }
    else { W = nW2; Wt = nw216; N = 768; }
    int n0 = blockIdx.x*32;
    if (n0 >= N) return;
    int k0 = blockIdx.y*32;
    __shared__ float tile[32][33];
    int tx = threadIdx.x & 31, ty = threadIdx.x >> 5;
    for (int i = ty; i < 32; i += 8)
        tile[i][tx] = W[(size_t)(k0+i)*N + n0 + tx];
    __syncthreads();
    for (int i = ty; i < 32; i += 8)
        Wt[(size_t)(n0+i)*K + k0 + tx] = __float2half(tile[tx][i]);
}

// ---------------- LayerNorm over 768, fp16 out ----------------
__global__ __launch_bounds__(256) void ln768_kernel(
    const float* __restrict__ x, const float* __restrict__ g,
    const float* __restrict__ b, __half* __restrict__ y)
{
    int row = blockIdx.x;
    int tid = threadIdx.x;
    const float* xr = x + (size_t)row * DD_;
    __half*      yr = y + (size_t)row * DD_;
    float v0 = xr[tid], v1 = xr[tid+256], v2 = xr[tid+512];
    __shared__ float red[8];
    float s = warpSum(v0 + v1 + v2);
    if ((tid & 31) == 0) red[tid >> 5] = s;
    __syncthreads();
    float tot = 0.f;
#pragma unroll
    for (int i = 0; i < 8; i++) tot += red[i];
    __syncthreads();
    float mean = tot * (1.f/768.f);
    float d0 = v0-mean, d1 = v1-mean, d2 = v2-mean;
    float q = warpSum(d0*d0 + d1*d1 + d2*d2);
    if ((tid & 31) == 0) red[tid >> 5] = q;
    __syncthreads();
    float vt = 0.f;
#pragma unroll
    for (int i = 0; i < 8; i++) vt += red[i];
    float rstd = rsqrtf(vt * (1.f/768.f) + 1e-5f);
    yr[tid]     = __float2half(d0*rstd*g[tid]     + b[tid]);
    yr[tid+256] = __float2half(d1*rstd*g[tid+256] + b[tid+256]);
    yr[tid+512] = __float2half(d2*rstd*g[tid+512] + b[tid+512]);
}

// ---------------- fp16 tensor-core GEMM, CTA 128x128, warp 64x32, BK=64 ----------------
template<int EPI, int OUTH>
__global__ __launch_bounds__(256) void gemm_f16k(
    const __half* __restrict__ A, const __half* __restrict__ Bt,
    const float* __restrict__ bias, const float* __restrict__ R,
    float* __restrict__ C, __half* __restrict__ Ch, int M, int N, int K)
{
    __shared__ __half sA[128*72];
    __shared__ __half sB[128*72];
    int tid = threadIdx.x;
    int m0 = blockIdx.y * 128, n0 = blockIdx.x * 128;
    int lane = tid & 31, warp = tid >> 5;
    int wm = (warp >> 2) * 64, wn = (warp & 3) * 32;
    int g = lane >> 2, tq = lane & 3;
    int ar = tid >> 1, ac = (tid & 1) * 32;

    const uint32_t* Au = (const uint32_t*)sA;
    const uint32_t* Bu = (const uint32_t*)sB;

    float acc[4][4][4];
#pragma unroll
    for (int mt=0;mt<4;mt++)
#pragma unroll
        for (int nt=0;nt<4;nt++)
#pragma unroll
            for (int c=0;c<4;c++) acc[mt][nt][c]=0.f;

    for (int k0 = 0; k0 < K; k0 += 64){
        const uint4* ap = (const uint4*)&A[(size_t)(m0+ar)*K + k0 + ac];
        uint4* asp = (uint4*)&sA[ar*72 + ac];
        asp[0]=ap[0]; asp[1]=ap[1]; asp[2]=ap[2]; asp[3]=ap[3];
        const uint4* bp = (const uint4*)&Bt[(size_t)(n0+ar)*K + k0 + ac];
        uint4* bsp = (uint4*)&sB[ar*72 + ac];
        bsp[0]=bp[0]; bsp[1]=bp[1]; bsp[2]=bp[2]; bsp[3]=bp[3];
        __syncthreads();
#pragma unroll
        for (int ks = 0; ks < 4; ks++){
            int kh = ks*8;
            uint32_t a[4][4], b[4][2];
#pragma unroll
            for (int mt = 0; mt < 4; mt++){
                int rm = wm + mt*16 + g;
                a[mt][0] = Au[rm*36 + kh + tq];
                a[mt][1] = Au[(rm+8)*36 + kh + tq];
                a[mt][2] = Au[rm*36 + kh + tq + 4];
                a[mt][3] = Au[(rm+8)*36 + kh + tq + 4];
            }
#pragma unroll
            for (int nt = 0; nt < 4; nt++){
                int n = wn + nt*8 + g;
                b[nt][0] = Bu[n*36 + kh + tq];
                b[nt][1] = Bu[n*36 + kh + tq + 4];
            }
#pragma unroll
            for (int mt = 0; mt < 4; mt++)
#pragma unroll
                for (int nt = 0; nt < 4; nt++)
                    mma_f16(acc[mt][nt], a[mt], b[nt]);
        }
        __syncthreads();
    }
#pragma unroll
    for (int mt = 0; mt < 4; mt++){
#pragma unroll
        for (int nt = 0; nt < 4; nt++){
            int n = n0 + wn + nt*8 + 2*tq;
            float b0 = bias[n], b1 = bias[n+1];
#pragma unroll
            for (int rh = 0; rh < 2; rh++){
                int m = m0 + wm + mt*16 + g + rh*8;
                float v0 = acc[mt][nt][rh*2+0] + b0;
                float v1 = acc[mt][nt][rh*2+1] + b1;
                if (EPI == 1){ v0 = gelu_tanh(v0); v1 = gelu_tanh(v1); }
                if (OUTH){
                    *(__half2*)&Ch[(size_t)m*N + n] = __floats2half2_rn(v0, v1);
                } else {
                    if (R){
                        v0 += R[(size_t)m*N + n];
                        v1 += R[(size_t)m*N + n + 1];
                    }
                    *(float2*)&C[(size_t)m*N + n] = make_float2(v0, v1);
                }
            }
        }
    }
}

// ---------------- fp16 QKV GEMM with head-transposed scatter ----------------
// Q/K fp16 padded [bh][l][32]; V fp32 d-major [bh][24][256]
__global__ __launch_bounds__(256) void gemm_qkv_f16(
    const __half* __restrict__ A, const __half* __restrict__ Bt,
    const float* __restrict__ bias,
    __half* __restrict__ qt, __half* __restrict__ kt, float* __restrict__ vt)
{
    const int N = 2304, K = 768;
    __shared__ __half sA[128*72];
    __shared__ __half sB[128*72];
    int tid = threadIdx.x;
    int m0 = blockIdx.y * 128, n0 = blockIdx.x * 128;
    int lane = tid & 31, warp = tid >> 5;
    int wm = (warp >> 2) * 64, wn = (warp & 3) * 32;
    int g = lane >> 2, tq = lane & 3;
    int ar = tid >> 1, ac = (tid & 1) * 32;

    const uint32_t* Au = (const uint32_t*)sA;
    const uint32_t* Bu = (const uint32_t*)sB;

    float acc[4][4][4];
#pragma unroll
    for (int mt=0;mt<4;mt++)
#pragma unroll
        for (int nt=0;nt<4;nt++)
#pragma unroll
            for (int c=0;c<4;c++) acc[mt][nt][c]=0.f;

    for (int k0 = 0; k0 < K; k0 += 64){
        const uint4* ap = (const uint4*)&A[(size_t)(m0+ar)*K + k0 + ac];
        uint4* asp = (uint4*)&sA[ar*72 + ac];
        asp[0]=ap[0]; asp[1]=ap[1]; asp[2]=ap[2]; asp[3]=ap[3];
        const uint4* bp = (const uint4*)&Bt[(size_t)(n0+ar)*K + k0 + ac];
        uint4* bsp = (uint4*)&sB[ar*72 + ac];
        bsp[0]=bp[0]; bsp[1]=bp[1]; bsp[2]=bp[2]; bsp[3]=bp[3];
        __syncthreads();
#pragma unroll
        for (int ks = 0; ks < 4; ks++){
            int kh = ks*8;
            uint32_t a[4][4], b[4][2];
#pragma unroll
            for (int mt = 0; mt < 4; mt++){
                int rm = wm + mt*16 + g;
                a[mt][0] = Au[rm*36 + kh + tq];
                a[mt][1] = Au[(rm+8)*36 + kh + tq];
                a[mt][2] = Au[rm*36 + kh + tq + 4];
                a[mt][3] = Au[(rm+8)*36 + kh + tq + 4];
            }
#pragma unroll
            for (int nt = 0; nt < 4; nt++){
                int n = wn + nt*8 + g;
                b[nt][0] = Bu[n*36 + kh + tq];
                b[nt][1] = Bu[n*36 + kh + tq + 4];
            }
#pragma unroll
            for (int mt = 0; mt < 4; mt++)
#pragma unroll
                for (int nt = 0; nt < 4; nt++)
                    mma_f16(acc[mt][nt], a[mt], b[nt]);
        }
        __syncthreads();
    }
#pragma unroll
    for (int mt = 0; mt < 4; mt++){
#pragma unroll
        for (int rh = 0; rh < 2; rh++){
            int m = m0 + wm + mt*16 + g + rh*8;
            int b = m >> 8, l = m & 255;
#pragma unroll
            for (int nt = 0; nt < 4; nt++){
#pragma unroll
                for (int e = 0; e < 2; e++){
                    int n = n0 + wn + nt*8 + 2*tq + e;
                    float v = acc[mt][nt][rh*2+e] + bias[n];
                    int seg = n / 768;
                    int nn = n - seg*768;
                    int dd = nn >> 5, h = nn & 31;
                    if (seg == 0){
                        qt[(((size_t)(b*32 + h))*256 + l)*32 + dd] = __float2half(v * SCALE_Q);
                    } else if (seg == 1){
                        kt[(((size_t)(b*32 + h))*256 + l)*32 + dd] = __float2half(v);
                    } else {
                        vt[(((size_t)(b*32 + h))*24 + dd)*256 + l] = v;
                    }
                }
            }
        }
    }
}

// ---------------- QK fp16 tensor-core kernel ----------------
// per (bh, 128x128 tile): qk[l][m] = sum_d q[l][d]*k[m][d], K=32 (zero-padded)
__global__ __launch_bounds__(256) void qk_f16_kernel(
    const __half* __restrict__ qt, const __half* __restrict__ kt,
    float* __restrict__ qk)
{
    __shared__ __half sQ[128*40];
    __shared__ __half sK[128*40];
    int bh = blockIdx.y;
    int l0 = (blockIdx.x >> 1) * 128;
    int m0 = (blockIdx.x & 1) * 128;
    int tid = threadIdx.x;
    {
        const uint4* qsrc = (const uint4*)(qt + (size_t)bh*8192 + (size_t)l0*32);
        const uint4* ksrc = (const uint4*)(kt + (size_t)bh*8192 + (size_t)m0*32);
#pragma unroll
        for (int x = 0; x < 2; x++){
            int i = tid + x*256;
            int r = i >> 2, c = (i & 3) * 8;
            *(uint4*)&sQ[r*40 + c] = qsrc[i];
            *(uint4*)&sK[r*40 + c] = ksrc[i];
        }
    }
    __syncthreads();
    int lane = tid & 31, warp = tid >> 5;
    int wm = (warp >> 2) * 64, wn = (warp & 3) * 32;
    int g = lane >> 2, tq = lane & 3;
    const uint32_t* Qu = (const uint32_t*)sQ;
    const uint32_t* Ku = (const uint32_t*)sK;

    float acc[4][4][4];
#pragma unroll
    for (int mt=0;mt<4;mt++)
#pragma unroll
        for (int nt=0;nt<4;nt++)
#pragma unroll
            for (int c=0;c<4;c++) acc[mt][nt][c]=0.f;

#pragma unroll
    for (int ks = 0; ks < 2; ks++){
        int kh = ks*8;
        uint32_t a[4][4], b[4][2];
#pragma unroll
        for (int mt = 0; mt < 4; mt++){
            int rm = wm + mt*16 + g;
            a[mt][0] = Qu[rm*20 + kh + tq];
            a[mt][1] = Qu[(rm+8)*20 + kh + tq];
            a[mt][2] = Qu[rm*20 + kh + tq + 4];
            a[mt][3] = Qu[(rm+8)*20 + kh + tq + 4];
        }
#pragma unroll
        for (int nt = 0; nt < 4; nt++){
            int n = wn + nt*8 + g;
            b[nt][0] = Ku[n*20 + kh + tq];
            b[nt][1] = Ku[n*20 + kh + tq + 4];
        }
#pragma unroll
        for (int mt = 0; mt < 4; mt++)
#pragma unroll
            for (int nt = 0; nt < 4; nt++)
                mma_f16(acc[mt][nt], a[mt], b[nt]);
    }
    float* out = qk + (size_t)bh*65536;
#pragma unroll
    for (int mt = 0; mt < 4; mt++){
#pragma unroll
        for (int nt = 0; nt < 4; nt++){
            int n = m0 + wn + nt*8 + 2*tq;
#pragma unroll
            for (int rh = 0; rh < 2; rh++){
                int m = l0 + wm + mt*16 + g + rh*8;
                *(float2*)&out[(size_t)m*256 + n] =
                    make_float2(acc[mt][nt][rh*2+0], acc[mt][nt][rh*2+1]);
            }
        }
    }
}

// ---------------- fused edge kernel: per (row, half) CTA, 256 threads, 2 CTAs/SM ----------------
#define EK_FLOATS 23168
__global__ __launch_bounds__(256, 2) void edge_attn_kernel(
    const float* __restrict__ e_in, const float* __restrict__ mask,
    const float* __restrict__ qk,         // raw QK, read-only
    const __half* __restrict__ ew16,
    const float* __restrict__ b_eg, const float* __restrict__ b_oe,
    const float* __restrict__ eln_g, const float* __restrict__ eln_b,
    const float* __restrict__ ffn_g, const float* __restrict__ ffn_b,
    const float* __restrict__ eb1, const float* __restrict__ eb2,
    float* __restrict__ e_out, __half* __restrict__ gate16,
    __half* __restrict__ logit16)
{
    extern __shared__ float sm[];
    float* sPar  = sm;
    float* sMask = sm + 512;
    __half* sW16 = (__half*)(sm + 640);
    __half* Weg_t = sW16;           // [64][72]
    __half* W1_t  = sW16 + 4608;    // [64][72]
    __half* W2_t  = sW16 + 9216;    // [64][72]
    __half* Woe_t = sW16 + 13824;   // [64][40]
    __half* sX16  = (__half*)(sm + 8832);   // [128][72] halves
    float*  sRed  = sm + 13440;             // [128][4] float2
    float*  sE    = sm + 14464;             // [128][68] f32

    int tid  = threadIdx.x;
    int lane = tid & 31;
    int g    = lane >> 2;
    int tq   = lane & 3;
    int wg8  = tid >> 5;
    int wm   = (wg8 >> 2) * 64;
    int wn   = (wg8 & 3) * 16;
    int bid  = blockIdx.x;
    int row  = bid >> 1;
    int grp  = bid & 1;
    int b    = row >> 8;
    int l    = row & 255;
    int m0g  = grp * 128;

    {
        const uint4* src = (const uint4*)ew16;
        uint4* dst = (uint4*)sW16;
#pragma unroll
        for (int i = 0; i < 8; i++)
            dst[tid + i*256] = src[tid + i*256];
    }
    if (tid < 64){
        sPar[tid]     = b_eg[tid];
        sPar[64+tid]  = b_oe[tid];
        sPar[128+tid] = eb1[tid];
        sPar[192+tid] = eb2[tid];
        sPar[256+tid] = eln_g[tid];
        sPar[320+tid] = eln_b[tid];
        sPar[384+tid] = ffn_g[tid];
        sPar[448+tid] = ffn_b[tid];
    }
    if (tid < 128) sMask[tid] = mask[(size_t)row*256 + m0g + tid];
    __syncthreads();

    {
        int ty = tid >> 4, tx = tid & 15;
        float lg0 = sPar[256+tx*4], lg1 = sPar[257+tx*4], lg2 = sPar[258+tx*4], lg3 = sPar[259+tx*4];
        float lb0 = sPar[320+tx*4], lb1 = sPar[321+tx*4], lb2 = sPar[322+tx*4], lb3 = sPar[323+tx*4];
        __half2* xp = (__half2*)sX16;
#pragma unroll
        for (int i = 0; i < 8; i++){
            int r = ty*8 + i;
            float4 e4 = *(const float4*)&e_in[((size_t)row*256 + m0g + r)*64 + tx*4];
            *(float4*)&sE[r*68 + tx*4] = e4;
            float s = sum16(e4.x + e4.y + e4.z + e4.w);
            float mean = s * (1.f/64.f);
            float d0=e4.x-mean, d1=e4.y-mean, d2=e4.z-mean, d3=e4.w-mean;
            float q = sum16(d0*d0 + d1*d1 + d2*d2 + d3*d3);
            float rs = rsqrtf(q * (1.f/64.f) + 1e-5f);
            xp[r*36 + tx*2    ] = __floats2half2_rn(d0*rs*lg0 + lb0, d1*rs*lg1 + lb1);
            xp[r*36 + tx*2 + 1] = __floats2half2_rn(d2*rs*lg2 + lb2, d3*rs*lg3 + lb3);
        }
    }
    __syncthreads();

    float acc[4][2][4];
    const uint32_t* Xu = (const uint32_t*)sX16;

#pragma unroll
    for (int mt=0;mt<4;mt++)
#pragma unroll
        for (int nt=0;nt<2;nt++)
#pragma unroll
            for (int c=0;c<4;c++) acc[mt][nt][c]=0.f;
    warp_gemm_f16<4>(Xu, 36, (const uint32_t*)Weg_t, 36, wm, wn, g, tq, acc);
    __syncthreads();

    size_t qkbase = ((size_t)(b*32))*65536 + (size_t)l*256 + m0g;
    if (wn < 32){
        __half2* hp = (__half2*)sX16;
#pragma unroll
        for (int mt=0;mt<4;mt++)
#pragma unroll
            for (int nt=0;nt<2;nt++){
                int nc = wn + nt*8 + 2*tq;
#pragma unroll
                for (int rh=0;rh<2;rh++){
                    int m = wm + mt*16 + g + rh*8;
                    size_t qi = qkbase + (size_t)nc*65536 + m;
                    float v0 = acc[mt][nt][rh*2+0] + sPar[nc]   + qk[qi];
                    float v1 = acc[mt][nt][rh*2+1] + sPar[nc+1] + qk[qi + 65536];
                    float mk = sMask[m];
                    logit16[qi]         = __float2half(v0 + mk);
                    logit16[qi + 65536] = __float2half(v1 + mk);
                    hp[m*36 + (nc>>1)] = __floats2half2_rn(v0, v1);
                }
            }
    } else {
#pragma unroll
        for (int mt=0;mt<4;mt++)
#pragma unroll
            for (int nt=0;nt<2;nt++){
                int nc = wn + nt*8 + 2*tq;
                int h0 = nc - 32;
#pragma unroll
                for (int rh=0;rh<2;rh++){
                    int m = wm + mt*16 + g + rh*8;
                    float mk = sMask[m];
                    size_t gi = qkbase + (size_t)h0*65536 + m;
                    gate16[gi]         = __float2half(sigmoidf_(acc[mt][nt][rh*2+0] + sPar[nc]   + mk));
                    gate16[gi + 65536] = __float2half(sigmoidf_(acc[mt][nt][rh*2+1] + sPar[nc+1] + mk));
                }
            }
    }
    __syncthreads();

#pragma unroll
    for (int mt=0;mt<4;mt++)
#pragma unroll
        for (int nt=0;nt<2;nt++)
#pragma unroll
            for (int c=0;c<4;c++) acc[mt][nt][c]=0.f;
    warp_gemm_f16<2>(Xu, 36, (const uint32_t*)Woe_t, 20, wm, wn, g, tq, acc);

    float r_[4][2][4];
#pragma unroll
    for (int mt=0;mt<4;mt++)
#pragma unroll
        for (int nt=0;nt<2;nt++){
            int nc = wn + nt*8 + 2*tq;
            int m  = wm + mt*16 + g;
            const float* ep = &sE[m*68 + nc];
            float2 ea = *(const float2*)ep;
            float2 eb = *(const float2*)(ep + 8*68);
            r_[mt][nt][0] = ea.x + acc[mt][nt][0] + sPar[64+nc];
            r_[mt][nt][1] = ea.y + acc[mt][nt][1] + sPar[64+nc+1];
            r_[mt][nt][2] = eb.x + acc[mt][nt][2] + sPar[64+nc];
            r_[mt][nt][3] = eb.y + acc[mt][nt][3] + sPar[64+nc+1];
        }

    {
        float2* rp = (float2*)sRed;
#pragma unroll
        for (int mt=0;mt<4;mt++)
#pragma unroll
            for (int rh=0;rh<2;rh++){
                float ps = r_[mt][0][rh*2] + r_[mt][0][rh*2+1]
                         + r_[mt][1][rh*2] + r_[mt][1][rh*2+1];
                float pq = r_[mt][0][rh*2]*r_[mt][0][rh*2] + r_[mt][0][rh*2+1]*r_[mt][0][rh*2+1]
                         + r_[mt][1][rh*2]*r_[mt][1][rh*2] + r_[mt][1][rh*2+1]*r_[mt][1][rh*2+1];
                ps += __shfl_xor_sync(FULLMASK, ps, 1);
                ps += __shfl_xor_sync(FULLMASK, ps, 2);
                pq += __shfl_xor_sync(FULLMASK, pq, 1);
                pq += __shfl_xor_sync(FULLMASK, pq, 2);
                if (tq == 0){
                    int m = wm + mt*16 + g + rh*8;
                    rp[m*4 + (wg8 & 3)] = make_float2(ps, pq);
                }
            }
    }
    __syncthreads();
    {
        __half2* xp = (__half2*)sX16;
        const float2* rp = (const float2*)sRed;
#pragma unroll
        for (int mt=0;mt<4;mt++)
#pragma unroll
            for (int rh=0;rh<2;rh++){
                int m = wm + mt*16 + g + rh*8;
                float2 p0 = rp[m*4+0], p1 = rp[m*4+1], p2 = rp[m*4+2], p3 = rp[m*4+3];
                float mu = (p0.x+p1.x+p2.x+p3.x) * (1.f/64.f);
                float vq = (p0.y+p1.y+p2.y+p3.y) * (1.f/64.f) - mu*mu;
                float rs = rsqrtf(vq + 1e-5f);
#pragma unroll
                for (int nt=0;nt<2;nt++){
                    int nc = wn + nt*8 + 2*tq;
                    float v0 = (r_[mt][nt][rh*2+0]-mu)*rs*sPar[384+nc]   + sPar[448+nc];
                    float v1 = (r_[mt][nt][rh*2+1]-mu)*rs*sPar[384+nc+1] + sPar[448+nc+1];
                    xp[m*36 + (nc>>1)] = __floats2half2_rn(v0, v1);
                }
            }
    }
    __syncthreads();

#pragma unroll
    for (int mt=0;mt<4;mt++)
#pragma unroll
        for (int nt=0;nt<2;nt++)
#pragma unroll
            for (int c=0;c<4;c++) acc[mt][nt][c]=0.f;
    warp_gemm_f16<4>(Xu, 36, (const uint32_t*)W1_t, 36, wm, wn, g, tq, acc);
    __syncthreads();
    {
        __half2* xp = (__half2*)sX16;
#pragma unroll
        for (int mt=0;mt<4;mt++)
#pragma unroll
            for (int nt=0;nt<2;nt++){
                int nc = wn + nt*8 + 2*tq;
#pragma unroll
                for (int rh=0;rh<2;rh++){
                    int m = wm + mt*16 + g + rh*8;
                    float v0 = gelu_tanh(acc[mt][nt][rh*2+0] + sPar[128+nc]);
                    float v1 = gelu_tanh(acc[mt][nt][rh*2+1] + sPar[128+nc+1]);
                    xp[m*36 + (nc>>1)] = __floats2half2_rn(v0, v1);
                }
            }
    }
    __syncthreads();

#pragma unroll
    for (int mt=0;mt<4;mt++)
#pragma unroll
        for (int nt=0;nt<2;nt++)
#pragma unroll
            for (int c=0;c<4;c++) acc[mt][nt][c]=0.f;
    warp_gemm_f16<4>(Xu, 36, (const uint32_t*)W2_t, 36, wm, wn, g, tq, acc);
#pragma unroll
    for (int mt=0;mt<4;mt++)
#pragma unroll
        for (int nt=0;nt<2;nt++){
            int nc = wn + nt*8 + 2*tq;
            int m  = wm + mt*16 + g;
            float* op = &e_out[((size_t)row*256 + m0g + m)*64 + nc];
            *(float2*)op = make_float2(
                r_[mt][nt][0] + acc[mt][nt][0] + sPar[192+nc],
                r_[mt][nt][1] + acc[mt][nt][1] + sPar[192+nc+1]);
            *(float2*)(op + 8*64) = make_float2(
                r_[mt][nt][2] + acc[mt][nt][2] + sPar[192+nc],
                r_[mt][nt][3] + acc[mt][nt][3] + sPar[192+nc+1]);
        }
}

// ---------------- softmax + AV kernel: per (bh, 32-l tile) ----------------
#define AV_FLOATS (8320 + 6240 + 4224)
__global__ __launch_bounds__(256) void av_softmax_kernel(
    const __half* __restrict__ logit16, const __half* __restrict__ gate16,
    const float* __restrict__ vt, __half* __restrict__ vatt)
{
    extern __shared__ float sm[];
    float* sL = sm;                    // [32][260]
    float* sV = sm + 8320;             // [24][260]
    __half* sG = (__half*)(sm + 14560);// [32][264]
    int bh = blockIdx.y;
    int l0 = blockIdx.x * 32;
    int b = bh >> 5, h = bh & 31;
    int tid = threadIdx.x;

    const __half* lb = logit16 + (size_t)bh*65536 + (size_t)l0*256;
    for (int i = tid; i < 1024; i += 256){
        int ll = i >> 5, m = (i & 31) * 8;
        uint4 raw = *(const uint4*)&lb[(size_t)ll*256 + m];
        const __half2* hp = (const __half2*)&raw;
#pragma unroll
        for (int e = 0; e < 4; e++){
            float2 f = __half22float2(hp[e]);
            sL[ll*260 + m + 2*e    ] = f.x;
            sL[ll*260 + m + 2*e + 1] = f.y;
        }
    }
    const __half* gb = gate16 + (size_t)bh*65536 + (size_t)l0*256;
    for (int i = tid; i < 1024; i += 256){
        int ll = i >> 5, m = (i & 31) * 8;
        *(uint4*)&sG[ll*264 + m] = *(const uint4*)&gb[(size_t)ll*256 + m];
    }
    const float* vb = vt + (size_t)bh*6144;
    for (int i = tid; i < 1536; i += 256){
        int dd = i >> 6, m = (i & 63) * 4;
        *(float4*)&sV[dd*260 + m] = *(const float4*)&vb[dd*256 + m];
    }
    __syncthreads();

    int w = tid >> 5, lane = tid & 31;
#pragma unroll
    for (int rr = 0; rr < 4; rr++){
        int row = w*4 + rr;
        float p[8], gg[8];
        float mx = -3.4e38f;
#pragma unroll
        for (int j = 0; j < 8; j++){
            p[j] = sL[row*260 + j*32 + lane];
            mx = fmaxf(mx, p[j]);
        }
        mx = warpMax(mx);
        float s = 0.f, gs = 0.f;
#pragma unroll
        for (int j = 0; j < 8; j++){
            p[j] = __expf(p[j] - mx);
            s += p[j];
            gg[j] = __half2float(sG[row*264 + j*32 + lane]);
            gs += gg[j];
        }
        s = warpSum(s); gs = warpSum(gs);
        float c = (1.f / s) * log1pf(gs);
#pragma unroll
        for (int j = 0; j < 8; j++)
            sL[row*260 + j*32 + lane] = p[j] * gg[j] * c;
    }
    __syncthreads();

    if (lane < 24){
        const float* vr = &sV[lane*260];
#pragma unroll
        for (int j = 0; j < 4; j++){
            int ll = w*4 + j;
            const float* ar = &sL[ll*260];
            float acc = 0.f;
#pragma unroll 8
            for (int m = 0; m < 256; m += 4){
                float4 a = *(const float4*)&ar[m];
                float4 v = *(const float4*)&vr[m];
                acc += a.x*v.x + a.y*v.y + a.z*v.z + a.w*v.w;
            }
            vatt[(size_t)(b*256 + l0 + ll)*768 + lane*32 + h] = __float2half(acc);
        }
    }
}

// ---------------- host ----------------
extern "C" void kernel_launch(void* const* d_in, const int* in_sizes, int n_in,
                              void* d_out, int out_size)
{
    const float* h_in   = (const float*)d_in[0];
    const float* e_in   = (const float*)d_in[1];
    const float* mask   = (const float*)d_in[2];
    const float* ln_h_g = (const float*)d_in[3];
    const float* ln_h_b = (const float*)d_in[4];
    const float* ln_e_g = (const float*)d_in[5];
    const float* ln_e_b = (const float*)d_in[6];
    const float* W_qkv  = (const float*)d_in[7];
    const float* b_qkv  = (const float*)d_in[8];
    const float* W_eg   = (const float*)d_in[9];
    const float* b_eg   = (const float*)d_in[10];
    const float* W_oh   = (const float*)d_in[11];
    const float* b_oh   = (const float*)d_in[12];
    const float* W_oe   = (const float*)d_in[13];
    const float* b_oe   = (const float*)d_in[14];
    const float* nffn_g = (const float*)d_in[15];
    const float* nffn_b = (const float*)d_in[16];
    const float* nW1    = (const float*)d_in[17];
    const float* nb1    = (const float*)d_in[18];
    const float* nW2    = (const float*)d_in[19];
    const float* nb2    = (const float*)d_in[20];
    const float* effn_g = (const float*)d_in[21];
    const float* effn_b = (const float*)d_in[22];
    const float* eW1    = (const float*)d_in[23];
    const float* eb1    = (const float*)d_in[24];
    const float* eW2    = (const float*)d_in[25];
    const float* eb2    = (const float*)d_in[26];

    float* out_h = (float*)d_out;
    float* out_e = out_h + (size_t)ROWS * DD_;

    float *vt, *qk, *hmid;
    __half *qt16, *kt16, *logit16, *gate16, *hln16, *hln216, *t16, *vatt16;
    __half *wqkv16, *woh16, *nw116, *nw216, *ew16;
    cudaGetSymbolAddress((void**)&qt16,    g_qt16);
    cudaGetSymbolAddress((void**)&kt16,    g_kt16);
    cudaGetSymbolAddress((void**)&vt,      g_vt);
    cudaGetSymbolAddress((void**)&qk,      g_qk);
    cudaGetSymbolAddress((void**)&logit16, g_logit16);
    cudaGetSymbolAddress((void**)&gate16,  g_gate16);
    cudaGetSymbolAddress((void**)&hmid,    g_hmid);
    cudaGetSymbolAddress((void**)&hln16,   g_hln16);
    cudaGetSymbolAddress((void**)&hln216,  g_hln216);
    cudaGetSymbolAddress((void**)&t16,     g_t16);
    cudaGetSymbolAddress((void**)&vatt16,  g_vatt16);
    cudaGetSymbolAddress((void**)&wqkv16,  g_wqkv16);
    cudaGetSymbolAddress((void**)&woh16,   g_woh16);
    cudaGetSymbolAddress((void**)&nw116,   g_nw116);
    cudaGetSymbolAddress((void**)&nw216,   g_nw216);
    cudaGetSymbolAddress((void**)&ew16,    g_ew16);

    cudaFuncSetAttribute(edge_attn_kernel,
                         cudaFuncAttributeMaxDynamicSharedMemorySize,
                         EK_FLOATS * 4);
    cudaFuncSetAttribute(av_softmax_kernel,
                         cudaFuncAttributeMaxDynamicSharedMemorySize,
                         AV_FLOATS * 4);

    // 0) weight prep + Q/K buffer zero (one launch)
    weight_prep<<<dim3(72, 24, 6), 256>>>(
        W_qkv, W_oh, nW1, nW2, W_eg, eW1, eW2, W_oe,
        wqkv16, woh16, nw116, nw216, ew16, qt16, kt16);

    // 1) h layernorm -> fp16
    ln768_kernel<<<ROWS, 256>>>(h_in, ln_h_g, ln_h_b, hln16);

    // 2) QKV GEMM (fp16 mma), Q/K fp16 padded scatter, V d-major fp32
    gemm_qkv_f16<<<dim3(18, 16), 256>>>(hln16, wqkv16, b_qkv, qt16, kt16, vt);

    // 3) QK = Q K^T per head (fp16 mma)
    qk_f16_kernel<<<dim3(4, 256), 256>>>(qt16, kt16, qk);

    // 4) edge attention + edge FFN: masked fp16 logits -> logit16, gates -> gate16
    edge_attn_kernel<<<2*ROWS, 256, EK_FLOATS * 4>>>(
        e_in, mask, qk, ew16,
        b_eg, b_oe,
        ln_e_g, ln_e_b, effn_g, effn_b,
        eb1, eb2,
        out_e, gate16, logit16);

    // 5) softmax + V_att = A' @ V -> fp16
    av_softmax_kernel<<<dim3(8, 256), 256, AV_FLOATS * 4>>>(
        logit16, gate16, vt, vatt16);

    // 6) h_mid = h + V_att @ W_oh + b_oh (fp16 mma)
    gemm_f16k<0,0><<<dim3(6, 16), 256>>>(vatt16, woh16, b_oh, h_in,
                                         hmid, nullptr, ROWS, DD_, DD_);

    // 7) node FFN (fp16 mma)
    ln768_kernel<<<ROWS, 256>>>(hmid, nffn_g, nffn_b, hln216);
    gemm_f16k<1,1><<<dim3(6, 16), 256>>>(hln216, nw116, nb1, nullptr,
                                         nullptr, t16, ROWS, DD_, DD_);
    gemm_f16k<0,0><<<dim3(6, 16), 256>>>(t16, nw216, nb2, hmid,
                                         out_h, nullptr, ROWS, DD_, DD_);
}